// round 1
// baseline (speedup 1.0000x reference)
#include <cuda_runtime.h>
#include <math.h>

#define BATCH 4096

// ---------------- scratch (device globals: no allocation allowed) ----------------
__device__ float g_M[(size_t)BATCH * BATCH];       // 64MB similarity matrix
__device__ float g_fi1[BATCH * 512];
__device__ float g_fi2[BATCH * 256];
__device__ float g_fi3[BATCH * 128];
__device__ float g_ft1[BATCH * 128];
__device__ float g_ft2[BATCH * 128];
__device__ float g_isp[BATCH * 128];
__device__ float g_ish[BATCH * 128];
__device__ float g_tsh[BATCH * 128];
__device__ float g_tsp[BATCH * 128];
__device__ float g_ln[BATCH * 128];                // normalized "left" features
__device__ float g_rn[BATCH * 128];                // normalized "right" features
__device__ double g_acc[4];                        // [0]=clip1 sum, [1]=clip2 sum, [2]=S_t, [3]=S_i
__device__ int g_n0;                               // count of y==0

// ---------------- init: zero accumulators + count labels ----------------
__global__ void so2_init(const int* __restrict__ y) {
    __shared__ int cnt[256];
    int t = threadIdx.x;
    int c = 0;
    for (int j = t; j < BATCH; j += 256) c += (y[j] == 0) ? 1 : 0;
    cnt[t] = c;
    __syncthreads();
    for (int off = 128; off > 0; off >>= 1) {
        if (t < off) cnt[t] += cnt[t + off];
        __syncthreads();
    }
    if (t == 0) {
        g_n0 = cnt[0];
        g_acc[0] = 0.0; g_acc[1] = 0.0; g_acc[2] = 0.0; g_acc[3] = 0.0;
    }
}

// ---------------- generic SGEMM (NT): C = act(A[M,K] @ W[N,K]^T + bias) ----------------
// 128x128 block tile, BK=8, 256 threads, 8x8 per thread.
template <bool RELU>
__global__ __launch_bounds__(256) void so2_sgemm(
    const float* __restrict__ A, const float* __restrict__ W,
    const float* __restrict__ bias, float* __restrict__ C,
    int M, int N, int K)
{
    const int BM = 128, BN = 128, BK = 8, TM = 8, TN = 8;
    __shared__ float As[BK][BM];
    __shared__ float Ws[BK][BN];
    int bm = blockIdx.y * BM, bn = blockIdx.x * BN;
    int tid = threadIdx.x;
    int tr = (tid / (BN / TN)) * TM;   // 0..120
    int tc = (tid % (BN / TN)) * TN;

    float acc[TM][TN];
#pragma unroll
    for (int i = 0; i < TM; i++)
#pragma unroll
        for (int j = 0; j < TN; j++) acc[i][j] = 0.f;

    for (int k0 = 0; k0 < K; k0 += BK) {
        for (int idx = tid; idx < BM * BK; idx += 256) {
            int r = idx >> 3, c = idx & 7;
            int gm = bm + r, gk = k0 + c;
            As[c][r] = (gm < M && gk < K) ? A[(size_t)gm * K + gk] : 0.f;
        }
        for (int idx = tid; idx < BN * BK; idx += 256) {
            int r = idx >> 3, c = idx & 7;
            int gn = bn + r, gk = k0 + c;
            Ws[c][r] = (gn < N && gk < K) ? W[(size_t)gn * K + gk] : 0.f;
        }
        __syncthreads();
#pragma unroll
        for (int kk = 0; kk < BK; kk++) {
            float a[TM], w[TN];
#pragma unroll
            for (int i = 0; i < TM; i++) a[i] = As[kk][tr + i];
#pragma unroll
            for (int j = 0; j < TN; j++) w[j] = Ws[kk][tc + j];
#pragma unroll
            for (int i = 0; i < TM; i++)
#pragma unroll
                for (int j = 0; j < TN; j++) acc[i][j] += a[i] * w[j];
        }
        __syncthreads();
    }

#pragma unroll
    for (int i = 0; i < TM; i++) {
        int gm = bm + tr + i;
        if (gm >= M) continue;
#pragma unroll
        for (int j = 0; j < TN; j++) {
            int gn = bn + tc + j;
            if (gn >= N) continue;
            float v = acc[i][j] + (bias ? bias[gn] : 0.f);
            if (RELU) v = fmaxf(v, 0.f);
            C[(size_t)gm * N + gn] = v;
        }
    }
}

// ---------------- row L2-normalize for [4096,128] ----------------
__global__ void so2_normalize(const float* __restrict__ x, float* __restrict__ out) {
    int r = blockIdx.x, t = threadIdx.x;  // 128 threads
    float v = x[r * 128 + t];
    __shared__ float red[128];
    red[t] = v * v;
    __syncthreads();
    for (int off = 64; off > 0; off >>= 1) {
        if (t < off) red[t] += red[t + off];
        __syncthreads();
    }
    float n = sqrtf(red[0]);
    n = fmaxf(n, 1e-12f);
    out[r * 128 + t] = v / n;
}

// ---------------- shared finalize math for one softmax row ----------------
// m: running max, Z: sum exp(l-m), X: sum exp(l-m)*l, P: sum_match exp(l-m),
// L: sum l, Lm: sum_match l, c: this row's label.
__device__ __forceinline__ float so2_row_term(
    float m, float Z, float X, float P, float L, float Lm, int c)
{
    float lse = m + logf(Z);
    float sum_p_logit = X / Z;
    float pmatch = P / Z;
    int n0 = g_n0;
    float nc = (c == 0) ? (float)n0 : (float)(BATCH - n0);
    float no = (float)BATCH - nc;
    float u = 1.0f / nc;
    float eu = expf(u);
    float denom = nc * eu + no;
    float lden = logf(denom);
    float lqm = u - lden;          // log q at matching positions
    float lqn = -lden;             // log q at non-matching positions
    float qm = eu / denom;
    float qn = 1.0f / denom;
    float sum_q_lq = nc * qm * lqm + no * qn * lqn;
    float sum_q_lp = qm * Lm + qn * (L - Lm) - lse;
    float sum_p_lp = sum_p_logit - lse;
    float sum_p_lq = lqm * pmatch + lqn * (1.0f - pmatch);
    return (sum_q_lq - sum_q_lp) + (sum_p_lp - sum_p_lq);
}

// ---------------- row reduction over M (logit = exp(*log_scale) * M[k,:]) ----------------
__global__ __launch_bounds__(256) void so2_row_reduce(
    const int* __restrict__ y, const float* __restrict__ log_scale, int acc_idx)
{
    int k = blockIdx.x;
    float s = expf(*log_scale);
    int c = y[k];
    const float* row = g_M + (size_t)k * BATCH;
    float m = -INFINITY, Z = 0.f, X = 0.f, P = 0.f, L = 0.f, Lm = 0.f;
    for (int j = threadIdx.x; j < BATCH; j += 256) {
        float l = s * row[j];
        float e;
        if (l > m) {
            float f = expf(m - l);
            Z *= f; X *= f; P *= f; m = l; e = 1.0f;
        } else {
            e = expf(l - m);
        }
        Z += e; X += e * l; L += l;
        if (y[j] == c) { P += e; Lm += l; }
    }
    __shared__ float sm[256], sZ[256], sX[256], sP[256], sL[256], sLm[256];
    int t = threadIdx.x;
    sm[t] = m; sZ[t] = Z; sX[t] = X; sP[t] = P; sL[t] = L; sLm[t] = Lm;
    __syncthreads();
    for (int off = 128; off > 0; off >>= 1) {
        if (t < off) {
            float m1 = sm[t], m2 = sm[t + off];
            float nm = fmaxf(m1, m2);
            float f1 = expf(m1 - nm), f2 = expf(m2 - nm);
            sZ[t] = sZ[t] * f1 + sZ[t + off] * f2;
            sX[t] = sX[t] * f1 + sX[t + off] * f2;
            sP[t] = sP[t] * f1 + sP[t + off] * f2;
            sm[t] = nm;
            sL[t] += sL[t + off];
            sLm[t] += sLm[t + off];
        }
        __syncthreads();
    }
    if (t == 0) {
        float term = so2_row_term(sm[0], sZ[0], sX[0], sP[0], sL[0], sLm[0], c);
        atomicAdd(&g_acc[acc_idx], (double)term);
    }
}

// ---------------- column reduction over M (logit = M[:,k], no scale) ----------------
__global__ __launch_bounds__(256) void so2_col_reduce(const int* __restrict__ y, int acc_idx)
{
    int tx = threadIdx.x;  // 32 columns
    int ty = threadIdx.y;  // 8 row groups
    int col = blockIdx.x * 32 + tx;
    int c = y[col];
    float m = -INFINITY, Z = 0.f, X = 0.f, P = 0.f, L = 0.f, Lm = 0.f;
    for (int j = ty; j < BATCH; j += 8) {
        float l = g_M[(size_t)j * BATCH + col];
        float e;
        if (l > m) {
            float f = expf(m - l);
            Z *= f; X *= f; P *= f; m = l; e = 1.0f;
        } else {
            e = expf(l - m);
        }
        Z += e; X += e * l; L += l;
        if (y[j] == c) { P += e; Lm += l; }
    }
    __shared__ float sm[8][32], sZ[8][32], sX[8][32], sP[8][32], sL[8][32], sLm[8][32];
    sm[ty][tx] = m; sZ[ty][tx] = Z; sX[ty][tx] = X;
    sP[ty][tx] = P; sL[ty][tx] = L; sLm[ty][tx] = Lm;
    __syncthreads();
    if (ty == 0) {
        for (int o = 1; o < 8; o++) {
            float m2 = sm[o][tx];
            float nm = fmaxf(m, m2);
            float f1 = expf(m - nm), f2 = expf(m2 - nm);
            Z = Z * f1 + sZ[o][tx] * f2;
            X = X * f1 + sX[o][tx] * f2;
            P = P * f1 + sP[o][tx] * f2;
            m = nm;
            L += sL[o][tx];
            Lm += sLm[o][tx];
        }
        float term = so2_row_term(m, Z, X, P, L, Lm, c);
        atomicAdd(&g_acc[acc_idx], (double)term);
    }
}

// ---------------- sum over (A^T A) .* (B^T B) for the Frobenius trick ----------------
__global__ void so2_gram_pair(const float* __restrict__ A, const float* __restrict__ Bm,
                              int acc_idx)
{
    __shared__ float Au[16][17], Av[16][17], Bu[16][17], Bv[16][17];
    int u0 = blockIdx.x * 16, v0 = blockIdx.y * 16;
    int tx = threadIdx.x, ty = threadIdx.y;
    float ga = 0.f, gb = 0.f;
    for (int r0 = 0; r0 < BATCH; r0 += 16) {
        Au[ty][tx] = A[(r0 + ty) * 128 + u0 + tx];
        Av[ty][tx] = A[(r0 + ty) * 128 + v0 + tx];
        Bu[ty][tx] = Bm[(r0 + ty) * 128 + u0 + tx];
        Bv[ty][tx] = Bm[(r0 + ty) * 128 + v0 + tx];
        __syncthreads();
#pragma unroll
        for (int rr = 0; rr < 16; rr++) {
            ga += Au[rr][tx] * Av[rr][ty];
            gb += Bu[rr][tx] * Bv[rr][ty];
        }
        __syncthreads();
    }
    __shared__ float red[256];
    int t = ty * 16 + tx;
    red[t] = ga * gb;
    __syncthreads();
    for (int off = 128; off > 0; off >>= 1) {
        if (t < off) red[t] += red[t + off];
        __syncthreads();
    }
    if (t == 0) atomicAdd(&g_acc[acc_idx], (double)red[0]);
}

// ---------------- 4 head outputs: dot(row, c_w) + c_b ----------------
__global__ void so2_head_out(
    const float* __restrict__ c1w, const float* __restrict__ c1b,
    const float* __restrict__ c2w, const float* __restrict__ c2b,
    const float* __restrict__ c3w, const float* __restrict__ c3b,
    const float* __restrict__ c4w, const float* __restrict__ c4b,
    float* __restrict__ out)
{
    int r = blockIdx.x, t = threadIdx.x;  // 128 threads
    __shared__ float red[4][128];
    red[0][t] = g_isp[r * 128 + t] * c1w[t];
    red[1][t] = g_ish[r * 128 + t] * c2w[t];
    red[2][t] = g_tsp[r * 128 + t] * c4w[t];   // t_sp_out uses c4
    red[3][t] = g_tsh[r * 128 + t] * c3w[t];   // t_sh_out uses c3
    __syncthreads();
    for (int off = 64; off > 0; off >>= 1) {
        if (t < off) {
#pragma unroll
            for (int a = 0; a < 4; a++) red[a][t] += red[a][t + off];
        }
        __syncthreads();
    }
    if (t == 0) {
        out[1 + r]             = red[0][0] + c1b[0];  // i_sp_out
        out[1 + BATCH + r]     = red[1][0] + c2b[0];  // i_sh_out
        out[1 + 2 * BATCH + r] = red[2][0] + c4b[0];  // t_sp_out
        out[1 + 3 * BATCH + r] = red[3][0] + c3b[0];  // t_sh_out
    }
}

// ---------------- final loss combine ----------------
__global__ void so2_finalize(float* __restrict__ out) {
    double loss_sp = 0.5 * (sqrt(g_acc[2]) + sqrt(g_acc[3]));
    double loss1 = g_acc[0] / (4.0 * BATCH);
    double loss_sh = g_acc[1] / (4.0 * BATCH);
    out[0] = (float)((loss_sp + loss_sh + loss1) / 3.0);
}

// ---------------- host driver ----------------
extern "C" void kernel_launch(void* const* d_in, const int* in_sizes, int n_in,
                              void* d_out, int out_size) {
    const float* i_   = (const float*)d_in[0];
    const float* t_   = (const float*)d_in[1];
    const int*   y    = (const int*)d_in[2];
    const float* l1w  = (const float*)d_in[3];  const float* l1b = (const float*)d_in[4];
    const float* l2w  = (const float*)d_in[5];  const float* l2b = (const float*)d_in[6];
    const float* l3w  = (const float*)d_in[7];  const float* l3b = (const float*)d_in[8];
    const float* tl1w = (const float*)d_in[9];  const float* tl1b = (const float*)d_in[10];
    const float* tl2w = (const float*)d_in[11]; const float* tl2b = (const float*)d_in[12];
    const float* ispw = (const float*)d_in[13]; const float* ispb = (const float*)d_in[14];
    const float* ishw = (const float*)d_in[15]; const float* ishb = (const float*)d_in[16];
    const float* tshw = (const float*)d_in[17]; const float* tshb = (const float*)d_in[18];
    const float* tspw = (const float*)d_in[19]; const float* tspb = (const float*)d_in[20];
    const float* c1w  = (const float*)d_in[21]; const float* c1b = (const float*)d_in[22];
    const float* c2w  = (const float*)d_in[23]; const float* c2b = (const float*)d_in[24];
    const float* c3w  = (const float*)d_in[25]; const float* c3b = (const float*)d_in[26];
    const float* c4w  = (const float*)d_in[27]; const float* c4b = (const float*)d_in[28];
    const float* scale1 = (const float*)d_in[29];
    const float* scale2 = (const float*)d_in[30];
    float* out = (float*)d_out;

    float *pM, *pfi1, *pfi2, *pfi3, *pft1, *pft2, *pisp, *pish, *ptsh, *ptsp, *pln, *prn;
    cudaGetSymbolAddress((void**)&pM, g_M);
    cudaGetSymbolAddress((void**)&pfi1, g_fi1);
    cudaGetSymbolAddress((void**)&pfi2, g_fi2);
    cudaGetSymbolAddress((void**)&pfi3, g_fi3);
    cudaGetSymbolAddress((void**)&pft1, g_ft1);
    cudaGetSymbolAddress((void**)&pft2, g_ft2);
    cudaGetSymbolAddress((void**)&pisp, g_isp);
    cudaGetSymbolAddress((void**)&pish, g_ish);
    cudaGetSymbolAddress((void**)&ptsh, g_tsh);
    cudaGetSymbolAddress((void**)&ptsp, g_tsp);
    cudaGetSymbolAddress((void**)&pln, g_ln);
    cudaGetSymbolAddress((void**)&prn, g_rn);

    so2_init<<<1, 256>>>(y);

    // image MLP
    so2_sgemm<true ><<<dim3(512 / 128, BATCH / 128), 256>>>(i_,   l1w, l1b, pfi1, BATCH, 512, 2048);
    so2_sgemm<true ><<<dim3(256 / 128, BATCH / 128), 256>>>(pfi1, l2w, l2b, pfi2, BATCH, 256, 512);
    so2_sgemm<false><<<dim3(1, BATCH / 128), 256>>>(pfi2, l3w, l3b, pfi3, BATCH, 128, 256);
    // tab MLP
    so2_sgemm<true ><<<dim3(1, BATCH / 128), 256>>>(t_,   tl1w, tl1b, pft1, BATCH, 128, 49);
    so2_sgemm<false><<<dim3(1, BATCH / 128), 256>>>(pft1, tl2w, tl2b, pft2, BATCH, 128, 128);
    // SS heads
    so2_sgemm<false><<<dim3(1, BATCH / 128), 256>>>(pfi3, ispw, ispb, pisp, BATCH, 128, 128);
    so2_sgemm<false><<<dim3(1, BATCH / 128), 256>>>(pfi3, ishw, ishb, pish, BATCH, 128, 128);
    so2_sgemm<false><<<dim3(1, BATCH / 128), 256>>>(pft2, tshw, tshb, ptsh, BATCH, 128, 128);
    so2_sgemm<false><<<dim3(1, BATCH / 128), 256>>>(pft2, tspw, tspb, ptsp, BATCH, 128, 128);

    // ---- clip loss 1 on (fi3, ft2) ----
    so2_normalize<<<BATCH, 128>>>(pfi3, pln);
    so2_normalize<<<BATCH, 128>>>(pft2, prn);
    so2_sgemm<false><<<dim3(BATCH / 128, BATCH / 128), 256>>>(pln, prn, (const float*)nullptr, pM, BATCH, BATCH, 128);
    so2_row_reduce<<<BATCH, 256>>>(y, scale1, 0);
    so2_col_reduce<<<BATCH / 32, dim3(32, 8)>>>(y, 0);

    // ---- clip loss 2 on (i_sh, t_sh) ----
    so2_normalize<<<BATCH, 128>>>(pish, pln);
    so2_normalize<<<BATCH, 128>>>(ptsh, prn);
    so2_sgemm<false><<<dim3(BATCH / 128, BATCH / 128), 256>>>(pln, prn, (const float*)nullptr, pM, BATCH, BATCH, 128);
    so2_row_reduce<<<BATCH, 256>>>(y, scale2, 1);
    so2_col_reduce<<<BATCH / 32, dim3(32, 8)>>>(y, 1);

    // ---- separate loss via Gram trick ----
    so2_gram_pair<<<dim3(8, 8), dim3(16, 16)>>>(ptsp, ptsh, 2);
    so2_gram_pair<<<dim3(8, 8), dim3(16, 16)>>>(pisp, pish, 3);

    // ---- outputs ----
    so2_head_out<<<BATCH, 128>>>(c1w, c1b, c2w, c2b, c3w, c3b, c4w, c4b, out);
    so2_finalize<<<1, 1>>>(out);
}

// round 2
// speedup vs baseline: 2.0623x; 2.0623x over previous
#include <cuda_runtime.h>
#include <math.h>

#define BATCH 4096

// ---------------- scratch (device globals) ----------------
__device__ float g_M[(size_t)BATCH * BATCH];       // 64MB similarity matrix
__device__ float g_fi1[BATCH * 512];
__device__ float g_fi2[BATCH * 256];
__device__ float g_fi3[BATCH * 128];
__device__ float g_fi3n[BATCH * 128];
__device__ float g_ft1[BATCH * 128];
__device__ float g_ft2[BATCH * 128];
__device__ float g_ft2n[BATCH * 128];
__device__ float g_isp[BATCH * 128];
__device__ float g_ish[BATCH * 128];
__device__ float g_ishn[BATCH * 128];
__device__ float g_tsh[BATCH * 128];
__device__ float g_tshn[BATCH * 128];
__device__ float g_tsp[BATCH * 128];
__device__ double g_acc[4];                        // [0]=clip1, [1]=clip2, [2]=S_t, [3]=S_i
__device__ int g_n0;

// ---------------- fast exp on the FMA pipe (deg-7 Taylor of 2^f) ----------------
__device__ __forceinline__ float fexp(float x) {
    float t = x * 1.4426950408889634f;
    float fi = floorf(t);
    float f = t - fi;
    float p = 1.52527338e-5f;
    p = fmaf(p, f, 1.54035304e-4f);
    p = fmaf(p, f, 1.33335581e-3f);
    p = fmaf(p, f, 9.61812911e-3f);
    p = fmaf(p, f, 5.55041087e-2f);
    p = fmaf(p, f, 2.40226507e-1f);
    p = fmaf(p, f, 6.93147181e-1f);
    p = fmaf(p, f, 1.0f);
    int i = (int)fi;
    return __int_as_float((i + 127) << 23) * p;
}

__device__ __forceinline__ float wsum(float v) {
#pragma unroll
    for (int o = 16; o > 0; o >>= 1) v += __shfl_xor_sync(0xffffffffu, v, o);
    return v;
}

// ---------------- init ----------------
__global__ void so2_init(const int* __restrict__ y) {
    __shared__ int cnt[256];
    int t = threadIdx.x;
    int c = 0;
    for (int j = t; j < BATCH; j += 256) c += (y[j] == 0) ? 1 : 0;
    cnt[t] = c;
    __syncthreads();
    for (int off = 128; off > 0; off >>= 1) {
        if (t < off) cnt[t] += cnt[t + off];
        __syncthreads();
    }
    if (t == 0) {
        g_n0 = cnt[0];
        g_acc[0] = 0.0; g_acc[1] = 0.0; g_acc[2] = 0.0; g_acc[3] = 0.0;
    }
}

// ---------------- big SGEMM (NT): C = act(A[M,K] @ W[N,K]^T + bias) ----------------
// BMx128 tile, BK=16, double-buffered, 256 threads, vectorized loads.
// Requires: M%BM==0, N%128==0, K%16==0, K%4==0.
template <int BM, int TM, bool RELU>
__global__ __launch_bounds__(256) void so2_gemm_big(
    const float* __restrict__ A, const float* __restrict__ W,
    const float* __restrict__ bias, float* __restrict__ C,
    int M, int N, int K)
{
    const int BN = 128, BK = 16, TN = 8;
    const int NA = BM / 64;   // float4 A loads per thread
    const int NW = 2;         // float4 W loads per thread
    __shared__ float As[2][BK][BM];
    __shared__ float Ws[2][BK][BN];
    int bm = blockIdx.y * BM, bn = blockIdx.x * BN;
    int tid = threadIdx.x;
    int tr = (tid / 16) * TM;
    int tc = (tid % 16) * TN;

    float4 pa[NA], pw[NW];

    auto fetch = [&](int k0) {
#pragma unroll
        for (int i = 0; i < NA; i++) {
            int l = tid + i * 256;
            int row = l >> 2, kq = (l & 3) * 4;
            pa[i] = *(const float4*)(A + (size_t)(bm + row) * K + k0 + kq);
        }
#pragma unroll
        for (int i = 0; i < NW; i++) {
            int l = tid + i * 256;
            int row = l >> 2, kq = (l & 3) * 4;
            pw[i] = *(const float4*)(W + (size_t)(bn + row) * K + k0 + kq);
        }
    };
    auto put = [&](int buf) {
#pragma unroll
        for (int i = 0; i < NA; i++) {
            int l = tid + i * 256;
            int row = l >> 2, kq = (l & 3) * 4;
            As[buf][kq + 0][row] = pa[i].x; As[buf][kq + 1][row] = pa[i].y;
            As[buf][kq + 2][row] = pa[i].z; As[buf][kq + 3][row] = pa[i].w;
        }
#pragma unroll
        for (int i = 0; i < NW; i++) {
            int l = tid + i * 256;
            int row = l >> 2, kq = (l & 3) * 4;
            Ws[buf][kq + 0][row] = pw[i].x; Ws[buf][kq + 1][row] = pw[i].y;
            Ws[buf][kq + 2][row] = pw[i].z; Ws[buf][kq + 3][row] = pw[i].w;
        }
    };

    float acc[TM][TN];
#pragma unroll
    for (int i = 0; i < TM; i++)
#pragma unroll
        for (int j = 0; j < TN; j++) acc[i][j] = 0.f;

    fetch(0);
    put(0);
    __syncthreads();
    int nt = K / BK;
    for (int t = 0; t < nt; t++) {
        int buf = t & 1;
        if (t + 1 < nt) fetch((t + 1) * BK);
#pragma unroll
        for (int kk = 0; kk < BK; kk++) {
            float a[TM], w[TN];
#pragma unroll
            for (int i = 0; i < TM / 4; i++)
                *(float4*)&a[i * 4] = *(const float4*)&As[buf][kk][tr + i * 4];
#pragma unroll
            for (int j = 0; j < TN / 4; j++)
                *(float4*)&w[j * 4] = *(const float4*)&Ws[buf][kk][tc + j * 4];
#pragma unroll
            for (int i = 0; i < TM; i++)
#pragma unroll
                for (int j = 0; j < TN; j++) acc[i][j] = fmaf(a[i], w[j], acc[i][j]);
        }
        if (t + 1 < nt) put(buf ^ 1);
        __syncthreads();
    }

    float bj[TN];
#pragma unroll
    for (int j = 0; j < TN; j++) bj[j] = bias ? bias[bn + tc + j] : 0.f;
#pragma unroll
    for (int i = 0; i < TM; i++) {
        int gm = bm + tr + i;
        float v[TN];
#pragma unroll
        for (int j = 0; j < TN; j++) {
            v[j] = acc[i][j] + bj[j];
            if (RELU) v[j] = fmaxf(v[j], 0.f);
        }
        *(float4*)(C + (size_t)gm * N + bn + tc) = make_float4(v[0], v[1], v[2], v[3]);
        *(float4*)(C + (size_t)gm * N + bn + tc + 4) = make_float4(v[4], v[5], v[6], v[7]);
    }
}

// ---------------- small fused GEMM: N=128, optional fused row-L2-normalize ----------------
// BM=32, BN=128, BK=16, 256 threads, grid = 128 blocks. Each warp owns 4 full rows.
template <bool RELU, bool NORM, bool K4>
__global__ __launch_bounds__(256) void so2_gemm_small(
    const float* __restrict__ A, const float* __restrict__ W,
    const float* __restrict__ bias, float* __restrict__ Craw,
    float* __restrict__ Cnorm, int K)
{
    const int BM = 32, BN = 128, BK = 16;
    __shared__ float As[BK][BM];
    __shared__ float Ws[BK][BN];
    int bm = blockIdx.x * BM;
    int tid = threadIdx.x;
    int warp = tid >> 5, lane = tid & 31;
    int tr = warp * 4;
    int tc = lane * 4;

    float acc[4][4];
#pragma unroll
    for (int i = 0; i < 4; i++)
#pragma unroll
        for (int j = 0; j < 4; j++) acc[i][j] = 0.f;

    int nt = (K + BK - 1) / BK;
    for (int t = 0; t < nt; t++) {
        int k0 = t * BK;
        if (K4) {
            if (tid < 128) {
                int row = tid >> 2, kq = (tid & 3) * 4;
                float4 v = *(const float4*)(A + (size_t)(bm + row) * K + k0 + kq);
                As[kq + 0][row] = v.x; As[kq + 1][row] = v.y;
                As[kq + 2][row] = v.z; As[kq + 3][row] = v.w;
            }
#pragma unroll
            for (int i = 0; i < 2; i++) {
                int l = tid + i * 256;
                int row = l >> 2, kq = (l & 3) * 4;
                float4 v = *(const float4*)(W + (size_t)row * K + k0 + kq);
                Ws[kq + 0][row] = v.x; Ws[kq + 1][row] = v.y;
                Ws[kq + 2][row] = v.z; Ws[kq + 3][row] = v.w;
            }
        } else {
            for (int idx = tid; idx < BM * BK; idx += 256) {
                int r = idx >> 4, c = idx & 15;
                int gk = k0 + c;
                As[c][r] = (gk < K) ? A[(size_t)(bm + r) * K + gk] : 0.f;
            }
            for (int idx = tid; idx < BN * BK; idx += 256) {
                int r = idx >> 4, c = idx & 15;
                int gk = k0 + c;
                Ws[c][r] = (gk < K) ? W[(size_t)r * K + gk] : 0.f;
            }
        }
        __syncthreads();
#pragma unroll
        for (int kk = 0; kk < BK; kk++) {
            float a[4], w[4];
            *(float4*)a = *(const float4*)&As[kk][tr];
            *(float4*)w = *(const float4*)&Ws[kk][tc];
#pragma unroll
            for (int i = 0; i < 4; i++)
#pragma unroll
                for (int j = 0; j < 4; j++) acc[i][j] = fmaf(a[i], w[j], acc[i][j]);
        }
        __syncthreads();
    }

    float b[4];
#pragma unroll
    for (int j = 0; j < 4; j++) b[j] = bias[tc + j];
    float v[4][4];
#pragma unroll
    for (int i = 0; i < 4; i++) {
#pragma unroll
        for (int j = 0; j < 4; j++) {
            v[i][j] = acc[i][j] + b[j];
            if (RELU) v[i][j] = fmaxf(v[i][j], 0.f);
        }
        *(float4*)(Craw + (size_t)(bm + tr + i) * 128 + tc) =
            make_float4(v[i][0], v[i][1], v[i][2], v[i][3]);
    }
    if (NORM) {
#pragma unroll
        for (int i = 0; i < 4; i++) {
            float s = v[i][0] * v[i][0] + v[i][1] * v[i][1] +
                      v[i][2] * v[i][2] + v[i][3] * v[i][3];
            s = wsum(s);
            float inv = 1.0f / fmaxf(sqrtf(s), 1e-12f);
            *(float4*)(Cnorm + (size_t)(bm + tr + i) * 128 + tc) =
                make_float4(v[i][0] * inv, v[i][1] * inv, v[i][2] * inv, v[i][3] * inv);
        }
    }
}

// ---------------- per-row softmax term (no max shift needed; |logit|<=~14.3) ----------------
__device__ __forceinline__ float so2_row_term(
    float Z, float X, float P, float L, float Lm, int c)
{
    float lse = logf(Z);
    float sum_p_logit = X / Z;
    float pmatch = P / Z;
    int n0 = g_n0;
    float nc = (c == 0) ? (float)n0 : (float)(BATCH - n0);
    float no = (float)BATCH - nc;
    float u = 1.0f / nc;
    float eu = expf(u);
    float denom = nc * eu + no;
    float lden = logf(denom);
    float lqm = u - lden;
    float lqn = -lden;
    float qm = eu / denom;
    float qn = 1.0f / denom;
    float sum_q_lq = nc * qm * lqm + no * qn * lqn;
    float sum_q_lp = qm * Lm + qn * (L - Lm) - lse;
    float sum_p_lp = sum_p_logit - lse;
    float sum_p_lq = lqm * pmatch + lqn * (1.0f - pmatch);
    return (sum_q_lq - sum_q_lp) + (sum_p_lp - sum_p_lq);
}

// ---------------- row reduction over M (logit = exp(*log_scale)*M[k,:]) ----------------
__global__ __launch_bounds__(256) void so2_row_reduce(
    const int* __restrict__ y, const float* __restrict__ log_scale, int acc_idx)
{
    int k = blockIdx.x;
    float s = expf(*log_scale);
    int c = y[k];
    const float4* row = (const float4*)(g_M + (size_t)k * BATCH);
    float Z = 0.f, X = 0.f, P = 0.f, L = 0.f, Lm = 0.f;
#pragma unroll
    for (int it = 0; it < 4; it++) {
        int j4 = threadIdx.x + it * 256;
        float4 vv = row[j4];
        float lv[4] = {vv.x, vv.y, vv.z, vv.w};
#pragma unroll
        for (int q = 0; q < 4; q++) {
            float l = s * lv[q];
            float e = fexp(l);
            Z += e; X += e * l; L += l;
            if (__ldg(&y[j4 * 4 + q]) == c) { P += e; Lm += l; }
        }
    }
    Z = wsum(Z); X = wsum(X); P = wsum(P); L = wsum(L); Lm = wsum(Lm);
    __shared__ float sZ[8], sX[8], sP[8], sL[8], sLm[8];
    int warp = threadIdx.x >> 5, lane = threadIdx.x & 31;
    if (lane == 0) { sZ[warp] = Z; sX[warp] = X; sP[warp] = P; sL[warp] = L; sLm[warp] = Lm; }
    __syncthreads();
    if (threadIdx.x == 0) {
        float tZ = 0, tX = 0, tP = 0, tL = 0, tLm = 0;
#pragma unroll
        for (int w = 0; w < 8; w++) { tZ += sZ[w]; tX += sX[w]; tP += sP[w]; tL += sL[w]; tLm += sLm[w]; }
        float term = so2_row_term(tZ, tX, tP, tL, tLm, c);
        atomicAdd(&g_acc[acc_idx], (double)term);
    }
}

// ---------------- column reduction over M (logit = M[:,k], no scale) ----------------
__global__ __launch_bounds__(256) void so2_col_reduce(const int* __restrict__ y, int acc_idx)
{
    __shared__ char sy[BATCH];
    int tid = threadIdx.y * 32 + threadIdx.x;
    for (int j = tid; j < BATCH; j += 256) sy[j] = (char)y[j];
    __syncthreads();
    int tx = threadIdx.x, ty = threadIdx.y;
    int col = blockIdx.x * 32 + tx;
    char c = sy[col];
    float Z = 0.f, X = 0.f, P = 0.f, L = 0.f, Lm = 0.f;
#pragma unroll 4
    for (int j = ty; j < BATCH; j += 8) {
        float l = g_M[(size_t)j * BATCH + col];
        float e = fexp(l);
        Z += e; X += e * l; L += l;
        if (sy[j] == c) { P += e; Lm += l; }
    }
    __shared__ float sm[8][32][5];
    sm[ty][tx][0] = Z; sm[ty][tx][1] = X; sm[ty][tx][2] = P;
    sm[ty][tx][3] = L; sm[ty][tx][4] = Lm;
    __syncthreads();
    if (ty == 0) {
#pragma unroll
        for (int o = 1; o < 8; o++) {
            Z += sm[o][tx][0]; X += sm[o][tx][1]; P += sm[o][tx][2];
            L += sm[o][tx][3]; Lm += sm[o][tx][4];
        }
        float term = so2_row_term(Z, X, P, L, Lm, (int)c);
        atomicAdd(&g_acc[acc_idx], (double)term);
    }
}

// ---------------- sum over (A^T A) .* (B^T B) for Frobenius trick ----------------
__global__ void so2_gram_pair(const float* __restrict__ A, const float* __restrict__ Bm,
                              int acc_idx)
{
    __shared__ float Au[16][17], Av[16][17], Bu[16][17], Bv[16][17];
    int u0 = blockIdx.x * 16, v0 = blockIdx.y * 16;
    int tx = threadIdx.x, ty = threadIdx.y;
    float ga = 0.f, gb = 0.f;
    for (int r0 = 0; r0 < BATCH; r0 += 16) {
        Au[ty][tx] = A[(r0 + ty) * 128 + u0 + tx];
        Av[ty][tx] = A[(r0 + ty) * 128 + v0 + tx];
        Bu[ty][tx] = Bm[(r0 + ty) * 128 + u0 + tx];
        Bv[ty][tx] = Bm[(r0 + ty) * 128 + v0 + tx];
        __syncthreads();
#pragma unroll
        for (int rr = 0; rr < 16; rr++) {
            ga += Au[rr][tx] * Av[rr][ty];
            gb += Bu[rr][tx] * Bv[rr][ty];
        }
        __syncthreads();
    }
    __shared__ float red[256];
    int t = ty * 16 + tx;
    red[t] = ga * gb;
    __syncthreads();
    for (int off = 128; off > 0; off >>= 1) {
        if (t < off) red[t] += red[t + off];
        __syncthreads();
    }
    if (t == 0) atomicAdd(&g_acc[acc_idx], (double)red[0]);
}

// ---------------- 4 head outputs ----------------
__global__ void so2_head_out(
    const float* __restrict__ c1w, const float* __restrict__ c1b,
    const float* __restrict__ c2w, const float* __restrict__ c2b,
    const float* __restrict__ c3w, const float* __restrict__ c3b,
    const float* __restrict__ c4w, const float* __restrict__ c4b,
    float* __restrict__ out)
{
    int r = blockIdx.x, t = threadIdx.x;  // 128 threads
    __shared__ float red[4][128];
    red[0][t] = g_isp[r * 128 + t] * c1w[t];
    red[1][t] = g_ish[r * 128 + t] * c2w[t];
    red[2][t] = g_tsp[r * 128 + t] * c4w[t];
    red[3][t] = g_tsh[r * 128 + t] * c3w[t];
    __syncthreads();
    for (int off = 64; off > 0; off >>= 1) {
        if (t < off) {
#pragma unroll
            for (int a = 0; a < 4; a++) red[a][t] += red[a][t + off];
        }
        __syncthreads();
    }
    if (t == 0) {
        out[1 + r]             = red[0][0] + c1b[0];
        out[1 + BATCH + r]     = red[1][0] + c2b[0];
        out[1 + 2 * BATCH + r] = red[2][0] + c4b[0];
        out[1 + 3 * BATCH + r] = red[3][0] + c3b[0];
    }
}

// ---------------- final loss combine ----------------
__global__ void so2_finalize(float* __restrict__ out) {
    double loss_sp = 0.5 * (sqrt(g_acc[2]) + sqrt(g_acc[3]));
    double loss1 = g_acc[0] / (4.0 * BATCH);
    double loss_sh = g_acc[1] / (4.0 * BATCH);
    out[0] = (float)((loss_sp + loss_sh + loss1) / 3.0);
}

// ---------------- host driver ----------------
extern "C" void kernel_launch(void* const* d_in, const int* in_sizes, int n_in,
                              void* d_out, int out_size) {
    const float* i_   = (const float*)d_in[0];
    const float* t_   = (const float*)d_in[1];
    const int*   y    = (const int*)d_in[2];
    const float* l1w  = (const float*)d_in[3];  const float* l1b = (const float*)d_in[4];
    const float* l2w  = (const float*)d_in[5];  const float* l2b = (const float*)d_in[6];
    const float* l3w  = (const float*)d_in[7];  const float* l3b = (const float*)d_in[8];
    const float* tl1w = (const float*)d_in[9];  const float* tl1b = (const float*)d_in[10];
    const float* tl2w = (const float*)d_in[11]; const float* tl2b = (const float*)d_in[12];
    const float* ispw = (const float*)d_in[13]; const float* ispb = (const float*)d_in[14];
    const float* ishw = (const float*)d_in[15]; const float* ishb = (const float*)d_in[16];
    const float* tshw = (const float*)d_in[17]; const float* tshb = (const float*)d_in[18];
    const float* tspw = (const float*)d_in[19]; const float* tspb = (const float*)d_in[20];
    const float* c1w  = (const float*)d_in[21]; const float* c1b = (const float*)d_in[22];
    const float* c2w  = (const float*)d_in[23]; const float* c2b = (const float*)d_in[24];
    const float* c3w  = (const float*)d_in[25]; const float* c3b = (const float*)d_in[26];
    const float* c4w  = (const float*)d_in[27]; const float* c4b = (const float*)d_in[28];
    const float* scale1 = (const float*)d_in[29];
    const float* scale2 = (const float*)d_in[30];
    float* out = (float*)d_out;

    float *pM, *pfi1, *pfi2, *pfi3, *pfi3n, *pft1, *pft2, *pft2n;
    float *pisp, *pish, *pishn, *ptsh, *ptshn, *ptsp;
    cudaGetSymbolAddress((void**)&pM, g_M);
    cudaGetSymbolAddress((void**)&pfi1, g_fi1);
    cudaGetSymbolAddress((void**)&pfi2, g_fi2);
    cudaGetSymbolAddress((void**)&pfi3, g_fi3);
    cudaGetSymbolAddress((void**)&pfi3n, g_fi3n);
    cudaGetSymbolAddress((void**)&pft1, g_ft1);
    cudaGetSymbolAddress((void**)&pft2, g_ft2);
    cudaGetSymbolAddress((void**)&pft2n, g_ft2n);
    cudaGetSymbolAddress((void**)&pisp, g_isp);
    cudaGetSymbolAddress((void**)&pish, g_ish);
    cudaGetSymbolAddress((void**)&pishn, g_ishn);
    cudaGetSymbolAddress((void**)&ptsh, g_tsh);
    cudaGetSymbolAddress((void**)&ptshn, g_tshn);
    cudaGetSymbolAddress((void**)&ptsp, g_tsp);

    so2_init<<<1, 256>>>(y);

    // image MLP
    so2_gemm_big<128, 8, true><<<dim3(4, 32), 256>>>(i_,   l1w, l1b, pfi1, BATCH, 512, 2048);
    so2_gemm_big<64,  4, true><<<dim3(2, 64), 256>>>(pfi1, l2w, l2b, pfi2, BATCH, 256, 512);
    so2_gemm_small<false, true,  true ><<<128, 256>>>(pfi2, l3w, l3b, pfi3, pfi3n, 256);
    // tab MLP
    so2_gemm_small<true,  false, false><<<128, 256>>>(t_,   tl1w, tl1b, pft1, nullptr, 49);
    so2_gemm_small<false, true,  true ><<<128, 256>>>(pft1, tl2w, tl2b, pft2, pft2n, 128);
    // SS heads
    so2_gemm_small<false, false, true ><<<128, 256>>>(pfi3, ispw, ispb, pisp, nullptr, 128);
    so2_gemm_small<false, true,  true ><<<128, 256>>>(pfi3, ishw, ishb, pish, pishn, 128);
    so2_gemm_small<false, true,  true ><<<128, 256>>>(pft2, tshw, tshb, ptsh, ptshn, 128);
    so2_gemm_small<false, false, true ><<<128, 256>>>(pft2, tspw, tspb, ptsp, nullptr, 128);

    // ---- clip loss 1 on (fi3, ft2) ----
    so2_gemm_big<128, 8, false><<<dim3(32, 32), 256>>>(pfi3n, pft2n, (const float*)nullptr, pM, BATCH, BATCH, 128);
    so2_row_reduce<<<BATCH, 256>>>(y, scale1, 0);
    so2_col_reduce<<<BATCH / 32, dim3(32, 8)>>>(y, 0);

    // ---- clip loss 2 on (i_sh, t_sh) ----
    so2_gemm_big<128, 8, false><<<dim3(32, 32), 256>>>(pishn, ptshn, (const float*)nullptr, pM, BATCH, BATCH, 128);
    so2_row_reduce<<<BATCH, 256>>>(y, scale2, 1);
    so2_col_reduce<<<BATCH / 32, dim3(32, 8)>>>(y, 1);

    // ---- separate loss via Gram trick ----
    so2_gram_pair<<<dim3(8, 8), dim3(16, 16)>>>(ptsp, ptsh, 2);
    so2_gram_pair<<<dim3(8, 8), dim3(16, 16)>>>(pisp, pish, 3);

    // ---- outputs ----
    so2_head_out<<<BATCH, 128>>>(c1w, c1b, c2w, c2b, c3w, c3b, c4w, c4b, out);
    so2_finalize<<<1, 1>>>(out);
}

// round 9
// speedup vs baseline: 2.7455x; 1.3312x over previous
#include <cuda_runtime.h>
#include <cuda_bf16.h>
#include <cstdint>
#include <stdint.h>
#include <math.h>

#define BATCH 4096

// ==================== scratch (device globals) ====================
__device__ float g_M[(size_t)BATCH * BATCH];            // 64MB similarity matrix
__device__ __nv_bfloat16 g_ihi[(size_t)BATCH * 2048];
__device__ __nv_bfloat16 g_ilo[(size_t)BATCH * 2048];
__device__ __nv_bfloat16 g_w1h[512 * 2048];
__device__ __nv_bfloat16 g_w1l[512 * 2048];
__device__ __nv_bfloat16 g_w2h[256 * 512];
__device__ __nv_bfloat16 g_w2l[256 * 512];
__device__ __nv_bfloat16 g_f1h[(size_t)BATCH * 512];
__device__ __nv_bfloat16 g_f1l[(size_t)BATCH * 512];
__device__ float g_fi2[BATCH * 256];
__device__ float g_fi3[BATCH * 128];
__device__ float g_ft1[BATCH * 128];
__device__ float g_ft2[BATCH * 128];
__device__ float g_isp[BATCH * 128];
__device__ float g_ish[BATCH * 128];
__device__ float g_tsh[BATCH * 128];
__device__ float g_tsp[BATCH * 128];
__device__ __nv_bfloat16 g_fi3nh[BATCH * 128];
__device__ __nv_bfloat16 g_fi3nl[BATCH * 128];
__device__ __nv_bfloat16 g_ft2nh[BATCH * 128];
__device__ __nv_bfloat16 g_ft2nl[BATCH * 128];
__device__ __nv_bfloat16 g_ishnh[BATCH * 128];
__device__ __nv_bfloat16 g_ishnl[BATCH * 128];
__device__ __nv_bfloat16 g_tshnh[BATCH * 128];
__device__ __nv_bfloat16 g_tshnl[BATCH * 128];
__device__ double g_acc[4];      // [0]=clip1, [1]=clip2, [2]=S_t, [3]=S_i
__device__ int g_n0;

// ==================== helpers ====================
__device__ __forceinline__ uint32_t s2u(const void* p) {
    uint32_t a;
    asm("{ .reg .u64 t; cvta.to.shared.u64 t, %1; cvt.u32.u64 %0, t; }" : "=r"(a) : "l"(p));
    return a;
}
__device__ __forceinline__ void ldmx4(uint32_t (&r)[4], uint32_t addr) {
    asm volatile("ldmatrix.sync.aligned.m8n8.x4.shared.b16 {%0,%1,%2,%3}, [%4];"
                 : "=r"(r[0]), "=r"(r[1]), "=r"(r[2]), "=r"(r[3]) : "r"(addr));
}
__device__ __forceinline__ void mma16816(float (&d)[4], const uint32_t (&a)[4],
                                         uint32_t b0, uint32_t b1) {
    asm volatile(
        "mma.sync.aligned.m16n8k16.row.col.f32.bf16.bf16.f32 "
        "{%0,%1,%2,%3}, {%4,%5,%6,%7}, {%8,%9}, {%0,%1,%2,%3};"
        : "+f"(d[0]), "+f"(d[1]), "+f"(d[2]), "+f"(d[3])
        : "r"(a[0]), "r"(a[1]), "r"(a[2]), "r"(a[3]), "r"(b0), "r"(b1));
}

__device__ __forceinline__ float fexp(float x) {
    float t = x * 1.4426950408889634f;
    float fi = floorf(t);
    float f = t - fi;
    float p = 1.52527338e-5f;
    p = fmaf(p, f, 1.54035304e-4f);
    p = fmaf(p, f, 1.33335581e-3f);
    p = fmaf(p, f, 9.61812911e-3f);
    p = fmaf(p, f, 5.55041087e-2f);
    p = fmaf(p, f, 2.40226507e-1f);
    p = fmaf(p, f, 6.93147181e-1f);
    p = fmaf(p, f, 1.0f);
    int i = (int)fi;
    return __int_as_float((i + 127) << 23) * p;
}
__device__ __forceinline__ float wsum(float v) {
#pragma unroll
    for (int o = 16; o > 0; o >>= 1) v += __shfl_xor_sync(0xffffffffu, v, o);
    return v;
}

// ==================== init ====================
__global__ void so2_init(const int* __restrict__ y) {
    __shared__ int cnt[256];
    int t = threadIdx.x;
    int c = 0;
    for (int j = t; j < BATCH; j += 256) c += (y[j] == 0) ? 1 : 0;
    cnt[t] = c;
    __syncthreads();
    for (int off = 128; off > 0; off >>= 1) {
        if (t < off) cnt[t] += cnt[t + off];
        __syncthreads();
    }
    if (t == 0) {
        g_n0 = cnt[0];
        g_acc[0] = 0.0; g_acc[1] = 0.0; g_acc[2] = 0.0; g_acc[3] = 0.0;
    }
}

// ==================== fp32 -> bf16 hi/lo split ====================
__global__ void so2_split(const float* __restrict__ x, __nv_bfloat16* __restrict__ hi,
                          __nv_bfloat16* __restrict__ lo, int n4) {
    int idx = blockIdx.x * blockDim.x + threadIdx.x;
    if (idx >= n4) return;
    float4 v = ((const float4*)x)[idx];
    float vv[4] = {v.x, v.y, v.z, v.w};
    unsigned short hs[4], ls[4];
#pragma unroll
    for (int j = 0; j < 4; j++) {
        __nv_bfloat16 h = __float2bfloat16(vv[j]);
        __nv_bfloat16 l = __float2bfloat16(vv[j] - __bfloat162float(h));
        hs[j] = __bfloat16_as_ushort(h);
        ls[j] = __bfloat16_as_ushort(l);
    }
    uint2 uh, ul;
    uh.x = (uint32_t)hs[0] | ((uint32_t)hs[1] << 16);
    uh.y = (uint32_t)hs[2] | ((uint32_t)hs[3] << 16);
    ul.x = (uint32_t)ls[0] | ((uint32_t)ls[1] << 16);
    ul.y = (uint32_t)ls[2] | ((uint32_t)ls[3] << 16);
    ((uint2*)hi)[idx] = uh;
    ((uint2*)lo)[idx] = ul;
}

// ==================== HMMA GEMM (NT): C = act(A[M,K] @ B[N,K]^T + bias) ====================
// mma.sync.m16n8k16 bf16 (portable sm_80+; no tcgen05 needed).
// 128x128 CTA tile, BK=32, 8 warps (2 warp-rows x 4 warp-cols), warp tile 64x32.
// SPLIT: A/B are bf16 hi+lo pairs; 3 MMA products (hh+hl+lh) give ~fp32 accuracy.
// OUTM==0: fp32 C.  OUTM==1: bf16 hi/lo split output (Ch, Cl).
template <bool SPLIT, bool RELU, int OUTM>
__global__ __launch_bounds__(256) void so2_gemm_mma(
    const __nv_bfloat16* __restrict__ Ah, const __nv_bfloat16* __restrict__ Al,
    const __nv_bfloat16* __restrict__ Bh, const __nv_bfloat16* __restrict__ Bl,
    const float* __restrict__ bias,
    float* __restrict__ Cf, __nv_bfloat16* __restrict__ Ch, __nv_bfloat16* __restrict__ Cl,
    int N, int K)
{
    constexpr int NTL = SPLIT ? 4 : 2;
    constexpr int LDSB = 80;                 // bytes per SMEM row (40 bf16, conflict-free)
    constexpr int TILEB = 128 * LDSB;        // 10240 bytes per tile
    __shared__ __align__(16) char smem[NTL * TILEB];
    uint32_t sbase = s2u(smem);

    int tid = threadIdx.x, lane = tid & 31, wid = tid >> 5;
    int wrow = wid & 1, wcol = wid >> 1;     // 2 x 4 warp grid
    int rbA = blockIdx.y * 128, rbB = blockIdx.x * 128;

    const __nv_bfloat16* srcs[4] = {Ah, SPLIT ? Al : Bh, Bh, Bl};
    int rbs[4] = {rbA, SPLIT ? rbA : rbB, rbB, rbB};

    float acc[4][4][4];
#pragma unroll
    for (int a = 0; a < 4; a++)
#pragma unroll
        for (int b = 0; b < 4; b++)
#pragma unroll
            for (int c = 0; c < 4; c++) acc[a][b][c] = 0.f;

    uint4 st[NTL][2];
    auto fetch = [&](int k0) {
#pragma unroll
        for (int j = 0; j < NTL; j++)
#pragma unroll
            for (int i = 0; i < 2; i++) {
                int idx = tid + i * 256;
                int row = idx >> 2, seg = idx & 3;
                st[j][i] = *(const uint4*)(srcs[j] + (size_t)(rbs[j] + row) * K + k0 + seg * 8);
            }
    };
    auto stash = [&]() {
#pragma unroll
        for (int j = 0; j < NTL; j++)
#pragma unroll
            for (int i = 0; i < 2; i++) {
                int idx = tid + i * 256;
                int row = idx >> 2, seg = idx & 3;
                *(uint4*)(smem + j * TILEB + row * LDSB + seg * 16) = st[j][i];
            }
    };

    // per-lane ldmatrix address bases (addr = base + subtile_row*LDSB + phase*32)
    uint32_t aBase = sbase + (uint32_t)((wrow * 64 + (lane & 15)) * LDSB + (lane >> 4) * 16);
    uint32_t bBase = sbase + (uint32_t)((wcol * 32 + (lane & 15)) * LDSB + (lane >> 4) * 16);
    const int BT0 = SPLIT ? 2 : 1;   // tile index of B-hi

    int NCH = K >> 5;
    fetch(0);
    for (int t = 0; t < NCH; t++) {
        stash();
        __syncthreads();
        if (t + 1 < NCH) fetch((t + 1) << 5);
#pragma unroll
        for (int p = 0; p < 2; p++) {
            uint32_t aH[4][4], bH[2][4];
            uint32_t aL[4][4], bL[2][4];
#pragma unroll
            for (int mi = 0; mi < 4; mi++)
                ldmx4(aH[mi], aBase + 0 * TILEB + mi * 16 * LDSB + p * 32);
            if (SPLIT) {
#pragma unroll
                for (int mi = 0; mi < 4; mi++)
                    ldmx4(aL[mi], aBase + 1 * TILEB + mi * 16 * LDSB + p * 32);
            }
#pragma unroll
            for (int np = 0; np < 2; np++)
                ldmx4(bH[np], bBase + BT0 * TILEB + np * 16 * LDSB + p * 32);
            if (SPLIT) {
#pragma unroll
                for (int np = 0; np < 2; np++)
                    ldmx4(bL[np], bBase + 3 * TILEB + np * 16 * LDSB + p * 32);
            }
#pragma unroll
            for (int mi = 0; mi < 4; mi++)
#pragma unroll
                for (int nt = 0; nt < 4; nt++) {
                    int np = nt >> 1, s = nt & 1;
                    mma16816(acc[mi][nt], aH[mi], bH[np][s], bH[np][2 + s]);
                    if (SPLIT) {
                        mma16816(acc[mi][nt], aH[mi], bL[np][s], bL[np][2 + s]);
                        mma16816(acc[mi][nt], aL[mi], bH[np][s], bH[np][2 + s]);
                    }
                }
        }
        __syncthreads();
    }

    // epilogue
    int g = lane >> 2, tig = lane & 3;
#pragma unroll
    for (int mi = 0; mi < 4; mi++)
#pragma unroll
        for (int q2 = 0; q2 < 2; q2++) {
            int row = rbA + wrow * 64 + mi * 16 + g + q2 * 8;
            size_t rowoff = (size_t)row * N;
#pragma unroll
            for (int nt = 0; nt < 4; nt++) {
                int col = rbB + wcol * 32 + nt * 8 + tig * 2;
                float v0 = acc[mi][nt][q2 * 2 + 0];
                float v1 = acc[mi][nt][q2 * 2 + 1];
                if (bias) { v0 += __ldg(bias + col); v1 += __ldg(bias + col + 1); }
                if (RELU) { v0 = fmaxf(v0, 0.f); v1 = fmaxf(v1, 0.f); }
                if (OUTM == 0) {
                    *(float2*)(Cf + rowoff + col) = make_float2(v0, v1);
                } else {
                    __nv_bfloat16 h0 = __float2bfloat16(v0), h1 = __float2bfloat16(v1);
                    __nv_bfloat16 l0 = __float2bfloat16(v0 - __bfloat162float(h0));
                    __nv_bfloat16 l1 = __float2bfloat16(v1 - __bfloat162float(h1));
                    uint32_t hp = (uint32_t)__bfloat16_as_ushort(h0) |
                                  ((uint32_t)__bfloat16_as_ushort(h1) << 16);
                    uint32_t lp = (uint32_t)__bfloat16_as_ushort(l0) |
                                  ((uint32_t)__bfloat16_as_ushort(l1) << 16);
                    *(uint32_t*)(Ch + rowoff + col) = hp;
                    *(uint32_t*)(Cl + rowoff + col) = lp;
                }
            }
        }
}

// ==================== small fused GEMM: N=128, optional fused L2-normalize -> bf16 hi/lo ====================
template <bool RELU, bool NORM, bool K4>
__global__ __launch_bounds__(256) void so2_gemm_small(
    const float* __restrict__ A, const float* __restrict__ W,
    const float* __restrict__ bias, float* __restrict__ Craw,
    __nv_bfloat16* __restrict__ Cnh, __nv_bfloat16* __restrict__ Cnl, int K)
{
    const int BM = 32, BN = 128, BK = 16;
    __shared__ float As[BK][BM];
    __shared__ float Ws[BK][BN];
    int bm = blockIdx.x * BM;
    int tid = threadIdx.x;
    int warp = tid >> 5, lane = tid & 31;
    int tr = warp * 4;
    int tc = lane * 4;

    float acc[4][4];
#pragma unroll
    for (int i = 0; i < 4; i++)
#pragma unroll
        for (int j = 0; j < 4; j++) acc[i][j] = 0.f;

    int nt = (K + BK - 1) / BK;
    for (int t = 0; t < nt; t++) {
        int k0 = t * BK;
        if (K4) {
            if (tid < 128) {
                int row = tid >> 2, kq = (tid & 3) * 4;
                float4 v = *(const float4*)(A + (size_t)(bm + row) * K + k0 + kq);
                As[kq + 0][row] = v.x; As[kq + 1][row] = v.y;
                As[kq + 2][row] = v.z; As[kq + 3][row] = v.w;
            }
#pragma unroll
            for (int i = 0; i < 2; i++) {
                int l = tid + i * 256;
                int row = l >> 2, kq = (l & 3) * 4;
                float4 v = *(const float4*)(W + (size_t)row * K + k0 + kq);
                Ws[kq + 0][row] = v.x; Ws[kq + 1][row] = v.y;
                Ws[kq + 2][row] = v.z; Ws[kq + 3][row] = v.w;
            }
        } else {
            for (int idx = tid; idx < BM * BK; idx += 256) {
                int r = idx >> 4, c = idx & 15;
                int gk = k0 + c;
                As[c][r] = (gk < K) ? A[(size_t)(bm + r) * K + gk] : 0.f;
            }
            for (int idx = tid; idx < BN * BK; idx += 256) {
                int r = idx >> 4, c = idx & 15;
                int gk = k0 + c;
                Ws[c][r] = (gk < K) ? W[(size_t)r * K + gk] : 0.f;
            }
        }
        __syncthreads();
#pragma unroll
        for (int kk = 0; kk < BK; kk++) {
            float a[4], w[4];
            *(float4*)a = *(const float4*)&As[kk][tr];
            *(float4*)w = *(const float4*)&Ws[kk][tc];
#pragma unroll
            for (int i = 0; i < 4; i++)
#pragma unroll
                for (int j = 0; j < 4; j++) acc[i][j] = fmaf(a[i], w[j], acc[i][j]);
        }
        __syncthreads();
    }

    float b[4];
#pragma unroll
    for (int j = 0; j < 4; j++) b[j] = bias[tc + j];
    float v[4][4];
#pragma unroll
    for (int i = 0; i < 4; i++) {
#pragma unroll
        for (int j = 0; j < 4; j++) {
            v[i][j] = acc[i][j] + b[j];
            if (RELU) v[i][j] = fmaxf(v[i][j], 0.f);
        }
        *(float4*)(Craw + (size_t)(bm + tr + i) * 128 + tc) =
            make_float4(v[i][0], v[i][1], v[i][2], v[i][3]);
    }
    if (NORM) {
#pragma unroll
        for (int i = 0; i < 4; i++) {
            float s = v[i][0] * v[i][0] + v[i][1] * v[i][1] +
                      v[i][2] * v[i][2] + v[i][3] * v[i][3];
            s = wsum(s);
            float inv = 1.0f / fmaxf(sqrtf(s), 1e-12f);
            unsigned short hs[4], ls[4];
#pragma unroll
            for (int j = 0; j < 4; j++) {
                float x = v[i][j] * inv;
                __nv_bfloat16 h = __float2bfloat16(x);
                __nv_bfloat16 l = __float2bfloat16(x - __bfloat162float(h));
                hs[j] = __bfloat16_as_ushort(h);
                ls[j] = __bfloat16_as_ushort(l);
            }
            uint2 uh, ul;
            uh.x = (uint32_t)hs[0] | ((uint32_t)hs[1] << 16);
            uh.y = (uint32_t)hs[2] | ((uint32_t)hs[3] << 16);
            ul.x = (uint32_t)ls[0] | ((uint32_t)ls[1] << 16);
            ul.y = (uint32_t)ls[2] | ((uint32_t)ls[3] << 16);
            *(uint2*)(Cnh + (size_t)(bm + tr + i) * 128 + tc) = uh;
            *(uint2*)(Cnl + (size_t)(bm + tr + i) * 128 + tc) = ul;
        }
    }
}

// ==================== per-row softmax term ====================
__device__ __forceinline__ float so2_row_term(
    float Z, float X, float P, float L, float Lm, int c)
{
    float lse = logf(Z);
    float sum_p_logit = X / Z;
    float pmatch = P / Z;
    int n0 = g_n0;
    float nc = (c == 0) ? (float)n0 : (float)(BATCH - n0);
    float no = (float)BATCH - nc;
    float u = 1.0f / nc;
    float eu = expf(u);
    float denom = nc * eu + no;
    float lden = logf(denom);
    float lqm = u - lden;
    float lqn = -lden;
    float qm = eu / denom;
    float qn = 1.0f / denom;
    float sum_q_lq = nc * qm * lqm + no * qn * lqn;
    float sum_q_lp = qm * Lm + qn * (L - Lm) - lse;
    float sum_p_lp = sum_p_logit - lse;
    float sum_p_lq = lqm * pmatch + lqn * (1.0f - pmatch);
    return (sum_q_lq - sum_q_lp) + (sum_p_lp - sum_p_lq);
}

// ==================== row reduction over M ====================
__global__ __launch_bounds__(256) void so2_row_reduce(
    const int* __restrict__ y, const float* __restrict__ log_scale, int acc_idx)
{
    int k = blockIdx.x;
    float s = expf(*log_scale);
    int c = y[k];
    const float4* row = (const float4*)(g_M + (size_t)k * BATCH);
    float Z = 0.f, X = 0.f, P = 0.f, L = 0.f, Lm = 0.f;
#pragma unroll
    for (int it = 0; it < 4; it++) {
        int j4 = threadIdx.x + it * 256;
        float4 vv = row[j4];
        float lv[4] = {vv.x, vv.y, vv.z, vv.w};
#pragma unroll
        for (int q = 0; q < 4; q++) {
            float l = s * lv[q];
            float e = fexp(l);
            Z += e; X += e * l; L += l;
            if (__ldg(&y[j4 * 4 + q]) == c) { P += e; Lm += l; }
        }
    }
    Z = wsum(Z); X = wsum(X); P = wsum(P); L = wsum(L); Lm = wsum(Lm);
    __shared__ float sZ[8], sX[8], sP[8], sL[8], sLm[8];
    int warp = threadIdx.x >> 5, lane = threadIdx.x & 31;
    if (lane == 0) { sZ[warp] = Z; sX[warp] = X; sP[warp] = P; sL[warp] = L; sLm[warp] = Lm; }
    __syncthreads();
    if (threadIdx.x == 0) {
        float tZ = 0, tX = 0, tP = 0, tL = 0, tLm = 0;
#pragma unroll
        for (int w = 0; w < 8; w++) { tZ += sZ[w]; tX += sX[w]; tP += sP[w]; tL += sL[w]; tLm += sLm[w]; }
        float term = so2_row_term(tZ, tX, tP, tL, tLm, c);
        atomicAdd(&g_acc[acc_idx], (double)term);
    }
}

// ==================== column reduction over M ====================
__global__ __launch_bounds__(256) void so2_col_reduce(const int* __restrict__ y, int acc_idx)
{
    __shared__ char sy[BATCH];
    int tid = threadIdx.y * 32 + threadIdx.x;
    for (int j = tid; j < BATCH; j += 256) sy[j] = (char)y[j];
    __syncthreads();
    int tx = threadIdx.x, ty = threadIdx.y;
    int col = blockIdx.x * 32 + tx;
    char c = sy[col];
    float Z = 0.f, X = 0.f, P = 0.f, L = 0.f, Lm = 0.f;
#pragma unroll 4
    for (int j = ty; j < BATCH; j += 8) {
        float l = g_M[(size_t)j * BATCH + col];
        float e = fexp(l);
        Z += e; X += e * l; L += l;
        if (sy[j] == c) { P += e; Lm += l; }
    }
    __shared__ float sm[8][32][5];
    sm[ty][tx][0] = Z; sm[ty][tx][1] = X; sm[ty][tx][2] = P;
    sm[ty][tx][3] = L; sm[ty][tx][4] = Lm;
    __syncthreads();
    if (ty == 0) {
#pragma unroll
        for (int o = 1; o < 8; o++) {
            Z += sm[o][tx][0]; X += sm[o][tx][1]; P += sm[o][tx][2];
            L += sm[o][tx][3]; Lm += sm[o][tx][4];
        }
        float term = so2_row_term(Z, X, P, L, Lm, (int)c);
        atomicAdd(&g_acc[acc_idx], (double)term);
    }
}

// ==================== sum over (A^T A) .* (B^T B) ====================
__global__ void so2_gram_pair(const float* __restrict__ A, const float* __restrict__ Bm,
                              int acc_idx)
{
    __shared__ float Au[16][17], Av[16][17], Bu[16][17], Bv[16][17];
    int u0 = blockIdx.x * 16, v0 = blockIdx.y * 16;
    int tx = threadIdx.x, ty = threadIdx.y;
    float ga = 0.f, gb = 0.f;
    for (int r0 = 0; r0 < BATCH; r0 += 16) {
        Au[ty][tx] = A[(r0 + ty) * 128 + u0 + tx];
        Av[ty][tx] = A[(r0 + ty) * 128 + v0 + tx];
        Bu[ty][tx] = Bm[(r0 + ty) * 128 + u0 + tx];
        Bv[ty][tx] = Bm[(r0 + ty) * 128 + v0 + tx];
        __syncthreads();
#pragma unroll
        for (int rr = 0; rr < 16; rr++) {
            ga += Au[rr][tx] * Av[rr][ty];
            gb += Bu[rr][tx] * Bv[rr][ty];
        }
        __syncthreads();
    }
    __shared__ float red[256];
    int t = ty * 16 + tx;
    red[t] = ga * gb;
    __syncthreads();
    for (int off = 128; off > 0; off >>= 1) {
        if (t < off) red[t] += red[t + off];
        __syncthreads();
    }
    if (t == 0) atomicAdd(&g_acc[acc_idx], (double)red[0]);
}

// ==================== 4 head outputs ====================
__global__ void so2_head_out(
    const float* __restrict__ c1w, const float* __restrict__ c1b,
    const float* __restrict__ c2w, const float* __restrict__ c2b,
    const float* __restrict__ c3w, const float* __restrict__ c3b,
    const float* __restrict__ c4w, const float* __restrict__ c4b,
    float* __restrict__ out)
{
    int r = blockIdx.x, t = threadIdx.x;  // 128 threads
    __shared__ float red[4][128];
    red[0][t] = g_isp[r * 128 + t] * c1w[t];
    red[1][t] = g_ish[r * 128 + t] * c2w[t];
    red[2][t] = g_tsp[r * 128 + t] * c4w[t];
    red[3][t] = g_tsh[r * 128 + t] * c3w[t];
    __syncthreads();
    for (int off = 64; off > 0; off >>= 1) {
        if (t < off) {
#pragma unroll
            for (int a = 0; a < 4; a++) red[a][t] += red[a][t + off];
        }
        __syncthreads();
    }
    if (t == 0) {
        out[1 + r]             = red[0][0] + c1b[0];
        out[1 + BATCH + r]     = red[1][0] + c2b[0];
        out[1 + 2 * BATCH + r] = red[2][0] + c4b[0];
        out[1 + 3 * BATCH + r] = red[3][0] + c3b[0];
    }
}

// ==================== final loss combine ====================
__global__ void so2_finalize(float* __restrict__ out) {
    double loss_sp = 0.5 * (sqrt(g_acc[2]) + sqrt(g_acc[3]));
    double loss1 = g_acc[0] / (4.0 * BATCH);
    double loss_sh = g_acc[1] / (4.0 * BATCH);
    out[0] = (float)((loss_sp + loss_sh + loss1) / 3.0);
}

// ==================== host driver ====================
extern "C" void kernel_launch(void* const* d_in, const int* in_sizes, int n_in,
                              void* d_out, int out_size) {
    const float* i_   = (const float*)d_in[0];
    const float* t_   = (const float*)d_in[1];
    const int*   y    = (const int*)d_in[2];
    const float* l1w  = (const float*)d_in[3];  const float* l1b = (const float*)d_in[4];
    const float* l2w  = (const float*)d_in[5];  const float* l2b = (const float*)d_in[6];
    const float* l3w  = (const float*)d_in[7];  const float* l3b = (const float*)d_in[8];
    const float* tl1w = (const float*)d_in[9];  const float* tl1b = (const float*)d_in[10];
    const float* tl2w = (const float*)d_in[11]; const float* tl2b = (const float*)d_in[12];
    const float* ispw = (const float*)d_in[13]; const float* ispb = (const float*)d_in[14];
    const float* ishw = (const float*)d_in[15]; const float* ishb = (const float*)d_in[16];
    const float* tshw = (const float*)d_in[17]; const float* tshb = (const float*)d_in[18];
    const float* tspw = (const float*)d_in[19]; const float* tspb = (const float*)d_in[20];
    const float* c1w  = (const float*)d_in[21]; const float* c1b = (const float*)d_in[22];
    const float* c2w  = (const float*)d_in[23]; const float* c2b = (const float*)d_in[24];
    const float* c3w  = (const float*)d_in[25]; const float* c3b = (const float*)d_in[26];
    const float* c4w  = (const float*)d_in[27]; const float* c4b = (const float*)d_in[28];
    const float* scale1 = (const float*)d_in[29];
    const float* scale2 = (const float*)d_in[30];
    float* out = (float*)d_out;

    float *pM, *pfi2, *pfi3, *pft1, *pft2, *pisp, *pish, *ptsh, *ptsp;
    __nv_bfloat16 *pihi, *pilo, *pw1h, *pw1l, *pw2h, *pw2l, *pf1h, *pf1l;
    __nv_bfloat16 *pfi3nh, *pfi3nl, *pft2nh, *pft2nl, *pishnh, *pishnl, *ptshnh, *ptshnl;
    cudaGetSymbolAddress((void**)&pM, g_M);
    cudaGetSymbolAddress((void**)&pfi2, g_fi2);
    cudaGetSymbolAddress((void**)&pfi3, g_fi3);
    cudaGetSymbolAddress((void**)&pft1, g_ft1);
    cudaGetSymbolAddress((void**)&pft2, g_ft2);
    cudaGetSymbolAddress((void**)&pisp, g_isp);
    cudaGetSymbolAddress((void**)&pish, g_ish);
    cudaGetSymbolAddress((void**)&ptsh, g_tsh);
    cudaGetSymbolAddress((void**)&ptsp, g_tsp);
    cudaGetSymbolAddress((void**)&pihi, g_ihi);
    cudaGetSymbolAddress((void**)&pilo, g_ilo);
    cudaGetSymbolAddress((void**)&pw1h, g_w1h);
    cudaGetSymbolAddress((void**)&pw1l, g_w1l);
    cudaGetSymbolAddress((void**)&pw2h, g_w2h);
    cudaGetSymbolAddress((void**)&pw2l, g_w2l);
    cudaGetSymbolAddress((void**)&pf1h, g_f1h);
    cudaGetSymbolAddress((void**)&pf1l, g_f1l);
    cudaGetSymbolAddress((void**)&pfi3nh, g_fi3nh);
    cudaGetSymbolAddress((void**)&pfi3nl, g_fi3nl);
    cudaGetSymbolAddress((void**)&pft2nh, g_ft2nh);
    cudaGetSymbolAddress((void**)&pft2nl, g_ft2nl);
    cudaGetSymbolAddress((void**)&pishnh, g_ishnh);
    cudaGetSymbolAddress((void**)&pishnl, g_ishnl);
    cudaGetSymbolAddress((void**)&ptshnh, g_tshnh);
    cudaGetSymbolAddress((void**)&ptshnl, g_tshnl);

    so2_init<<<1, 256>>>(y);

    // bf16 hi/lo conversions
    so2_split<<<(BATCH * 2048 / 4 + 255) / 256, 256>>>(i_, pihi, pilo, BATCH * 2048 / 4);
    so2_split<<<(512 * 2048 / 4 + 255) / 256, 256>>>(l1w, pw1h, pw1l, 512 * 2048 / 4);
    so2_split<<<(256 * 512 / 4 + 255) / 256, 256>>>(l2w, pw2h, pw2l, 256 * 512 / 4);

    // image MLP layers 1-2 on HMMA tensor cores (split bf16 ~ fp32 accuracy)
    so2_gemm_mma<true, true, 1><<<dim3(4, 32), 256>>>(
        pihi, pilo, pw1h, pw1l, l1b, nullptr, pf1h, pf1l, 512, 2048);
    so2_gemm_mma<true, true, 0><<<dim3(2, 32), 256>>>(
        pf1h, pf1l, pw2h, pw2l, l2b, pfi2, nullptr, nullptr, 256, 512);
    so2_gemm_small<false, true, true><<<128, 256>>>(pfi2, l3w, l3b, pfi3, pfi3nh, pfi3nl, 256);

    // tab MLP
    so2_gemm_small<true, false, false><<<128, 256>>>(t_, tl1w, tl1b, pft1, nullptr, nullptr, 49);
    so2_gemm_small<false, true, true><<<128, 256>>>(pft1, tl2w, tl2b, pft2, pft2nh, pft2nl, 128);

    // SS heads
    so2_gemm_small<false, false, true><<<128, 256>>>(pfi3, ispw, ispb, pisp, nullptr, nullptr, 128);
    so2_gemm_small<false, true, true><<<128, 256>>>(pfi3, ishw, ishb, pish, pishnh, pishnl, 128);
    so2_gemm_small<false, true, true><<<128, 256>>>(pft2, tshw, tshb, ptsh, ptshnh, ptshnl, 128);
    so2_gemm_small<false, false, true><<<128, 256>>>(pft2, tspw, tspb, ptsp, nullptr, nullptr, 128);

    // ---- clip loss 1 on (fi3, ft2): M = i_n @ t_n^T via HMMA (split bf16) ----
    so2_gemm_mma<true, false, 0><<<dim3(32, 32), 256>>>(
        pfi3nh, pfi3nl, pft2nh, pft2nl, nullptr, pM, nullptr, nullptr, BATCH, 128);
    so2_row_reduce<<<BATCH, 256>>>(y, scale1, 0);
    so2_col_reduce<<<BATCH / 32, dim3(32, 8)>>>(y, 0);

    // ---- clip loss 2 on (i_sh, t_sh) ----
    so2_gemm_mma<true, false, 0><<<dim3(32, 32), 256>>>(
        pishnh, pishnl, ptshnh, ptshnl, nullptr, pM, nullptr, nullptr, BATCH, 128);
    so2_row_reduce<<<BATCH, 256>>>(y, scale2, 1);
    so2_col_reduce<<<BATCH / 32, dim3(32, 8)>>>(y, 1);

    // ---- separate loss via Gram trick ----
    so2_gram_pair<<<dim3(8, 8), dim3(16, 16)>>>(ptsp, ptsh, 2);
    so2_gram_pair<<<dim3(8, 8), dim3(16, 16)>>>(pisp, pish, 3);

    // ---- outputs ----
    so2_head_out<<<BATCH, 128>>>(c1w, c1b, c2w, c2b, c3w, c3b, c4w, c4b, out);
    so2_finalize<<<1, 1>>>(out);
}

// round 10
// speedup vs baseline: 3.8178x; 1.3906x over previous
#include <cuda_runtime.h>
#include <cuda_bf16.h>
#include <cstdint>
#include <stdint.h>
#include <math.h>

#define BATCH 4096

// ==================== scratch (device globals) ====================
__device__ __nv_bfloat16 g_ihi[(size_t)BATCH * 2048];
__device__ __nv_bfloat16 g_ilo[(size_t)BATCH * 2048];
__device__ __nv_bfloat16 g_w1h[512 * 2048];
__device__ __nv_bfloat16 g_w1l[512 * 2048];
__device__ __nv_bfloat16 g_w2h[256 * 512];
__device__ __nv_bfloat16 g_w2l[256 * 512];
__device__ __nv_bfloat16 g_f1h[(size_t)BATCH * 512];
__device__ __nv_bfloat16 g_f1l[(size_t)BATCH * 512];
__device__ float g_fi2[BATCH * 256];
__device__ float g_fi3[BATCH * 128];
__device__ float g_ft1[BATCH * 128];
__device__ float g_ft2[BATCH * 128];
__device__ float g_isp[BATCH * 128];
__device__ float g_ish[BATCH * 128];
__device__ float g_tsh[BATCH * 128];
__device__ float g_tsp[BATCH * 128];
__device__ __nv_bfloat16 g_fi3nh[BATCH * 128];
__device__ __nv_bfloat16 g_ft2nh[BATCH * 128];
__device__ __nv_bfloat16 g_ishnh[BATCH * 128];
__device__ __nv_bfloat16 g_tshnh[BATCH * 128];
__device__ float g_rs[2][5 * BATCH];   // row softmax stats per loss: Z,X,P,L,Lm
__device__ float g_cs[2][5 * BATCH];   // col softmax stats per loss
__device__ double g_acc[4];            // [0]=clip1, [1]=clip2, [2]=S_t, [3]=S_i
__device__ int g_n0;

// ==================== helpers ====================
__device__ __forceinline__ uint32_t s2u(const void* p) {
    uint32_t a;
    asm("{ .reg .u64 t; cvta.to.shared.u64 t, %1; cvt.u32.u64 %0, t; }" : "=r"(a) : "l"(p));
    return a;
}
__device__ __forceinline__ void ldmx4(uint32_t (&r)[4], uint32_t addr) {
    asm volatile("ldmatrix.sync.aligned.m8n8.x4.shared.b16 {%0,%1,%2,%3}, [%4];"
                 : "=r"(r[0]), "=r"(r[1]), "=r"(r[2]), "=r"(r[3]) : "r"(addr));
}
__device__ __forceinline__ void mma16816(float (&d)[4], const uint32_t (&a)[4],
                                         uint32_t b0, uint32_t b1) {
    asm volatile(
        "mma.sync.aligned.m16n8k16.row.col.f32.bf16.bf16.f32 "
        "{%0,%1,%2,%3}, {%4,%5,%6,%7}, {%8,%9}, {%0,%1,%2,%3};"
        : "+f"(d[0]), "+f"(d[1]), "+f"(d[2]), "+f"(d[3])
        : "r"(a[0]), "r"(a[1]), "r"(a[2]), "r"(a[3]), "r"(b0), "r"(b1));
}
__device__ __forceinline__ float fexp(float x) {
    float t = x * 1.4426950408889634f;
    float fi = floorf(t);
    float f = t - fi;
    float p = 1.52527338e-5f;
    p = fmaf(p, f, 1.54035304e-4f);
    p = fmaf(p, f, 1.33335581e-3f);
    p = fmaf(p, f, 9.61812911e-3f);
    p = fmaf(p, f, 5.55041087e-2f);
    p = fmaf(p, f, 2.40226507e-1f);
    p = fmaf(p, f, 6.93147181e-1f);
    p = fmaf(p, f, 1.0f);
    int i = (int)fi;
    return __int_as_float((i + 127) << 23) * p;
}
__device__ __forceinline__ float wsum(float v) {
#pragma unroll
    for (int o = 16; o > 0; o >>= 1) v += __shfl_xor_sync(0xffffffffu, v, o);
    return v;
}
__device__ __forceinline__ float r4t(float v) {   // reduce over tig (lane bits 0,1)
    v += __shfl_xor_sync(0xffffffffu, v, 1);
    v += __shfl_xor_sync(0xffffffffu, v, 2);
    return v;
}
__device__ __forceinline__ float r8g(float v) {   // reduce over g (lane bits 2,3,4)
    v += __shfl_xor_sync(0xffffffffu, v, 4);
    v += __shfl_xor_sync(0xffffffffu, v, 8);
    v += __shfl_xor_sync(0xffffffffu, v, 16);
    return v;
}

// ==================== init ====================
__global__ void so2_init(const int* __restrict__ y) {
    __shared__ int cnt[256];
    int t = threadIdx.x;
    int c = 0;
    for (int j = t; j < BATCH; j += 256) c += (y[j] == 0) ? 1 : 0;
    cnt[t] = c;
    __syncthreads();
    for (int off = 128; off > 0; off >>= 1) {
        if (t < off) cnt[t] += cnt[t + off];
        __syncthreads();
    }
    if (t == 0) {
        g_n0 = cnt[0];
        g_acc[0] = 0.0; g_acc[1] = 0.0; g_acc[2] = 0.0; g_acc[3] = 0.0;
    }
}

// ==================== fp32 -> bf16 hi/lo split ====================
__global__ void so2_split(const float* __restrict__ x, __nv_bfloat16* __restrict__ hi,
                          __nv_bfloat16* __restrict__ lo, int n4) {
    int idx = blockIdx.x * blockDim.x + threadIdx.x;
    if (idx >= n4) return;
    float4 v = ((const float4*)x)[idx];
    float vv[4] = {v.x, v.y, v.z, v.w};
    unsigned short hs[4], ls[4];
#pragma unroll
    for (int j = 0; j < 4; j++) {
        __nv_bfloat16 h = __float2bfloat16(vv[j]);
        __nv_bfloat16 l = __float2bfloat16(vv[j] - __bfloat162float(h));
        hs[j] = __bfloat16_as_ushort(h);
        ls[j] = __bfloat16_as_ushort(l);
    }
    uint2 uh, ul;
    uh.x = (uint32_t)hs[0] | ((uint32_t)hs[1] << 16);
    uh.y = (uint32_t)hs[2] | ((uint32_t)hs[3] << 16);
    ul.x = (uint32_t)ls[0] | ((uint32_t)ls[1] << 16);
    ul.y = (uint32_t)ls[2] | ((uint32_t)ls[3] << 16);
    ((uint2*)hi)[idx] = uh;
    ((uint2*)lo)[idx] = ul;
}

// ==================== HMMA GEMM (NT): C = act(A @ B^T + bias), split bf16 ====================
// 128x128 CTA tile, BK=32, 8 warps (2x4), warp tile 64x32.
// SPLIT: 3 MMA products (hh+hl+lh) ~ fp32. OUTM==0: fp32 C; OUTM==1: bf16 hi/lo out.
template <bool SPLIT, bool RELU, int OUTM>
__global__ __launch_bounds__(256) void so2_gemm_mma(
    const __nv_bfloat16* __restrict__ Ah, const __nv_bfloat16* __restrict__ Al,
    const __nv_bfloat16* __restrict__ Bh, const __nv_bfloat16* __restrict__ Bl,
    const float* __restrict__ bias,
    float* __restrict__ Cf, __nv_bfloat16* __restrict__ Ch, __nv_bfloat16* __restrict__ Cl,
    int N, int K)
{
    constexpr int NTL = SPLIT ? 4 : 2;
    constexpr int LDSB = 80;
    constexpr int TILEB = 128 * LDSB;
    __shared__ __align__(16) char smem[NTL * TILEB];
    uint32_t sbase = s2u(smem);

    int tid = threadIdx.x, lane = tid & 31, wid = tid >> 5;
    int wrow = wid & 1, wcol = wid >> 1;
    int rbA = blockIdx.y * 128, rbB = blockIdx.x * 128;

    const __nv_bfloat16* srcs[4] = {Ah, SPLIT ? Al : Bh, Bh, Bl};
    int rbs[4] = {rbA, SPLIT ? rbA : rbB, rbB, rbB};

    float acc[4][4][4];
#pragma unroll
    for (int a = 0; a < 4; a++)
#pragma unroll
        for (int b = 0; b < 4; b++)
#pragma unroll
            for (int c = 0; c < 4; c++) acc[a][b][c] = 0.f;

    uint4 st[NTL][2];
    auto fetch = [&](int k0) {
#pragma unroll
        for (int j = 0; j < NTL; j++)
#pragma unroll
            for (int i = 0; i < 2; i++) {
                int idx = tid + i * 256;
                int row = idx >> 2, seg = idx & 3;
                st[j][i] = *(const uint4*)(srcs[j] + (size_t)(rbs[j] + row) * K + k0 + seg * 8);
            }
    };
    auto stash = [&]() {
#pragma unroll
        for (int j = 0; j < NTL; j++)
#pragma unroll
            for (int i = 0; i < 2; i++) {
                int idx = tid + i * 256;
                int row = idx >> 2, seg = idx & 3;
                *(uint4*)(smem + j * TILEB + row * LDSB + seg * 16) = st[j][i];
            }
    };

    uint32_t aBase = sbase + (uint32_t)((wrow * 64 + (lane & 15)) * LDSB + (lane >> 4) * 16);
    uint32_t bBase = sbase + (uint32_t)((wcol * 32 + (lane & 15)) * LDSB + (lane >> 4) * 16);
    const int BT0 = SPLIT ? 2 : 1;

    int NCH = K >> 5;
    fetch(0);
    for (int t = 0; t < NCH; t++) {
        stash();
        __syncthreads();
        if (t + 1 < NCH) fetch((t + 1) << 5);
#pragma unroll
        for (int p = 0; p < 2; p++) {
            uint32_t aH[4][4], bH[2][4];
            uint32_t aL[4][4], bL[2][4];
#pragma unroll
            for (int mi = 0; mi < 4; mi++)
                ldmx4(aH[mi], aBase + 0 * TILEB + mi * 16 * LDSB + p * 32);
            if (SPLIT) {
#pragma unroll
                for (int mi = 0; mi < 4; mi++)
                    ldmx4(aL[mi], aBase + 1 * TILEB + mi * 16 * LDSB + p * 32);
            }
#pragma unroll
            for (int np = 0; np < 2; np++)
                ldmx4(bH[np], bBase + BT0 * TILEB + np * 16 * LDSB + p * 32);
            if (SPLIT) {
#pragma unroll
                for (int np = 0; np < 2; np++)
                    ldmx4(bL[np], bBase + 3 * TILEB + np * 16 * LDSB + p * 32);
            }
#pragma unroll
            for (int mi = 0; mi < 4; mi++)
#pragma unroll
                for (int nt = 0; nt < 4; nt++) {
                    int np = nt >> 1, s = nt & 1;
                    mma16816(acc[mi][nt], aH[mi], bH[np][s], bH[np][2 + s]);
                    if (SPLIT) {
                        mma16816(acc[mi][nt], aH[mi], bL[np][s], bL[np][2 + s]);
                        mma16816(acc[mi][nt], aL[mi], bH[np][s], bH[np][2 + s]);
                    }
                }
        }
        __syncthreads();
    }

    int g = lane >> 2, tig = lane & 3;
#pragma unroll
    for (int mi = 0; mi < 4; mi++)
#pragma unroll
        for (int q2 = 0; q2 < 2; q2++) {
            int row = rbA + wrow * 64 + mi * 16 + g + q2 * 8;
            size_t rowoff = (size_t)row * N;
#pragma unroll
            for (int nt = 0; nt < 4; nt++) {
                int col = rbB + wcol * 32 + nt * 8 + tig * 2;
                float v0 = acc[mi][nt][q2 * 2 + 0];
                float v1 = acc[mi][nt][q2 * 2 + 1];
                if (bias) { v0 += __ldg(bias + col); v1 += __ldg(bias + col + 1); }
                if (RELU) { v0 = fmaxf(v0, 0.f); v1 = fmaxf(v1, 0.f); }
                if (OUTM == 0) {
                    *(float2*)(Cf + rowoff + col) = make_float2(v0, v1);
                } else {
                    __nv_bfloat16 h0 = __float2bfloat16(v0), h1 = __float2bfloat16(v1);
                    __nv_bfloat16 l0 = __float2bfloat16(v0 - __bfloat162float(h0));
                    __nv_bfloat16 l1 = __float2bfloat16(v1 - __bfloat162float(h1));
                    uint32_t hp = (uint32_t)__bfloat16_as_ushort(h0) |
                                  ((uint32_t)__bfloat16_as_ushort(h1) << 16);
                    uint32_t lp = (uint32_t)__bfloat16_as_ushort(l0) |
                                  ((uint32_t)__bfloat16_as_ushort(l1) << 16);
                    *(uint32_t*)(Ch + rowoff + col) = hp;
                    *(uint32_t*)(Cl + rowoff + col) = lp;
                }
            }
        }
}

// ==================== fused clip GEMM: M-tile in regs -> softmax stats via atomics ====================
// M = A @ B^T (plain bf16 HMMA). Row logits = s*M (s=exp(log_scale)); col logits = M.
// Accumulates per-row and per-col (Z, X, P, L, Lm) into rs/cs float arrays (5*4096 each).
__global__ __launch_bounds__(256) void so2_clip_gemm(
    const __nv_bfloat16* __restrict__ Ah, const __nv_bfloat16* __restrict__ Bh,
    const int* __restrict__ y, const float* __restrict__ log_scale,
    float* __restrict__ rs, float* __restrict__ cs)
{
    constexpr int LDSB = 80, TILEB = 128 * LDSB, K = 128;
    __shared__ __align__(16) char smem[2 * TILEB];
    __shared__ char ya[128], yb[128];
    uint32_t sbase = s2u(smem);

    int tid = threadIdx.x, lane = tid & 31, wid = tid >> 5;
    int wrow = wid & 1, wcol = wid >> 1;
    int rbA = blockIdx.y * 128, rbB = blockIdx.x * 128;
    if (tid < 128) { ya[tid] = (char)y[rbA + tid]; yb[tid] = (char)y[rbB + tid]; }

    const __nv_bfloat16* srcs[2] = {Ah, Bh};
    int rbs[2] = {rbA, rbB};

    float acc[4][4][4];
#pragma unroll
    for (int a = 0; a < 4; a++)
#pragma unroll
        for (int b = 0; b < 4; b++)
#pragma unroll
            for (int c = 0; c < 4; c++) acc[a][b][c] = 0.f;

    uint4 st[2][2];
    auto fetch = [&](int k0) {
#pragma unroll
        for (int j = 0; j < 2; j++)
#pragma unroll
            for (int i = 0; i < 2; i++) {
                int idx = tid + i * 256;
                int row = idx >> 2, seg = idx & 3;
                st[j][i] = *(const uint4*)(srcs[j] + (size_t)(rbs[j] + row) * K + k0 + seg * 8);
            }
    };
    auto stash = [&]() {
#pragma unroll
        for (int j = 0; j < 2; j++)
#pragma unroll
            for (int i = 0; i < 2; i++) {
                int idx = tid + i * 256;
                int row = idx >> 2, seg = idx & 3;
                *(uint4*)(smem + j * TILEB + row * LDSB + seg * 16) = st[j][i];
            }
    };
    uint32_t aBase = sbase + (uint32_t)((wrow * 64 + (lane & 15)) * LDSB + (lane >> 4) * 16);
    uint32_t bBase = sbase + (uint32_t)((32 * wcol + (lane & 15)) * LDSB + (lane >> 4) * 16) + TILEB;

    fetch(0);
#pragma unroll
    for (int t = 0; t < 4; t++) {
        stash();
        __syncthreads();
        if (t + 1 < 4) fetch((t + 1) << 5);
#pragma unroll
        for (int p = 0; p < 2; p++) {
            uint32_t aH[4][4], bH[2][4];
#pragma unroll
            for (int mi = 0; mi < 4; mi++)
                ldmx4(aH[mi], aBase + mi * 16 * LDSB + p * 32);
#pragma unroll
            for (int np = 0; np < 2; np++)
                ldmx4(bH[np], bBase + np * 16 * LDSB + p * 32);
#pragma unroll
            for (int mi = 0; mi < 4; mi++)
#pragma unroll
                for (int nt = 0; nt < 4; nt++) {
                    int np = nt >> 1, s = nt & 1;
                    mma16816(acc[mi][nt], aH[mi], bH[np][s], bH[np][2 + s]);
                }
        }
        __syncthreads();
    }

    // ---- fused softmax-stats epilogue ----
    float s = expf(*log_scale);
    int g = lane >> 2, tig = lane & 3;
    float cZ[8], cX[8], cP[8], cL[8], cLm[8];
#pragma unroll
    for (int i = 0; i < 8; i++) { cZ[i] = 0; cX[i] = 0; cP[i] = 0; cL[i] = 0; cLm[i] = 0; }

#pragma unroll
    for (int mi = 0; mi < 4; mi++)
#pragma unroll
        for (int q2 = 0; q2 < 2; q2++) {
            int rloc = wrow * 64 + mi * 16 + g + q2 * 8;
            char cr = ya[rloc];
            float rZ = 0, rX = 0, rP = 0, rL = 0, rLm = 0;
#pragma unroll
            for (int nt = 0; nt < 4; nt++)
#pragma unroll
                for (int cp = 0; cp < 2; cp++) {
                    int cloc = wcol * 32 + nt * 8 + tig * 2 + cp;
                    float m = acc[mi][nt][q2 * 2 + cp];
                    bool mt = (yb[cloc] == cr);
                    float lr = s * m;
                    float er = fexp(lr);
                    float ec = fexp(m);
                    rZ += er; rX += er * lr; rL += lr;
                    if (mt) { rP += er; rLm += lr; }
                    int ci = nt * 2 + cp;
                    cZ[ci] += ec; cX[ci] += ec * m; cL[ci] += m;
                    if (mt) { cP[ci] += ec; cLm[ci] += m; }
                }
            rZ = r4t(rZ); rX = r4t(rX); rP = r4t(rP); rL = r4t(rL); rLm = r4t(rLm);
            if (tig == 0) {
                int r = rbA + rloc;
                atomicAdd(rs + 0 * BATCH + r, rZ);
                atomicAdd(rs + 1 * BATCH + r, rX);
                atomicAdd(rs + 2 * BATCH + r, rP);
                atomicAdd(rs + 3 * BATCH + r, rL);
                atomicAdd(rs + 4 * BATCH + r, rLm);
            }
        }
#pragma unroll
    for (int ci = 0; ci < 8; ci++) {
        float z = r8g(cZ[ci]), x = r8g(cX[ci]), pp = r8g(cP[ci]);
        float ll = r8g(cL[ci]), lm = r8g(cLm[ci]);
        if (g == 0) {
            int c = rbB + wcol * 32 + (ci >> 1) * 8 + tig * 2 + (ci & 1);
            atomicAdd(cs + 0 * BATCH + c, z);
            atomicAdd(cs + 1 * BATCH + c, x);
            atomicAdd(cs + 2 * BATCH + c, pp);
            atomicAdd(cs + 3 * BATCH + c, ll);
            atomicAdd(cs + 4 * BATCH + c, lm);
        }
    }
}

// ==================== per-row softmax term ====================
__device__ __forceinline__ float so2_row_term(
    float Z, float X, float P, float L, float Lm, int c)
{
    float lse = logf(Z);
    float sum_p_logit = X / Z;
    float pmatch = P / Z;
    int n0 = g_n0;
    float nc = (c == 0) ? (float)n0 : (float)(BATCH - n0);
    float no = (float)BATCH - nc;
    float u = 1.0f / nc;
    float eu = expf(u);
    float denom = nc * eu + no;
    float lden = logf(denom);
    float lqm = u - lden;
    float lqn = -lden;
    float qm = eu / denom;
    float qn = 1.0f / denom;
    float sum_q_lq = nc * qm * lqm + no * qn * lqn;
    float sum_q_lp = qm * Lm + qn * (L - Lm) - lse;
    float sum_p_lp = sum_p_logit - lse;
    float sum_p_lq = lqm * pmatch + lqn * (1.0f - pmatch);
    return (sum_q_lq - sum_q_lp) + (sum_p_lp - sum_p_lq);
}

// ==================== clip finalize: 4096 rows + 4096 cols -> g_acc ====================
__global__ void so2_clip_final(const int* __restrict__ y, int li, int acc_idx) {
    int idx = blockIdx.x * 256 + threadIdx.x;    // 8192 total
    float term = 0.f;
    {
        const float* st;
        int k;
        if (idx < BATCH) { st = g_rs[li]; k = idx; }
        else { st = g_cs[li]; k = idx - BATCH; }
        float Z = st[0 * BATCH + k], X = st[1 * BATCH + k], P = st[2 * BATCH + k];
        float L = st[3 * BATCH + k], Lm = st[4 * BATCH + k];
        term = so2_row_term(Z, X, P, L, Lm, y[k]);
    }
    __shared__ double sd[256];
    sd[threadIdx.x] = (double)term;
    __syncthreads();
    for (int off = 128; off > 0; off >>= 1) {
        if (threadIdx.x < off) sd[threadIdx.x] += sd[threadIdx.x + off];
        __syncthreads();
    }
    if (threadIdx.x == 0) atomicAdd(&g_acc[acc_idx], sd[0]);
}

// ==================== small fused GEMM: N=128, optional fused L2-normalize -> bf16 hi ====================
template <bool RELU, bool NORM, bool K4>
__global__ __launch_bounds__(256) void so2_gemm_small(
    const float* __restrict__ A, const float* __restrict__ W,
    const float* __restrict__ bias, float* __restrict__ Craw,
    __nv_bfloat16* __restrict__ Cnh, int K)
{
    const int BM = 32, BN = 128, BK = 16;
    __shared__ float As[BK][BM];
    __shared__ float Ws[BK][BN];
    int bm = blockIdx.x * BM;
    int tid = threadIdx.x;
    int warp = tid >> 5, lane = tid & 31;
    int tr = warp * 4;
    int tc = lane * 4;

    float acc[4][4];
#pragma unroll
    for (int i = 0; i < 4; i++)
#pragma unroll
        for (int j = 0; j < 4; j++) acc[i][j] = 0.f;

    int nt = (K + BK - 1) / BK;
    for (int t = 0; t < nt; t++) {
        int k0 = t * BK;
        if (K4) {
            if (tid < 128) {
                int row = tid >> 2, kq = (tid & 3) * 4;
                float4 v = *(const float4*)(A + (size_t)(bm + row) * K + k0 + kq);
                As[kq + 0][row] = v.x; As[kq + 1][row] = v.y;
                As[kq + 2][row] = v.z; As[kq + 3][row] = v.w;
            }
#pragma unroll
            for (int i = 0; i < 2; i++) {
                int l = tid + i * 256;
                int row = l >> 2, kq = (l & 3) * 4;
                float4 v = *(const float4*)(W + (size_t)row * K + k0 + kq);
                Ws[kq + 0][row] = v.x; Ws[kq + 1][row] = v.y;
                Ws[kq + 2][row] = v.z; Ws[kq + 3][row] = v.w;
            }
        } else {
            for (int idx = tid; idx < BM * BK; idx += 256) {
                int r = idx >> 4, c = idx & 15;
                int gk = k0 + c;
                As[c][r] = (gk < K) ? A[(size_t)(bm + r) * K + gk] : 0.f;
            }
            for (int idx = tid; idx < BN * BK; idx += 256) {
                int r = idx >> 4, c = idx & 15;
                int gk = k0 + c;
                Ws[c][r] = (gk < K) ? W[(size_t)r * K + gk] : 0.f;
            }
        }
        __syncthreads();
#pragma unroll
        for (int kk = 0; kk < BK; kk++) {
            float a[4], w[4];
            *(float4*)a = *(const float4*)&As[kk][tr];
            *(float4*)w = *(const float4*)&Ws[kk][tc];
#pragma unroll
            for (int i = 0; i < 4; i++)
#pragma unroll
                for (int j = 0; j < 4; j++) acc[i][j] = fmaf(a[i], w[j], acc[i][j]);
        }
        __syncthreads();
    }

    float b[4];
#pragma unroll
    for (int j = 0; j < 4; j++) b[j] = bias[tc + j];
    float v[4][4];
#pragma unroll
    for (int i = 0; i < 4; i++) {
#pragma unroll
        for (int j = 0; j < 4; j++) {
            v[i][j] = acc[i][j] + b[j];
            if (RELU) v[i][j] = fmaxf(v[i][j], 0.f);
        }
        *(float4*)(Craw + (size_t)(bm + tr + i) * 128 + tc) =
            make_float4(v[i][0], v[i][1], v[i][2], v[i][3]);
    }
    if (NORM) {
#pragma unroll
        for (int i = 0; i < 4; i++) {
            float s = v[i][0] * v[i][0] + v[i][1] * v[i][1] +
                      v[i][2] * v[i][2] + v[i][3] * v[i][3];
            s = wsum(s);
            float inv = 1.0f / fmaxf(sqrtf(s), 1e-12f);
            unsigned short hs[4];
#pragma unroll
            for (int j = 0; j < 4; j++)
                hs[j] = __bfloat16_as_ushort(__float2bfloat16(v[i][j] * inv));
            uint2 u;
            u.x = (uint32_t)hs[0] | ((uint32_t)hs[1] << 16);
            u.y = (uint32_t)hs[2] | ((uint32_t)hs[3] << 16);
            *(uint2*)(Cnh + (size_t)(bm + tr + i) * 128 + tc) = u;
        }
    }
}

// ==================== batched SS-heads GEMM (4 heads in one launch) + head outputs ====================
struct HeadsArgs {
    const float* A[4];
    const float* W[4];
    const float* b[4];
    float* raw[4];
    __nv_bfloat16* nh[4];
    const float* cw[4];
    const float* cb[4];
    int outoff[4];
};
__global__ __launch_bounds__(256) void so2_heads(HeadsArgs ha, float* __restrict__ out) {
    const int BM = 32, BK = 16, K = 128;
    int h = blockIdx.y;
    const float* A = ha.A[h];
    const float* W = ha.W[h];
    const float* bias = ha.b[h];
    float* Craw = ha.raw[h];
    __nv_bfloat16* Cnh = ha.nh[h];
    const float* cw = ha.cw[h];

    __shared__ float As[BK][BM];
    __shared__ float Ws[BK][128];
    int bm = blockIdx.x * BM;
    int tid = threadIdx.x;
    int warp = tid >> 5, lane = tid & 31;
    int tr = warp * 4;
    int tc = lane * 4;

    float acc[4][4];
#pragma unroll
    for (int i = 0; i < 4; i++)
#pragma unroll
        for (int j = 0; j < 4; j++) acc[i][j] = 0.f;

    for (int t = 0; t < K / BK; t++) {
        int k0 = t * BK;
        if (tid < 128) {
            int row = tid >> 2, kq = (tid & 3) * 4;
            float4 v = *(const float4*)(A + (size_t)(bm + row) * K + k0 + kq);
            As[kq + 0][row] = v.x; As[kq + 1][row] = v.y;
            As[kq + 2][row] = v.z; As[kq + 3][row] = v.w;
        }
#pragma unroll
        for (int i = 0; i < 2; i++) {
            int l = tid + i * 256;
            int row = l >> 2, kq = (l & 3) * 4;
            float4 v = *(const float4*)(W + (size_t)row * K + k0 + kq);
            Ws[kq + 0][row] = v.x; Ws[kq + 1][row] = v.y;
            Ws[kq + 2][row] = v.z; Ws[kq + 3][row] = v.w;
        }
        __syncthreads();
#pragma unroll
        for (int kk = 0; kk < BK; kk++) {
            float a[4], w[4];
            *(float4*)a = *(const float4*)&As[kk][tr];
            *(float4*)w = *(const float4*)&Ws[kk][tc];
#pragma unroll
            for (int i = 0; i < 4; i++)
#pragma unroll
                for (int j = 0; j < 4; j++) acc[i][j] = fmaf(a[i], w[j], acc[i][j]);
        }
        __syncthreads();
    }

    float b4[4], cw4[4];
#pragma unroll
    for (int j = 0; j < 4; j++) { b4[j] = bias[tc + j]; cw4[j] = cw[tc + j]; }
    float v[4][4];
#pragma unroll
    for (int i = 0; i < 4; i++) {
#pragma unroll
        for (int j = 0; j < 4; j++) v[i][j] = acc[i][j] + b4[j];
        *(float4*)(Craw + (size_t)(bm + tr + i) * 128 + tc) =
            make_float4(v[i][0], v[i][1], v[i][2], v[i][3]);
        // fused head output: dot(row, cw) + cb
        float d = v[i][0] * cw4[0] + v[i][1] * cw4[1] + v[i][2] * cw4[2] + v[i][3] * cw4[3];
        d = wsum(d);
        if (lane == 0) out[ha.outoff[h] + bm + tr + i] = d + ha.cb[h][0];
    }
    if (Cnh) {
#pragma unroll
        for (int i = 0; i < 4; i++) {
            float s = v[i][0] * v[i][0] + v[i][1] * v[i][1] +
                      v[i][2] * v[i][2] + v[i][3] * v[i][3];
            s = wsum(s);
            float inv = 1.0f / fmaxf(sqrtf(s), 1e-12f);
            unsigned short hs[4];
#pragma unroll
            for (int j = 0; j < 4; j++)
                hs[j] = __bfloat16_as_ushort(__float2bfloat16(v[i][j] * inv));
            uint2 u;
            u.x = (uint32_t)hs[0] | ((uint32_t)hs[1] << 16);
            u.y = (uint32_t)hs[2] | ((uint32_t)hs[3] << 16);
            *(uint2*)(Cnh + (size_t)(bm + tr + i) * 128 + tc) = u;
        }
    }
}

// ==================== sum over (A^T A) .* (B^T B) ====================
__global__ void so2_gram_pair(const float* __restrict__ A, const float* __restrict__ Bm,
                              int acc_idx)
{
    __shared__ float Au[16][17], Av[16][17], Bu[16][17], Bv[16][17];
    int u0 = blockIdx.x * 16, v0 = blockIdx.y * 16;
    int tx = threadIdx.x, ty = threadIdx.y;
    float ga = 0.f, gb = 0.f;
    for (int r0 = 0; r0 < BATCH; r0 += 16) {
        Au[ty][tx] = A[(r0 + ty) * 128 + u0 + tx];
        Av[ty][tx] = A[(r0 + ty) * 128 + v0 + tx];
        Bu[ty][tx] = Bm[(r0 + ty) * 128 + u0 + tx];
        Bv[ty][tx] = Bm[(r0 + ty) * 128 + v0 + tx];
        __syncthreads();
#pragma unroll
        for (int rr = 0; rr < 16; rr++) {
            ga += Au[rr][tx] * Av[rr][ty];
            gb += Bu[rr][tx] * Bv[rr][ty];
        }
        __syncthreads();
    }
    __shared__ float red[256];
    int t = ty * 16 + tx;
    red[t] = ga * gb;
    __syncthreads();
    for (int off = 128; off > 0; off >>= 1) {
        if (t < off) red[t] += red[t + off];
        __syncthreads();
    }
    if (t == 0) atomicAdd(&g_acc[acc_idx], (double)red[0]);
}

// ==================== final loss combine ====================
__global__ void so2_finalize(float* __restrict__ out) {
    double loss_sp = 0.5 * (sqrt(g_acc[2]) + sqrt(g_acc[3]));
    double loss1 = g_acc[0] / (4.0 * BATCH);
    double loss_sh = g_acc[1] / (4.0 * BATCH);
    out[0] = (float)((loss_sp + loss_sh + loss1) / 3.0);
}

// ==================== host driver ====================
extern "C" void kernel_launch(void* const* d_in, const int* in_sizes, int n_in,
                              void* d_out, int out_size) {
    const float* i_   = (const float*)d_in[0];
    const float* t_   = (const float*)d_in[1];
    const int*   y    = (const int*)d_in[2];
    const float* l1w  = (const float*)d_in[3];  const float* l1b = (const float*)d_in[4];
    const float* l2w  = (const float*)d_in[5];  const float* l2b = (const float*)d_in[6];
    const float* l3w  = (const float*)d_in[7];  const float* l3b = (const float*)d_in[8];
    const float* tl1w = (const float*)d_in[9];  const float* tl1b = (const float*)d_in[10];
    const float* tl2w = (const float*)d_in[11]; const float* tl2b = (const float*)d_in[12];
    const float* ispw = (const float*)d_in[13]; const float* ispb = (const float*)d_in[14];
    const float* ishw = (const float*)d_in[15]; const float* ishb = (const float*)d_in[16];
    const float* tshw = (const float*)d_in[17]; const float* tshb = (const float*)d_in[18];
    const float* tspw = (const float*)d_in[19]; const float* tspb = (const float*)d_in[20];
    const float* c1w  = (const float*)d_in[21]; const float* c1b = (const float*)d_in[22];
    const float* c2w  = (const float*)d_in[23]; const float* c2b = (const float*)d_in[24];
    const float* c3w  = (const float*)d_in[25]; const float* c3b = (const float*)d_in[26];
    const float* c4w  = (const float*)d_in[27]; const float* c4b = (const float*)d_in[28];
    const float* scale1 = (const float*)d_in[29];
    const float* scale2 = (const float*)d_in[30];
    float* out = (float*)d_out;

    float *pfi2, *pfi3, *pft1, *pft2, *pisp, *pish, *ptsh, *ptsp, *prs, *pcs;
    __nv_bfloat16 *pihi, *pilo, *pw1h, *pw1l, *pw2h, *pw2l, *pf1h, *pf1l;
    __nv_bfloat16 *pfi3nh, *pft2nh, *pishnh, *ptshnh;
    cudaGetSymbolAddress((void**)&pfi2, g_fi2);
    cudaGetSymbolAddress((void**)&pfi3, g_fi3);
    cudaGetSymbolAddress((void**)&pft1, g_ft1);
    cudaGetSymbolAddress((void**)&pft2, g_ft2);
    cudaGetSymbolAddress((void**)&pisp, g_isp);
    cudaGetSymbolAddress((void**)&pish, g_ish);
    cudaGetSymbolAddress((void**)&ptsh, g_tsh);
    cudaGetSymbolAddress((void**)&ptsp, g_tsp);
    cudaGetSymbolAddress((void**)&prs, g_rs);
    cudaGetSymbolAddress((void**)&pcs, g_cs);
    cudaGetSymbolAddress((void**)&pihi, g_ihi);
    cudaGetSymbolAddress((void**)&pilo, g_ilo);
    cudaGetSymbolAddress((void**)&pw1h, g_w1h);
    cudaGetSymbolAddress((void**)&pw1l, g_w1l);
    cudaGetSymbolAddress((void**)&pw2h, g_w2h);
    cudaGetSymbolAddress((void**)&pw2l, g_w2l);
    cudaGetSymbolAddress((void**)&pf1h, g_f1h);
    cudaGetSymbolAddress((void**)&pf1l, g_f1l);
    cudaGetSymbolAddress((void**)&pfi3nh, g_fi3nh);
    cudaGetSymbolAddress((void**)&pft2nh, g_ft2nh);
    cudaGetSymbolAddress((void**)&pishnh, g_ishnh);
    cudaGetSymbolAddress((void**)&ptshnh, g_tshnh);

    so2_init<<<1, 256>>>(y);
    cudaMemsetAsync(prs, 0, sizeof(float) * 2 * 5 * BATCH);
    cudaMemsetAsync(pcs, 0, sizeof(float) * 2 * 5 * BATCH);

    // bf16 hi/lo conversions
    so2_split<<<(BATCH * 2048 / 4 + 255) / 256, 256>>>(i_, pihi, pilo, BATCH * 2048 / 4);
    so2_split<<<(512 * 2048 / 4 + 255) / 256, 256>>>(l1w, pw1h, pw1l, 512 * 2048 / 4);
    so2_split<<<(256 * 512 / 4 + 255) / 256, 256>>>(l2w, pw2h, pw2l, 256 * 512 / 4);

    // image MLP layers 1-2 on HMMA (split bf16 ~ fp32 accuracy)
    so2_gemm_mma<true, true, 1><<<dim3(4, 32), 256>>>(
        pihi, pilo, pw1h, pw1l, l1b, nullptr, pf1h, pf1l, 512, 2048);
    so2_gemm_mma<true, true, 0><<<dim3(2, 32), 256>>>(
        pf1h, pf1l, pw2h, pw2l, l2b, pfi2, nullptr, nullptr, 256, 512);
    so2_gemm_small<false, true, true><<<128, 256>>>(pfi2, l3w, l3b, pfi3, pfi3nh, 256);

    // tab MLP
    so2_gemm_small<true, false, false><<<128, 256>>>(t_, tl1w, tl1b, pft1, nullptr, 49);
    so2_gemm_small<false, true, true><<<128, 256>>>(pft1, tl2w, tl2b, pft2, pft2nh, 128);

    // SS heads: one batched launch (raw + norms + fused head outputs)
    HeadsArgs ha;
    ha.A[0] = pfi3; ha.W[0] = ispw; ha.b[0] = ispb; ha.raw[0] = pisp; ha.nh[0] = nullptr;
    ha.cw[0] = c1w; ha.cb[0] = c1b; ha.outoff[0] = 1;
    ha.A[1] = pfi3; ha.W[1] = ishw; ha.b[1] = ishb; ha.raw[1] = pish; ha.nh[1] = pishnh;
    ha.cw[1] = c2w; ha.cb[1] = c2b; ha.outoff[1] = 1 + BATCH;
    ha.A[2] = pft2; ha.W[2] = tspw; ha.b[2] = tspb; ha.raw[2] = ptsp; ha.nh[2] = nullptr;
    ha.cw[2] = c4w; ha.cb[2] = c4b; ha.outoff[2] = 1 + 2 * BATCH;
    ha.A[3] = pft2; ha.W[3] = tshw; ha.b[3] = tshb; ha.raw[3] = ptsh; ha.nh[3] = ptshnh;
    ha.cw[3] = c3w; ha.cb[3] = c3b; ha.outoff[3] = 1 + 3 * BATCH;
    so2_heads<<<dim3(128, 4), 256>>>(ha, out);

    // ---- clip losses: fused GEMM + softmax stats (no M materialization) ----
    so2_clip_gemm<<<dim3(32, 32), 256>>>(pfi3nh, pft2nh, y, scale1, prs, pcs);
    so2_clip_gemm<<<dim3(32, 32), 256>>>(pishnh, ptshnh, y, scale2,
                                         prs + 5 * BATCH, pcs + 5 * BATCH);
    so2_clip_final<<<32, 256>>>(y, 0, 0);
    so2_clip_final<<<32, 256>>>(y, 1, 1);

    // ---- separate loss via Gram trick ----
    so2_gram_pair<<<dim3(8, 8), dim3(16, 16)>>>(ptsp, ptsh, 2);
    so2_gram_pair<<<dim3(8, 8), dim3(16, 16)>>>(pisp, pish, 3);

    // ---- outputs ----
    so2_finalize<<<1, 1>>>(out);
}

// round 13
// speedup vs baseline: 4.6968x; 1.2302x over previous
#include <cuda_runtime.h>
#include <cuda_bf16.h>
#include <cstdint>
#include <stdint.h>
#include <math.h>

#define BATCH 4096

// ==================== scratch (device globals) ====================
__device__ __nv_bfloat16 g_ihi[(size_t)BATCH * 2048];
__device__ __nv_bfloat16 g_ilo[(size_t)BATCH * 2048];
__device__ __nv_bfloat16 g_w1h[512 * 2048];
__device__ __nv_bfloat16 g_w1l[512 * 2048];
__device__ __nv_bfloat16 g_w2h[256 * 512];
__device__ __nv_bfloat16 g_w2l[256 * 512];
__device__ __nv_bfloat16 g_f1h[(size_t)BATCH * 512];
__device__ __nv_bfloat16 g_f1l[(size_t)BATCH * 512];
__device__ float g_fi2[BATCH * 256];
__device__ float g_fi3[BATCH * 128];
__device__ float g_ft2[BATCH * 128];
__device__ float g_isp[BATCH * 128];
__device__ float g_ish[BATCH * 128];
__device__ float g_tsh[BATCH * 128];
__device__ float g_tsp[BATCH * 128];
__device__ __nv_bfloat16 g_fi3nh[BATCH * 128];
__device__ __nv_bfloat16 g_ft2nh[BATCH * 128];
__device__ __nv_bfloat16 g_ishnh[BATCH * 128];
__device__ __nv_bfloat16 g_tshnh[BATCH * 128];
__device__ float g_rs[2][5 * BATCH];   // row softmax stats per loss: Z,X,P,L,Lm
__device__ float g_cs[2][5 * BATCH];   // col softmax stats per loss
__device__ double g_acc[4];            // [0]=clip1, [1]=clip2, [2]=S_t, [3]=S_i
__device__ int g_n0;

// ==================== helpers ====================
__device__ __forceinline__ uint32_t s2u(const void* p) {
    uint32_t a;
    asm("{ .reg .u64 t; cvta.to.shared.u64 t, %1; cvt.u32.u64 %0, t; }" : "=r"(a) : "l"(p));
    return a;
}
__device__ __forceinline__ void ldmx4(uint32_t (&r)[4], uint32_t addr) {
    asm volatile("ldmatrix.sync.aligned.m8n8.x4.shared.b16 {%0,%1,%2,%3}, [%4];"
                 : "=r"(r[0]), "=r"(r[1]), "=r"(r[2]), "=r"(r[3]) : "r"(addr));
}
__device__ __forceinline__ void mma16816(float (&d)[4], const uint32_t (&a)[4],
                                         uint32_t b0, uint32_t b1) {
    asm volatile(
        "mma.sync.aligned.m16n8k16.row.col.f32.bf16.bf16.f32 "
        "{%0,%1,%2,%3}, {%4,%5,%6,%7}, {%8,%9}, {%0,%1,%2,%3};"
        : "+f"(d[0]), "+f"(d[1]), "+f"(d[2]), "+f"(d[3])
        : "r"(a[0]), "r"(a[1]), "r"(a[2]), "r"(a[3]), "r"(b0), "r"(b1));
}
__device__ __forceinline__ float fexp(float x) {
    float t = x * 1.4426950408889634f;
    float fi = floorf(t);
    float f = t - fi;
    float p = 1.52527338e-5f;
    p = fmaf(p, f, 1.54035304e-4f);
    p = fmaf(p, f, 1.33335581e-3f);
    p = fmaf(p, f, 9.61812911e-3f);
    p = fmaf(p, f, 5.55041087e-2f);
    p = fmaf(p, f, 2.40226507e-1f);
    p = fmaf(p, f, 6.93147181e-1f);
    p = fmaf(p, f, 1.0f);
    int i = (int)fi;
    return __int_as_float((i + 127) << 23) * p;
}
__device__ __forceinline__ float wsum(float v) {
#pragma unroll
    for (int o = 16; o > 0; o >>= 1) v += __shfl_xor_sync(0xffffffffu, v, o);
    return v;
}
__device__ __forceinline__ float r4t(float v) {
    v += __shfl_xor_sync(0xffffffffu, v, 1);
    v += __shfl_xor_sync(0xffffffffu, v, 2);
    return v;
}
__device__ __forceinline__ float r8g(float v) {
    v += __shfl_xor_sync(0xffffffffu, v, 4);
    v += __shfl_xor_sync(0xffffffffu, v, 8);
    v += __shfl_xor_sync(0xffffffffu, v, 16);
    return v;
}

// ==================== init: zero stats + count labels + zero acc ====================
__global__ void so2_init(const int* __restrict__ y) {
    int b = blockIdx.x, t = threadIdx.x;
    if (b == 0) {
        __shared__ int cnt[256];
        int c = 0;
        for (int j = t; j < BATCH; j += 256) c += (y[j] == 0) ? 1 : 0;
        cnt[t] = c;
        __syncthreads();
        for (int off = 128; off > 0; off >>= 1) {
            if (t < off) cnt[t] += cnt[t + off];
            __syncthreads();
        }
        if (t == 0) {
            g_n0 = cnt[0];
            g_acc[0] = 0.0; g_acc[1] = 0.0; g_acc[2] = 0.0; g_acc[3] = 0.0;
        }
    } else {
        // zero g_rs + g_cs: 2*2*5*4096 floats = 81920 floats over 40 blocks
        int idx = (b - 1) * 2048 + t * 8;
        float* base = (idx < 2 * 5 * BATCH) ? &g_rs[0][0] : &g_cs[0][0];
        int off = (idx < 2 * 5 * BATCH) ? idx : idx - 2 * 5 * BATCH;
        float4 z = make_float4(0.f, 0.f, 0.f, 0.f);
        *(float4*)(base + off) = z;
        *(float4*)(base + off + 4) = z;
    }
}

// ==================== fp32 -> bf16 hi/lo split ====================
__global__ void so2_split(const float* __restrict__ x, __nv_bfloat16* __restrict__ hi,
                          __nv_bfloat16* __restrict__ lo, int n4) {
    int idx = blockIdx.x * blockDim.x + threadIdx.x;
    if (idx >= n4) return;
    float4 v = ((const float4*)x)[idx];
    float vv[4] = {v.x, v.y, v.z, v.w};
    unsigned short hs[4], ls[4];
#pragma unroll
    for (int j = 0; j < 4; j++) {
        __nv_bfloat16 h = __float2bfloat16(vv[j]);
        __nv_bfloat16 l = __float2bfloat16(vv[j] - __bfloat162float(h));
        hs[j] = __bfloat16_as_ushort(h);
        ls[j] = __bfloat16_as_ushort(l);
    }
    uint2 uh, ul;
    uh.x = (uint32_t)hs[0] | ((uint32_t)hs[1] << 16);
    uh.y = (uint32_t)hs[2] | ((uint32_t)hs[3] << 16);
    ul.x = (uint32_t)ls[0] | ((uint32_t)ls[1] << 16);
    ul.y = (uint32_t)ls[2] | ((uint32_t)ls[3] << 16);
    ((uint2*)hi)[idx] = uh;
    ((uint2*)lo)[idx] = ul;
}

// ==================== HMMA GEMM (NT): C = act(A @ B^T + bias), split bf16 ====================
template <bool SPLIT, bool RELU, int OUTM>
__global__ __launch_bounds__(256) void so2_gemm_mma(
    const __nv_bfloat16* __restrict__ Ah, const __nv_bfloat16* __restrict__ Al,
    const __nv_bfloat16* __restrict__ Bh, const __nv_bfloat16* __restrict__ Bl,
    const float* __restrict__ bias,
    float* __restrict__ Cf, __nv_bfloat16* __restrict__ Ch, __nv_bfloat16* __restrict__ Cl,
    int N, int K)
{
    constexpr int NTL = SPLIT ? 4 : 2;
    constexpr int LDSB = 80;
    constexpr int TILEB = 128 * LDSB;
    __shared__ __align__(16) char smem[NTL * TILEB];
    uint32_t sbase = s2u(smem);

    int tid = threadIdx.x, lane = tid & 31, wid = tid >> 5;
    int wrow = wid & 1, wcol = wid >> 1;
    int rbA = blockIdx.y * 128, rbB = blockIdx.x * 128;

    const __nv_bfloat16* srcs[4] = {Ah, SPLIT ? Al : Bh, Bh, Bl};
    int rbs[4] = {rbA, SPLIT ? rbA : rbB, rbB, rbB};

    float acc[4][4][4];
#pragma unroll
    for (int a = 0; a < 4; a++)
#pragma unroll
        for (int b = 0; b < 4; b++)
#pragma unroll
            for (int c = 0; c < 4; c++) acc[a][b][c] = 0.f;

    uint4 st[NTL][2];
    auto fetch = [&](int k0) {
#pragma unroll
        for (int j = 0; j < NTL; j++)
#pragma unroll
            for (int i = 0; i < 2; i++) {
                int idx = tid + i * 256;
                int row = idx >> 2, seg = idx & 3;
                st[j][i] = *(const uint4*)(srcs[j] + (size_t)(rbs[j] + row) * K + k0 + seg * 8);
            }
    };
    auto stash = [&]() {
#pragma unroll
        for (int j = 0; j < NTL; j++)
#pragma unroll
            for (int i = 0; i < 2; i++) {
                int idx = tid + i * 256;
                int row = idx >> 2, seg = idx & 3;
                *(uint4*)(smem + j * TILEB + row * LDSB + seg * 16) = st[j][i];
            }
    };

    uint32_t aBase = sbase + (uint32_t)((wrow * 64 + (lane & 15)) * LDSB + (lane >> 4) * 16);
    uint32_t bBase = sbase + (uint32_t)((wcol * 32 + (lane & 15)) * LDSB + (lane >> 4) * 16);
    const int BT0 = SPLIT ? 2 : 1;

    int NCH = K >> 5;
    fetch(0);
    for (int t = 0; t < NCH; t++) {
        stash();
        __syncthreads();
        if (t + 1 < NCH) fetch((t + 1) << 5);
#pragma unroll
        for (int p = 0; p < 2; p++) {
            uint32_t aH[4][4], bH[2][4];
            uint32_t aL[4][4], bL[2][4];
#pragma unroll
            for (int mi = 0; mi < 4; mi++)
                ldmx4(aH[mi], aBase + 0 * TILEB + mi * 16 * LDSB + p * 32);
            if (SPLIT) {
#pragma unroll
                for (int mi = 0; mi < 4; mi++)
                    ldmx4(aL[mi], aBase + 1 * TILEB + mi * 16 * LDSB + p * 32);
            }
#pragma unroll
            for (int np = 0; np < 2; np++)
                ldmx4(bH[np], bBase + BT0 * TILEB + np * 16 * LDSB + p * 32);
            if (SPLIT) {
#pragma unroll
                for (int np = 0; np < 2; np++)
                    ldmx4(bL[np], bBase + 3 * TILEB + np * 16 * LDSB + p * 32);
            }
#pragma unroll
            for (int mi = 0; mi < 4; mi++)
#pragma unroll
                for (int nt = 0; nt < 4; nt++) {
                    int np = nt >> 1, s = nt & 1;
                    mma16816(acc[mi][nt], aH[mi], bH[np][s], bH[np][2 + s]);
                    if (SPLIT) {
                        mma16816(acc[mi][nt], aH[mi], bL[np][s], bL[np][2 + s]);
                        mma16816(acc[mi][nt], aL[mi], bH[np][s], bH[np][2 + s]);
                    }
                }
        }
        __syncthreads();
    }

    int g = lane >> 2, tig = lane & 3;
#pragma unroll
    for (int mi = 0; mi < 4; mi++)
#pragma unroll
        for (int q2 = 0; q2 < 2; q2++) {
            int row = rbA + wrow * 64 + mi * 16 + g + q2 * 8;
            size_t rowoff = (size_t)row * N;
#pragma unroll
            for (int nt = 0; nt < 4; nt++) {
                int col = rbB + wcol * 32 + nt * 8 + tig * 2;
                float v0 = acc[mi][nt][q2 * 2 + 0];
                float v1 = acc[mi][nt][q2 * 2 + 1];
                if (bias) { v0 += __ldg(bias + col); v1 += __ldg(bias + col + 1); }
                if (RELU) { v0 = fmaxf(v0, 0.f); v1 = fmaxf(v1, 0.f); }
                if (OUTM == 0) {
                    *(float2*)(Cf + rowoff + col) = make_float2(v0, v1);
                } else {
                    __nv_bfloat16 h0 = __float2bfloat16(v0), h1 = __float2bfloat16(v1);
                    __nv_bfloat16 l0 = __float2bfloat16(v0 - __bfloat162float(h0));
                    __nv_bfloat16 l1 = __float2bfloat16(v1 - __bfloat162float(h1));
                    uint32_t hp = (uint32_t)__bfloat16_as_ushort(h0) |
                                  ((uint32_t)__bfloat16_as_ushort(h1) << 16);
                    uint32_t lp = (uint32_t)__bfloat16_as_ushort(l0) |
                                  ((uint32_t)__bfloat16_as_ushort(l1) << 16);
                    *(uint32_t*)(Ch + rowoff + col) = hp;
                    *(uint32_t*)(Cl + rowoff + col) = lp;
                }
            }
        }
}

// ==================== fused clip GEMM: M-tile in regs -> softmax stats via atomics ====================
__global__ __launch_bounds__(256) void so2_clip_gemm(
    const __nv_bfloat16* __restrict__ Ah, const __nv_bfloat16* __restrict__ Bh,
    const int* __restrict__ y, const float* __restrict__ log_scale,
    float* __restrict__ rs, float* __restrict__ cs)
{
    constexpr int LDSB = 80, TILEB = 128 * LDSB, K = 128;
    __shared__ __align__(16) char smem[2 * TILEB];
    __shared__ char ya[128], yb[128];
    uint32_t sbase = s2u(smem);

    int tid = threadIdx.x, lane = tid & 31, wid = tid >> 5;
    int wrow = wid & 1, wcol = wid >> 1;
    int rbA = blockIdx.y * 128, rbB = blockIdx.x * 128;
    if (tid < 128) { ya[tid] = (char)y[rbA + tid]; yb[tid] = (char)y[rbB + tid]; }

    const __nv_bfloat16* srcs[2] = {Ah, Bh};
    int rbs[2] = {rbA, rbB};

    float acc[4][4][4];
#pragma unroll
    for (int a = 0; a < 4; a++)
#pragma unroll
        for (int b = 0; b < 4; b++)
#pragma unroll
            for (int c = 0; c < 4; c++) acc[a][b][c] = 0.f;

    uint4 st[2][2];
    auto fetch = [&](int k0) {
#pragma unroll
        for (int j = 0; j < 2; j++)
#pragma unroll
            for (int i = 0; i < 2; i++) {
                int idx = tid + i * 256;
                int row = idx >> 2, seg = idx & 3;
                st[j][i] = *(const uint4*)(srcs[j] + (size_t)(rbs[j] + row) * K + k0 + seg * 8);
            }
    };
    auto stash = [&]() {
#pragma unroll
        for (int j = 0; j < 2; j++)
#pragma unroll
            for (int i = 0; i < 2; i++) {
                int idx = tid + i * 256;
                int row = idx >> 2, seg = idx & 3;
                *(uint4*)(smem + j * TILEB + row * LDSB + seg * 16) = st[j][i];
            }
    };
    uint32_t aBase = sbase + (uint32_t)((wrow * 64 + (lane & 15)) * LDSB + (lane >> 4) * 16);
    uint32_t bBase = sbase + (uint32_t)((32 * wcol + (lane & 15)) * LDSB + (lane >> 4) * 16) + TILEB;

    fetch(0);
#pragma unroll
    for (int t = 0; t < 4; t++) {
        stash();
        __syncthreads();
        if (t + 1 < 4) fetch((t + 1) << 5);
#pragma unroll
        for (int p = 0; p < 2; p++) {
            uint32_t aH[4][4], bH[2][4];
#pragma unroll
            for (int mi = 0; mi < 4; mi++)
                ldmx4(aH[mi], aBase + mi * 16 * LDSB + p * 32);
#pragma unroll
            for (int np = 0; np < 2; np++)
                ldmx4(bH[np], bBase + np * 16 * LDSB + p * 32);
#pragma unroll
            for (int mi = 0; mi < 4; mi++)
#pragma unroll
                for (int nt = 0; nt < 4; nt++) {
                    int np = nt >> 1, s = nt & 1;
                    mma16816(acc[mi][nt], aH[mi], bH[np][s], bH[np][2 + s]);
                }
        }
        __syncthreads();
    }

    float s = expf(*log_scale);
    int g = lane >> 2, tig = lane & 3;
    float cZ[8], cX[8], cP[8], cL[8], cLm[8];
#pragma unroll
    for (int i = 0; i < 8; i++) { cZ[i] = 0; cX[i] = 0; cP[i] = 0; cL[i] = 0; cLm[i] = 0; }

#pragma unroll
    for (int mi = 0; mi < 4; mi++)
#pragma unroll
        for (int q2 = 0; q2 < 2; q2++) {
            int rloc = wrow * 64 + mi * 16 + g + q2 * 8;
            char cr = ya[rloc];
            float rZ = 0, rX = 0, rP = 0, rL = 0, rLm = 0;
#pragma unroll
            for (int nt = 0; nt < 4; nt++)
#pragma unroll
                for (int cp = 0; cp < 2; cp++) {
                    int cloc = wcol * 32 + nt * 8 + tig * 2 + cp;
                    float m = acc[mi][nt][q2 * 2 + cp];
                    bool mt = (yb[cloc] == cr);
                    float lr = s * m;
                    float er = fexp(lr);
                    float ec = fexp(m);
                    rZ += er; rX += er * lr; rL += lr;
                    if (mt) { rP += er; rLm += lr; }
                    int ci = nt * 2 + cp;
                    cZ[ci] += ec; cX[ci] += ec * m; cL[ci] += m;
                    if (mt) { cP[ci] += ec; cLm[ci] += m; }
                }
            rZ = r4t(rZ); rX = r4t(rX); rP = r4t(rP); rL = r4t(rL); rLm = r4t(rLm);
            if (tig == 0) {
                int r = rbA + rloc;
                atomicAdd(rs + 0 * BATCH + r, rZ);
                atomicAdd(rs + 1 * BATCH + r, rX);
                atomicAdd(rs + 2 * BATCH + r, rP);
                atomicAdd(rs + 3 * BATCH + r, rL);
                atomicAdd(rs + 4 * BATCH + r, rLm);
            }
        }
#pragma unroll
    for (int ci = 0; ci < 8; ci++) {
        float z = r8g(cZ[ci]), x = r8g(cX[ci]), pp = r8g(cP[ci]);
        float ll = r8g(cL[ci]), lm = r8g(cLm[ci]);
        if (g == 0) {
            int c = rbB + wcol * 32 + (ci >> 1) * 8 + tig * 2 + (ci & 1);
            atomicAdd(cs + 0 * BATCH + c, z);
            atomicAdd(cs + 1 * BATCH + c, x);
            atomicAdd(cs + 2 * BATCH + c, pp);
            atomicAdd(cs + 3 * BATCH + c, ll);
            atomicAdd(cs + 4 * BATCH + c, lm);
        }
    }
}

// ==================== per-row softmax term ====================
__device__ __forceinline__ float so2_row_term(
    float Z, float X, float P, float L, float Lm, int c)
{
    float lse = logf(Z);
    float sum_p_logit = X / Z;
    float pmatch = P / Z;
    int n0 = g_n0;
    float nc = (c == 0) ? (float)n0 : (float)(BATCH - n0);
    float no = (float)BATCH - nc;
    float u = 1.0f / nc;
    float eu = expf(u);
    float denom = nc * eu + no;
    float lden = logf(denom);
    float lqm = u - lden;
    float lqn = -lden;
    float qm = eu / denom;
    float qn = 1.0f / denom;
    float sum_q_lq = nc * qm * lqm + no * qn * lqn;
    float sum_q_lp = qm * Lm + qn * (L - Lm) - lse;
    float sum_p_lp = sum_p_logit - lse;
    float sum_p_lq = lqm * pmatch + lqn * (1.0f - pmatch);
    return (sum_q_lq - sum_q_lp) + (sum_p_lp - sum_p_lq);
}

// ==================== clip finalize: both losses in one launch (grid 64) ====================
__global__ void so2_clip_final(const int* __restrict__ y) {
    int gi = blockIdx.x * 256 + threadIdx.x;     // 16384 total
    int li = gi >> 13;                            // 0 or 1
    int idx = gi & 8191;
    float term;
    {
        const float* st;
        int k;
        if (idx < BATCH) { st = g_rs[li]; k = idx; }
        else { st = g_cs[li]; k = idx - BATCH; }
        float Z = st[0 * BATCH + k], X = st[1 * BATCH + k], P = st[2 * BATCH + k];
        float L = st[3 * BATCH + k], Lm = st[4 * BATCH + k];
        term = so2_row_term(Z, X, P, L, Lm, y[k]);
    }
    __shared__ double sd[256];
    sd[threadIdx.x] = (double)term;
    __syncthreads();
    for (int off = 128; off > 0; off >>= 1) {
        if (threadIdx.x < off) sd[threadIdx.x] += sd[threadIdx.x + off];
        __syncthreads();
    }
    if (threadIdx.x == 0) atomicAdd(&g_acc[li], sd[0]);
}

// ==================== small fused GEMM w/ prefetch: N=128, K%16==0 ====================
template <bool RELU, bool NORM>
__global__ __launch_bounds__(256) void so2_gemm_small(
    const float* __restrict__ A, const float* __restrict__ W,
    const float* __restrict__ bias, float* __restrict__ Craw,
    __nv_bfloat16* __restrict__ Cnh, int K)
{
    const int BM = 32, BK = 16;
    __shared__ float As[BK][BM];
    __shared__ float Ws[BK][128];
    int bm = blockIdx.x * BM;
    int tid = threadIdx.x;
    int warp = tid >> 5, lane = tid & 31;
    int tr = warp * 4, tc = lane * 4;

    float acc[4][4];
#pragma unroll
    for (int i = 0; i < 4; i++)
#pragma unroll
        for (int j = 0; j < 4; j++) acc[i][j] = 0.f;

    float4 pa, pw[2];
    auto fetch = [&](int k0) {
        if (tid < 128) {
            int row = tid >> 2, kq = (tid & 3) * 4;
            pa = *(const float4*)(A + (size_t)(bm + row) * K + k0 + kq);
        }
#pragma unroll
        for (int i = 0; i < 2; i++) {
            int l = tid + i * 256;
            int row = l >> 2, kq = (l & 3) * 4;
            pw[i] = *(const float4*)(W + (size_t)row * K + k0 + kq);
        }
    };
    auto stash = [&]() {
        if (tid < 128) {
            int row = tid >> 2, kq = (tid & 3) * 4;
            As[kq + 0][row] = pa.x; As[kq + 1][row] = pa.y;
            As[kq + 2][row] = pa.z; As[kq + 3][row] = pa.w;
        }
#pragma unroll
        for (int i = 0; i < 2; i++) {
            int l = tid + i * 256;
            int row = l >> 2, kq = (l & 3) * 4;
            Ws[kq + 0][row] = pw[i].x; Ws[kq + 1][row] = pw[i].y;
            Ws[kq + 2][row] = pw[i].z; Ws[kq + 3][row] = pw[i].w;
        }
    };

    int nt = K / BK;
    fetch(0);
    for (int t = 0; t < nt; t++) {
        stash();
        __syncthreads();
        if (t + 1 < nt) fetch((t + 1) * BK);
#pragma unroll
        for (int kk = 0; kk < BK; kk++) {
            float a[4], w[4];
            *(float4*)a = *(const float4*)&As[kk][tr];
            *(float4*)w = *(const float4*)&Ws[kk][tc];
#pragma unroll
            for (int i = 0; i < 4; i++)
#pragma unroll
                for (int j = 0; j < 4; j++) acc[i][j] = fmaf(a[i], w[j], acc[i][j]);
        }
        __syncthreads();
    }

    float b[4];
#pragma unroll
    for (int j = 0; j < 4; j++) b[j] = bias[tc + j];
    float v[4][4];
#pragma unroll
    for (int i = 0; i < 4; i++) {
#pragma unroll
        for (int j = 0; j < 4; j++) {
            v[i][j] = acc[i][j] + b[j];
            if (RELU) v[i][j] = fmaxf(v[i][j], 0.f);
        }
        *(float4*)(Craw + (size_t)(bm + tr + i) * 128 + tc) =
            make_float4(v[i][0], v[i][1], v[i][2], v[i][3]);
    }
    if (NORM) {
#pragma unroll
        for (int i = 0; i < 4; i++) {
            float s = v[i][0] * v[i][0] + v[i][1] * v[i][1] +
                      v[i][2] * v[i][2] + v[i][3] * v[i][3];
            s = wsum(s);
            float inv = 1.0f / fmaxf(sqrtf(s), 1e-12f);
            unsigned short hs[4];
#pragma unroll
            for (int j = 0; j < 4; j++)
                hs[j] = __bfloat16_as_ushort(__float2bfloat16(v[i][j] * inv));
            uint2 u;
            u.x = (uint32_t)hs[0] | ((uint32_t)hs[1] << 16);
            u.y = (uint32_t)hs[2] | ((uint32_t)hs[3] << 16);
            *(uint2*)(Cnh + (size_t)(bm + tr + i) * 128 + tc) = u;
        }
    }
}

// ==================== fused tab MLP: ft2 = (relu(t@W1^T+b1))@W2^T+b2 ====================
__global__ __launch_bounds__(256) void so2_tab_fused(
    const float* __restrict__ T, const float* __restrict__ W1, const float* __restrict__ B1,
    const float* __restrict__ W2, const float* __restrict__ B2,
    float* __restrict__ ft2, __nv_bfloat16* __restrict__ ft2nh)
{
    const int BM = 32, BK = 16, K1 = 49;
    __shared__ float As[BK][BM];
    __shared__ float Ws[BK][128];
    __shared__ float F1[BM][132];
    int bm = blockIdx.x * BM;
    int tid = threadIdx.x;
    int warp = tid >> 5, lane = tid & 31;
    int tr = warp * 4, tc = lane * 4;

    float acc[4][4];
#pragma unroll
    for (int i = 0; i < 4; i++)
#pragma unroll
        for (int j = 0; j < 4; j++) acc[i][j] = 0.f;

    for (int t = 0; t < 4; t++) {
        int k0 = t * BK;
        for (int idx = tid; idx < BM * BK; idx += 256) {
            int r = idx >> 4, c = idx & 15;
            int gk = k0 + c;
            As[c][r] = (gk < K1) ? T[(size_t)(bm + r) * K1 + gk] : 0.f;
        }
        for (int idx = tid; idx < 128 * BK; idx += 256) {
            int r = idx >> 4, c = idx & 15;
            int gk = k0 + c;
            Ws[c][r] = (gk < K1) ? W1[(size_t)r * K1 + gk] : 0.f;
        }
        __syncthreads();
#pragma unroll
        for (int kk = 0; kk < BK; kk++) {
            float a[4], w[4];
            *(float4*)a = *(const float4*)&As[kk][tr];
            *(float4*)w = *(const float4*)&Ws[kk][tc];
#pragma unroll
            for (int i = 0; i < 4; i++)
#pragma unroll
                for (int j = 0; j < 4; j++) acc[i][j] = fmaf(a[i], w[j], acc[i][j]);
        }
        __syncthreads();
    }
#pragma unroll
    for (int i = 0; i < 4; i++)
#pragma unroll
        for (int j = 0; j < 4; j++)
            F1[tr + i][tc + j] = fmaxf(acc[i][j] + B1[tc + j], 0.f);

#pragma unroll
    for (int i = 0; i < 4; i++)
#pragma unroll
        for (int j = 0; j < 4; j++) acc[i][j] = 0.f;

    float4 pw[2];
    auto fetchW = [&](int k0) {
#pragma unroll
        for (int i = 0; i < 2; i++) {
            int l = tid + i * 256;
            int row = l >> 2, kq = (l & 3) * 4;
            pw[i] = *(const float4*)(W2 + (size_t)row * 128 + k0 + kq);
        }
    };
    auto stashW = [&]() {
#pragma unroll
        for (int i = 0; i < 2; i++) {
            int l = tid + i * 256;
            int row = l >> 2, kq = (l & 3) * 4;
            Ws[kq + 0][row] = pw[i].x; Ws[kq + 1][row] = pw[i].y;
            Ws[kq + 2][row] = pw[i].z; Ws[kq + 3][row] = pw[i].w;
        }
    };
    fetchW(0);
    for (int t = 0; t < 8; t++) {
        stashW();
        __syncthreads();
        if (t + 1 < 8) fetchW((t + 1) * BK);
#pragma unroll
        for (int kk = 0; kk < BK; kk++) {
            float a[4], w[4];
#pragma unroll
            for (int i = 0; i < 4; i++) a[i] = F1[tr + i][t * BK + kk];
            *(float4*)w = *(const float4*)&Ws[kk][tc];
#pragma unroll
            for (int i = 0; i < 4; i++)
#pragma unroll
                for (int j = 0; j < 4; j++) acc[i][j] = fmaf(a[i], w[j], acc[i][j]);
        }
        __syncthreads();
    }

    float b[4];
#pragma unroll
    for (int j = 0; j < 4; j++) b[j] = B2[tc + j];
    float v[4][4];
#pragma unroll
    for (int i = 0; i < 4; i++) {
#pragma unroll
        for (int j = 0; j < 4; j++) v[i][j] = acc[i][j] + b[j];
        *(float4*)(ft2 + (size_t)(bm + tr + i) * 128 + tc) =
            make_float4(v[i][0], v[i][1], v[i][2], v[i][3]);
    }
#pragma unroll
    for (int i = 0; i < 4; i++) {
        float s = v[i][0] * v[i][0] + v[i][1] * v[i][1] +
                  v[i][2] * v[i][2] + v[i][3] * v[i][3];
        s = wsum(s);
        float inv = 1.0f / fmaxf(sqrtf(s), 1e-12f);
        unsigned short hs[4];
#pragma unroll
        for (int j = 0; j < 4; j++)
            hs[j] = __bfloat16_as_ushort(__float2bfloat16(v[i][j] * inv));
        uint2 u;
        u.x = (uint32_t)hs[0] | ((uint32_t)hs[1] << 16);
        u.y = (uint32_t)hs[2] | ((uint32_t)hs[3] << 16);
        *(uint2*)(ft2nh + (size_t)(bm + tr + i) * 128 + tc) = u;
    }
}

// ==================== batched SS-heads GEMM (4 heads) + fused head outputs ====================
struct HeadsArgs {
    const float* A[4];
    const float* W[4];
    const float* b[4];
    float* raw[4];
    __nv_bfloat16* nh[4];
    const float* cw[4];
    const float* cb[4];
    int outoff[4];
};
__global__ __launch_bounds__(256) void so2_heads(HeadsArgs ha, float* __restrict__ out) {
    const int BM = 32, BK = 16, K = 128;
    int h = blockIdx.y;
    const float* A = ha.A[h];
    const float* W = ha.W[h];
    const float* bias = ha.b[h];
    float* Craw = ha.raw[h];
    __nv_bfloat16* Cnh = ha.nh[h];
    const float* cw = ha.cw[h];

    __shared__ float As[BK][BM];
    __shared__ float Ws[BK][128];
    int bm = blockIdx.x * BM;
    int tid = threadIdx.x;
    int warp = tid >> 5, lane = tid & 31;
    int tr = warp * 4, tc = lane * 4;

    float acc[4][4];
#pragma unroll
    for (int i = 0; i < 4; i++)
#pragma unroll
        for (int j = 0; j < 4; j++) acc[i][j] = 0.f;

    float4 pa, pw[2];
    auto fetch = [&](int k0) {
        if (tid < 128) {
            int row = tid >> 2, kq = (tid & 3) * 4;
            pa = *(const float4*)(A + (size_t)(bm + row) * K + k0 + kq);
        }
#pragma unroll
        for (int i = 0; i < 2; i++) {
            int l = tid + i * 256;
            int row = l >> 2, kq = (l & 3) * 4;
            pw[i] = *(const float4*)(W + (size_t)row * K + k0 + kq);
        }
    };
    auto stash = [&]() {
        if (tid < 128) {
            int row = tid >> 2, kq = (tid & 3) * 4;
            As[kq + 0][row] = pa.x; As[kq + 1][row] = pa.y;
            As[kq + 2][row] = pa.z; As[kq + 3][row] = pa.w;
        }
#pragma unroll
        for (int i = 0; i < 2; i++) {
            int l = tid + i * 256;
            int row = l >> 2, kq = (l & 3) * 4;
            Ws[kq + 0][row] = pw[i].x; Ws[kq + 1][row] = pw[i].y;
            Ws[kq + 2][row] = pw[i].z; Ws[kq + 3][row] = pw[i].w;
        }
    };

    fetch(0);
    for (int t = 0; t < K / BK; t++) {
        stash();
        __syncthreads();
        if (t + 1 < K / BK) fetch((t + 1) * BK);
#pragma unroll
        for (int kk = 0; kk < BK; kk++) {
            float a[4], w[4];
            *(float4*)a = *(const float4*)&As[kk][tr];
            *(float4*)w = *(const float4*)&Ws[kk][tc];
#pragma unroll
            for (int i = 0; i < 4; i++)
#pragma unroll
                for (int j = 0; j < 4; j++) acc[i][j] = fmaf(a[i], w[j], acc[i][j]);
        }
        __syncthreads();
    }

    float b4[4], cw4[4];
#pragma unroll
    for (int j = 0; j < 4; j++) { b4[j] = bias[tc + j]; cw4[j] = cw[tc + j]; }
    float v[4][4];
#pragma unroll
    for (int i = 0; i < 4; i++) {
#pragma unroll
        for (int j = 0; j < 4; j++) v[i][j] = acc[i][j] + b4[j];
        *(float4*)(Craw + (size_t)(bm + tr + i) * 128 + tc) =
            make_float4(v[i][0], v[i][1], v[i][2], v[i][3]);
        float d = v[i][0] * cw4[0] + v[i][1] * cw4[1] + v[i][2] * cw4[2] + v[i][3] * cw4[3];
        d = wsum(d);
        if (lane == 0) out[ha.outoff[h] + bm + tr + i] = d + ha.cb[h][0];
    }
    if (Cnh) {
#pragma unroll
        for (int i = 0; i < 4; i++) {
            float s = v[i][0] * v[i][0] + v[i][1] * v[i][1] +
                      v[i][2] * v[i][2] + v[i][3] * v[i][3];
            s = wsum(s);
            float inv = 1.0f / fmaxf(sqrtf(s), 1e-12f);
            unsigned short hs[4];
#pragma unroll
            for (int j = 0; j < 4; j++)
                hs[j] = __bfloat16_as_ushort(__float2bfloat16(v[i][j] * inv));
            uint2 u;
            u.x = (uint32_t)hs[0] | ((uint32_t)hs[1] << 16);
            u.y = (uint32_t)hs[2] | ((uint32_t)hs[3] << 16);
            *(uint2*)(Cnh + (size_t)(bm + tr + i) * 128 + tc) = u;
        }
    }
}

// ==================== sum over (A^T A) .* (B^T B), both pairs in one launch ====================
__global__ void so2_gram_pair(const float* __restrict__ A0, const float* __restrict__ B0,
                              const float* __restrict__ A1, const float* __restrict__ B1)
{
    const float* A = (blockIdx.z == 0) ? A0 : A1;
    const float* Bm = (blockIdx.z == 0) ? B0 : B1;
    int acc_idx = 2 + blockIdx.z;
    __shared__ float Au[16][17], Av[16][17], Bu[16][17], Bv[16][17];
    int u0 = blockIdx.x * 16, v0 = blockIdx.y * 16;
    int tx = threadIdx.x, ty = threadIdx.y;
    float ga = 0.f, gb = 0.f;
    for (int r0 = 0; r0 < BATCH; r0 += 16) {
        Au[ty][tx] = A[(r0 + ty) * 128 + u0 + tx];
        Av[ty][tx] = A[(r0 + ty) * 128 + v0 + tx];
        Bu[ty][tx] = Bm[(r0 + ty) * 128 + u0 + tx];
        Bv[ty][tx] = Bm[(r0 + ty) * 128 + v0 + tx];
        __syncthreads();
#pragma unroll
        for (int rr = 0; rr < 16; rr++) {
            ga += Au[rr][tx] * Av[rr][ty];
            gb += Bu[rr][tx] * Bv[rr][ty];
        }
        __syncthreads();
    }
    __shared__ float red[256];
    int t = ty * 16 + tx;
    red[t] = ga * gb;
    __syncthreads();
    for (int off = 128; off > 0; off >>= 1) {
        if (t < off) red[t] += red[t + off];
        __syncthreads();
    }
    if (t == 0) atomicAdd(&g_acc[acc_idx], (double)red[0]);
}

// ==================== final loss combine ====================
__global__ void so2_finalize(float* __restrict__ out) {
    double loss_sp = 0.5 * (sqrt(g_acc[2]) + sqrt(g_acc[3]));
    double loss1 = g_acc[0] / (4.0 * BATCH);
    double loss_sh = g_acc[1] / (4.0 * BATCH);
    out[0] = (float)((loss_sp + loss_sh + loss1) / 3.0);
}

// ==================== host driver (single stream) ====================
extern "C" void kernel_launch(void* const* d_in, const int* in_sizes, int n_in,
                              void* d_out, int out_size) {
    const float* i_   = (const float*)d_in[0];
    const float* t_   = (const float*)d_in[1];
    const int*   y    = (const int*)d_in[2];
    const float* l1w  = (const float*)d_in[3];  const float* l1b = (const float*)d_in[4];
    const float* l2w  = (const float*)d_in[5];  const float* l2b = (const float*)d_in[6];
    const float* l3w  = (const float*)d_in[7];  const float* l3b = (const float*)d_in[8];
    const float* tl1w = (const float*)d_in[9];  const float* tl1b = (const float*)d_in[10];
    const float* tl2w = (const float*)d_in[11]; const float* tl2b = (const float*)d_in[12];
    const float* ispw = (const float*)d_in[13]; const float* ispb = (const float*)d_in[14];
    const float* ishw = (const float*)d_in[15]; const float* ishb = (const float*)d_in[16];
    const float* tshw = (const float*)d_in[17]; const float* tshb = (const float*)d_in[18];
    const float* tspw = (const float*)d_in[19]; const float* tspb = (const float*)d_in[20];
    const float* c1w  = (const float*)d_in[21]; const float* c1b = (const float*)d_in[22];
    const float* c2w  = (const float*)d_in[23]; const float* c2b = (const float*)d_in[24];
    const float* c3w  = (const float*)d_in[25]; const float* c3b = (const float*)d_in[26];
    const float* c4w  = (const float*)d_in[27]; const float* c4b = (const float*)d_in[28];
    const float* scale1 = (const float*)d_in[29];
    const float* scale2 = (const float*)d_in[30];
    float* out = (float*)d_out;

    float *pfi2, *pfi3, *pft2, *pisp, *pish, *ptsh, *ptsp, *prs, *pcs;
    __nv_bfloat16 *pihi, *pilo, *pw1h, *pw1l, *pw2h, *pw2l, *pf1h, *pf1l;
    __nv_bfloat16 *pfi3nh, *pft2nh, *pishnh, *ptshnh;
    cudaGetSymbolAddress((void**)&pfi2, g_fi2);
    cudaGetSymbolAddress((void**)&pfi3, g_fi3);
    cudaGetSymbolAddress((void**)&pft2, g_ft2);
    cudaGetSymbolAddress((void**)&pisp, g_isp);
    cudaGetSymbolAddress((void**)&pish, g_ish);
    cudaGetSymbolAddress((void**)&ptsh, g_tsh);
    cudaGetSymbolAddress((void**)&ptsp, g_tsp);
    cudaGetSymbolAddress((void**)&prs, g_rs);
    cudaGetSymbolAddress((void**)&pcs, g_cs);
    cudaGetSymbolAddress((void**)&pihi, g_ihi);
    cudaGetSymbolAddress((void**)&pilo, g_ilo);
    cudaGetSymbolAddress((void**)&pw1h, g_w1h);
    cudaGetSymbolAddress((void**)&pw1l, g_w1l);
    cudaGetSymbolAddress((void**)&pw2h, g_w2h);
    cudaGetSymbolAddress((void**)&pw2l, g_w2l);
    cudaGetSymbolAddress((void**)&pf1h, g_f1h);
    cudaGetSymbolAddress((void**)&pf1l, g_f1l);
    cudaGetSymbolAddress((void**)&pfi3nh, g_fi3nh);
    cudaGetSymbolAddress((void**)&pft2nh, g_ft2nh);
    cudaGetSymbolAddress((void**)&pishnh, g_ishnh);
    cudaGetSymbolAddress((void**)&ptshnh, g_tshnh);

    so2_init<<<41, 256>>>(y);

    // bf16 hi/lo conversions
    so2_split<<<(BATCH * 2048 / 4 + 255) / 256, 256>>>(i_, pihi, pilo, BATCH * 2048 / 4);
    so2_split<<<(512 * 2048 / 4 + 255) / 256, 256>>>(l1w, pw1h, pw1l, 512 * 2048 / 4);
    so2_split<<<(256 * 512 / 4 + 255) / 256, 256>>>(l2w, pw2h, pw2l, 256 * 512 / 4);

    // image MLP layers 1-2 on HMMA (split bf16 ~ fp32 accuracy)
    so2_gemm_mma<true, true, 1><<<dim3(4, 32), 256>>>(
        pihi, pilo, pw1h, pw1l, l1b, nullptr, pf1h, pf1l, 512, 2048);
    so2_gemm_mma<true, true, 0><<<dim3(2, 32), 256>>>(
        pf1h, pf1l, pw2h, pw2l, l2b, pfi2, nullptr, nullptr, 256, 512);
    so2_gemm_small<false, true><<<128, 256>>>(pfi2, l3w, l3b, pfi3, pfi3nh, 256);

    // tab MLP (fused both layers)
    so2_tab_fused<<<128, 256>>>(t_, tl1w, tl1b, tl2w, tl2b, pft2, pft2nh);

    // SS heads: one batched launch (raw + norms + fused head outputs)
    HeadsArgs ha;
    ha.A[0] = pfi3; ha.W[0] = ispw; ha.b[0] = ispb; ha.raw[0] = pisp; ha.nh[0] = nullptr;
    ha.cw[0] = c1w; ha.cb[0] = c1b; ha.outoff[0] = 1;
    ha.A[1] = pfi3; ha.W[1] = ishw; ha.b[1] = ishb; ha.raw[1] = pish; ha.nh[1] = pishnh;
    ha.cw[1] = c2w; ha.cb[1] = c2b; ha.outoff[1] = 1 + BATCH;
    ha.A[2] = pft2; ha.W[2] = tspw; ha.b[2] = tspb; ha.raw[2] = ptsp; ha.nh[2] = nullptr;
    ha.cw[2] = c4w; ha.cb[2] = c4b; ha.outoff[2] = 1 + 2 * BATCH;
    ha.A[3] = pft2; ha.W[3] = tshw; ha.b[3] = tshb; ha.raw[3] = ptsh; ha.nh[3] = ptshnh;
    ha.cw[3] = c3w; ha.cb[3] = c3b; ha.outoff[3] = 1 + 3 * BATCH;
    so2_heads<<<dim3(128, 4), 256>>>(ha, out);

    // ---- clip losses: fused GEMM + softmax stats (no M materialization) ----
    so2_clip_gemm<<<dim3(32, 32), 256>>>(pfi3nh, pft2nh, y, scale1, prs, pcs);
    so2_clip_gemm<<<dim3(32, 32), 256>>>(pishnh, ptshnh, y, scale2,
                                         prs + 5 * BATCH, pcs + 5 * BATCH);
    so2_clip_final<<<64, 256>>>(y);

    // ---- separate loss via Gram trick (both pairs, one launch) ----
    so2_gram_pair<<<dim3(8, 8, 2), dim3(16, 16)>>>(ptsp, ptsh, pisp, pish);

    // ---- outputs ----
    so2_finalize<<<1, 1>>>(out);
}

// round 15
// speedup vs baseline: 4.9050x; 1.0443x over previous
#include <cuda_runtime.h>
#include <cuda_bf16.h>
#include <cstdint>
#include <stdint.h>
#include <math.h>

#define BATCH 4096

// ==================== scratch (device globals) ====================
__device__ __nv_bfloat16 g_f1h[(size_t)BATCH * 512];
__device__ __nv_bfloat16 g_f1l[(size_t)BATCH * 512];
__device__ float g_fi2a[BATCH * 256];
__device__ float g_fi2b[BATCH * 256];
__device__ float g_fi3[BATCH * 128];
__device__ float g_ft2[BATCH * 128];
__device__ float g_isp[BATCH * 128];
__device__ float g_ish[BATCH * 128];
__device__ float g_tsh[BATCH * 128];
__device__ float g_tsp[BATCH * 128];
__device__ __nv_bfloat16 g_fi3nh[BATCH * 128];
__device__ __nv_bfloat16 g_ft2nh[BATCH * 128];
__device__ __nv_bfloat16 g_ishnh[BATCH * 128];
__device__ __nv_bfloat16 g_tshnh[BATCH * 128];
__device__ float g_rs[2][5 * BATCH];   // row softmax stats per loss: Z,X,P,L,Lm
__device__ float g_cs[2][5 * BATCH];   // col softmax stats per loss
__device__ double g_acc[4];            // [0]=clip1, [1]=clip2, [2]=S_t, [3]=S_i
__device__ int g_n0;

// ==================== helpers ====================
__device__ __forceinline__ uint32_t s2u(const void* p) {
    uint32_t a;
    asm("{ .reg .u64 t; cvta.to.shared.u64 t, %1; cvt.u32.u64 %0, t; }" : "=r"(a) : "l"(p));
    return a;
}
__device__ __forceinline__ void ldmx4(uint32_t (&r)[4], uint32_t addr) {
    asm volatile("ldmatrix.sync.aligned.m8n8.x4.shared.b16 {%0,%1,%2,%3}, [%4];"
                 : "=r"(r[0]), "=r"(r[1]), "=r"(r[2]), "=r"(r[3]) : "r"(addr));
}
__device__ __forceinline__ void mma16816(float (&d)[4], const uint32_t (&a)[4],
                                         uint32_t b0, uint32_t b1) {
    asm volatile(
        "mma.sync.aligned.m16n8k16.row.col.f32.bf16.bf16.f32 "
        "{%0,%1,%2,%3}, {%4,%5,%6,%7}, {%8,%9}, {%0,%1,%2,%3};"
        : "+f"(d[0]), "+f"(d[1]), "+f"(d[2]), "+f"(d[3])
        : "r"(a[0]), "r"(a[1]), "r"(a[2]), "r"(a[3]), "r"(b0), "r"(b1));
}
__device__ __forceinline__ float fexp(float x) {
    float t = x * 1.4426950408889634f;
    float fi = floorf(t);
    float f = t - fi;
    float p = 1.52527338e-5f;
    p = fmaf(p, f, 1.54035304e-4f);
    p = fmaf(p, f, 1.33335581e-3f);
    p = fmaf(p, f, 9.61812911e-3f);
    p = fmaf(p, f, 5.55041087e-2f);
    p = fmaf(p, f, 2.40226507e-1f);
    p = fmaf(p, f, 6.93147181e-1f);
    p = fmaf(p, f, 1.0f);
    int i = (int)fi;
    return __int_as_float((i + 127) << 23) * p;
}
__device__ __forceinline__ float wsum(float v) {
#pragma unroll
    for (int o = 16; o > 0; o >>= 1) v += __shfl_xor_sync(0xffffffffu, v, o);
    return v;
}
__device__ __forceinline__ float r4t(float v) {
    v += __shfl_xor_sync(0xffffffffu, v, 1);
    v += __shfl_xor_sync(0xffffffffu, v, 2);
    return v;
}
__device__ __forceinline__ float r8g(float v) {
    v += __shfl_xor_sync(0xffffffffu, v, 4);
    v += __shfl_xor_sync(0xffffffffu, v, 8);
    v += __shfl_xor_sync(0xffffffffu, v, 16);
    return v;
}
// 8 fp32 (two uint4) -> 8 bf16 hi (uint4) + 8 bf16 lo (uint4)
__device__ __forceinline__ void cvt8(const uint4& a, const uint4& b, uint4& hi, uint4& lo) {
    float f[8];
    *(uint4*)&f[0] = a;
    *(uint4*)&f[4] = b;
    unsigned short hs[8], ls[8];
#pragma unroll
    for (int j = 0; j < 8; j++) {
        __nv_bfloat16 h = __float2bfloat16(f[j]);
        __nv_bfloat16 l = __float2bfloat16(f[j] - __bfloat162float(h));
        hs[j] = __bfloat16_as_ushort(h);
        ls[j] = __bfloat16_as_ushort(l);
    }
    hi.x = (uint32_t)hs[0] | ((uint32_t)hs[1] << 16);
    hi.y = (uint32_t)hs[2] | ((uint32_t)hs[3] << 16);
    hi.z = (uint32_t)hs[4] | ((uint32_t)hs[5] << 16);
    hi.w = (uint32_t)hs[6] | ((uint32_t)hs[7] << 16);
    lo.x = (uint32_t)ls[0] | ((uint32_t)ls[1] << 16);
    lo.y = (uint32_t)ls[2] | ((uint32_t)ls[3] << 16);
    lo.z = (uint32_t)ls[4] | ((uint32_t)ls[5] << 16);
    lo.w = (uint32_t)ls[6] | ((uint32_t)ls[7] << 16);
}

// ==================== init: zero stats + count labels + zero acc ====================
__global__ void so2_init(const int* __restrict__ y) {
    int b = blockIdx.x, t = threadIdx.x;
    if (b == 0) {
        __shared__ int cnt[256];
        int c = 0;
        for (int j = t; j < BATCH; j += 256) c += (y[j] == 0) ? 1 : 0;
        cnt[t] = c;
        __syncthreads();
        for (int off = 128; off > 0; off >>= 1) {
            if (t < off) cnt[t] += cnt[t + off];
            __syncthreads();
        }
        if (t == 0) {
            g_n0 = cnt[0];
            g_acc[0] = 0.0; g_acc[1] = 0.0; g_acc[2] = 0.0; g_acc[3] = 0.0;
        }
    } else {
        int idx = (b - 1) * 2048 + t * 8;
        float* base = (idx < 2 * 5 * BATCH) ? &g_rs[0][0] : &g_cs[0][0];
        int off = (idx < 2 * 5 * BATCH) ? idx : idx - 2 * 5 * BATCH;
        float4 z = make_float4(0.f, 0.f, 0.f, 0.f);
        *(float4*)(base + off) = z;
        *(float4*)(base + off + 4) = z;
    }
}

// ==================== split HMMA GEMM (NT): C = act(A @ B^T + bias) ====================
// A/B each represented as bf16 hi+lo (given, or converted inline from fp32).
// 3 MMA products (hh + h*Bl + Al*h) ~ fp32 accuracy.
// A32/B32: source is fp32, convert during SMEM staging.
// OUTM==0: fp32 out (Cf0/Cf1 selected by blockIdx.z; K-split via Kcomp<Kstride).
// OUTM==1: bf16 hi/lo out (Ch, Cl).
template <bool A32, bool B32, bool RELU, int OUTM>
__global__ __launch_bounds__(256) void so2_gemm_mma(
    const float* __restrict__ Af, const __nv_bfloat16* __restrict__ Ah,
    const __nv_bfloat16* __restrict__ Al,
    const float* __restrict__ Bf, const __nv_bfloat16* __restrict__ Bh,
    const __nv_bfloat16* __restrict__ Bl,
    const float* __restrict__ bias,
    float* __restrict__ Cf0, float* __restrict__ Cf1,
    __nv_bfloat16* __restrict__ Ch, __nv_bfloat16* __restrict__ Cl,
    int N, int Kstride, int Kcomp)
{
    constexpr int LDSB = 80;
    constexpr int TILEB = 128 * LDSB;
    __shared__ __align__(16) char smem[4 * TILEB];
    uint32_t sbase = s2u(smem);

    int tid = threadIdx.x, lane = tid & 31, wid = tid >> 5;
    int wrow = wid & 1, wcol = wid >> 1;
    int rbA = blockIdx.y * 128, rbB = blockIdx.x * 128;
    int kOff = blockIdx.z * Kcomp;
    float* Cf = (blockIdx.z == 0) ? Cf0 : Cf1;

    float acc[4][4][4];
#pragma unroll
    for (int a = 0; a < 4; a++)
#pragma unroll
        for (int b = 0; b < 4; b++)
#pragma unroll
            for (int c = 0; c < 4; c++) acc[a][b][c] = 0.f;

    uint4 stA[4], stB[4];
    auto fetch = [&](int k0) {
        int kk = kOff + k0;
#pragma unroll
        for (int g = 0; g < 2; g++) {
            int idx = tid + g * 256;
            int row = idx >> 2, seg = idx & 3;
            if (A32) {
                const float* p = Af + (size_t)(rbA + row) * Kstride + kk + seg * 8;
                stA[g * 2] = *(const uint4*)p;
                stA[g * 2 + 1] = *(const uint4*)(p + 4);
            } else {
                stA[g] = *(const uint4*)(Ah + (size_t)(rbA + row) * Kstride + kk + seg * 8);
                stA[2 + g] = *(const uint4*)(Al + (size_t)(rbA + row) * Kstride + kk + seg * 8);
            }
            if (B32) {
                const float* p = Bf + (size_t)(rbB + row) * Kstride + kk + seg * 8;
                stB[g * 2] = *(const uint4*)p;
                stB[g * 2 + 1] = *(const uint4*)(p + 4);
            } else {
                stB[g] = *(const uint4*)(Bh + (size_t)(rbB + row) * Kstride + kk + seg * 8);
                stB[2 + g] = *(const uint4*)(Bl + (size_t)(rbB + row) * Kstride + kk + seg * 8);
            }
        }
    };
    auto stash = [&]() {
#pragma unroll
        for (int g = 0; g < 2; g++) {
            int idx = tid + g * 256;
            int row = idx >> 2, seg = idx & 3;
            uint32_t off = (uint32_t)(row * LDSB + seg * 16);
            if (A32) {
                uint4 hi, lo;
                cvt8(stA[g * 2], stA[g * 2 + 1], hi, lo);
                *(uint4*)(smem + 0 * TILEB + off) = hi;
                *(uint4*)(smem + 1 * TILEB + off) = lo;
            } else {
                *(uint4*)(smem + 0 * TILEB + off) = stA[g];
                *(uint4*)(smem + 1 * TILEB + off) = stA[2 + g];
            }
            if (B32) {
                uint4 hi, lo;
                cvt8(stB[g * 2], stB[g * 2 + 1], hi, lo);
                *(uint4*)(smem + 2 * TILEB + off) = hi;
                *(uint4*)(smem + 3 * TILEB + off) = lo;
            } else {
                *(uint4*)(smem + 2 * TILEB + off) = stB[g];
                *(uint4*)(smem + 3 * TILEB + off) = stB[2 + g];
            }
        }
    };

    uint32_t aBase = sbase + (uint32_t)((wrow * 64 + (lane & 15)) * LDSB + (lane >> 4) * 16);
    uint32_t bBase = sbase + (uint32_t)((wcol * 32 + (lane & 15)) * LDSB + (lane >> 4) * 16);

    int NCH = Kcomp >> 5;
    fetch(0);
    for (int t = 0; t < NCH; t++) {
        stash();
        __syncthreads();
        if (t + 1 < NCH) fetch((t + 1) << 5);
#pragma unroll
        for (int p = 0; p < 2; p++) {
            uint32_t aH[4][4], aL[4][4], bH[2][4], bL[2][4];
#pragma unroll
            for (int mi = 0; mi < 4; mi++)
                ldmx4(aH[mi], aBase + 0 * TILEB + mi * 16 * LDSB + p * 32);
#pragma unroll
            for (int mi = 0; mi < 4; mi++)
                ldmx4(aL[mi], aBase + 1 * TILEB + mi * 16 * LDSB + p * 32);
#pragma unroll
            for (int np = 0; np < 2; np++)
                ldmx4(bH[np], bBase + 2 * TILEB + np * 16 * LDSB + p * 32);
#pragma unroll
            for (int np = 0; np < 2; np++)
                ldmx4(bL[np], bBase + 3 * TILEB + np * 16 * LDSB + p * 32);
#pragma unroll
            for (int mi = 0; mi < 4; mi++)
#pragma unroll
                for (int nt = 0; nt < 4; nt++) {
                    int np = nt >> 1, s = nt & 1;
                    mma16816(acc[mi][nt], aH[mi], bH[np][s], bH[np][2 + s]);
                    mma16816(acc[mi][nt], aH[mi], bL[np][s], bL[np][2 + s]);
                    mma16816(acc[mi][nt], aL[mi], bH[np][s], bH[np][2 + s]);
                }
        }
        __syncthreads();
    }

    int g = lane >> 2, tig = lane & 3;
#pragma unroll
    for (int mi = 0; mi < 4; mi++)
#pragma unroll
        for (int q2 = 0; q2 < 2; q2++) {
            int row = rbA + wrow * 64 + mi * 16 + g + q2 * 8;
            size_t rowoff = (size_t)row * N;
#pragma unroll
            for (int nt = 0; nt < 4; nt++) {
                int col = rbB + wcol * 32 + nt * 8 + tig * 2;
                float v0 = acc[mi][nt][q2 * 2 + 0];
                float v1 = acc[mi][nt][q2 * 2 + 1];
                if (bias) { v0 += __ldg(bias + col); v1 += __ldg(bias + col + 1); }
                if (RELU) { v0 = fmaxf(v0, 0.f); v1 = fmaxf(v1, 0.f); }
                if (OUTM == 0) {
                    *(float2*)(Cf + rowoff + col) = make_float2(v0, v1);
                } else {
                    __nv_bfloat16 h0 = __float2bfloat16(v0), h1 = __float2bfloat16(v1);
                    __nv_bfloat16 l0 = __float2bfloat16(v0 - __bfloat162float(h0));
                    __nv_bfloat16 l1 = __float2bfloat16(v1 - __bfloat162float(h1));
                    uint32_t hp = (uint32_t)__bfloat16_as_ushort(h0) |
                                  ((uint32_t)__bfloat16_as_ushort(h1) << 16);
                    uint32_t lp = (uint32_t)__bfloat16_as_ushort(l0) |
                                  ((uint32_t)__bfloat16_as_ushort(l1) << 16);
                    *(uint32_t*)(Ch + rowoff + col) = hp;
                    *(uint32_t*)(Cl + rowoff + col) = lp;
                }
            }
        }
}

// ==================== fused clip GEMM: both losses in one launch (grid.z=2) ====================
__global__ __launch_bounds__(256) void so2_clip_gemm(
    const __nv_bfloat16* __restrict__ Ah0, const __nv_bfloat16* __restrict__ Bh0,
    const float* __restrict__ ls0,
    const __nv_bfloat16* __restrict__ Ah1, const __nv_bfloat16* __restrict__ Bh1,
    const float* __restrict__ ls1,
    const int* __restrict__ y)
{
    constexpr int LDSB = 80, TILEB = 128 * LDSB, K = 128;
    __shared__ __align__(16) char smem[2 * TILEB];
    __shared__ char ya[128], yb[128];
    uint32_t sbase = s2u(smem);

    int z = blockIdx.z;
    const __nv_bfloat16* Ah = z ? Ah1 : Ah0;
    const __nv_bfloat16* Bh = z ? Bh1 : Bh0;
    const float* log_scale = z ? ls1 : ls0;
    float* rs = &g_rs[z][0];
    float* cs = &g_cs[z][0];

    int tid = threadIdx.x, lane = tid & 31, wid = tid >> 5;
    int wrow = wid & 1, wcol = wid >> 1;
    int rbA = blockIdx.y * 128, rbB = blockIdx.x * 128;
    if (tid < 128) { ya[tid] = (char)y[rbA + tid]; yb[tid] = (char)y[rbB + tid]; }

    float acc[4][4][4];
#pragma unroll
    for (int a = 0; a < 4; a++)
#pragma unroll
        for (int b = 0; b < 4; b++)
#pragma unroll
            for (int c = 0; c < 4; c++) acc[a][b][c] = 0.f;

    uint4 st[2][2];
    auto fetch = [&](int k0) {
#pragma unroll
        for (int i = 0; i < 2; i++) {
            int idx = tid + i * 256;
            int row = idx >> 2, seg = idx & 3;
            st[0][i] = *(const uint4*)(Ah + (size_t)(rbA + row) * K + k0 + seg * 8);
            st[1][i] = *(const uint4*)(Bh + (size_t)(rbB + row) * K + k0 + seg * 8);
        }
    };
    auto stash = [&]() {
#pragma unroll
        for (int j = 0; j < 2; j++)
#pragma unroll
            for (int i = 0; i < 2; i++) {
                int idx = tid + i * 256;
                int row = idx >> 2, seg = idx & 3;
                *(uint4*)(smem + j * TILEB + row * LDSB + seg * 16) = st[j][i];
            }
    };
    uint32_t aBase = sbase + (uint32_t)((wrow * 64 + (lane & 15)) * LDSB + (lane >> 4) * 16);
    uint32_t bBase = sbase + (uint32_t)((32 * wcol + (lane & 15)) * LDSB + (lane >> 4) * 16) + TILEB;

    fetch(0);
#pragma unroll
    for (int t = 0; t < 4; t++) {
        stash();
        __syncthreads();
        if (t + 1 < 4) fetch((t + 1) << 5);
#pragma unroll
        for (int p = 0; p < 2; p++) {
            uint32_t aH[4][4], bH[2][4];
#pragma unroll
            for (int mi = 0; mi < 4; mi++)
                ldmx4(aH[mi], aBase + mi * 16 * LDSB + p * 32);
#pragma unroll
            for (int np = 0; np < 2; np++)
                ldmx4(bH[np], bBase + np * 16 * LDSB + p * 32);
#pragma unroll
            for (int mi = 0; mi < 4; mi++)
#pragma unroll
                for (int nt = 0; nt < 4; nt++) {
                    int np = nt >> 1, s = nt & 1;
                    mma16816(acc[mi][nt], aH[mi], bH[np][s], bH[np][2 + s]);
                }
        }
        __syncthreads();
    }

    float s = expf(*log_scale);
    int g = lane >> 2, tig = lane & 3;
    float cZ[8], cX[8], cP[8], cL[8], cLm[8];
#pragma unroll
    for (int i = 0; i < 8; i++) { cZ[i] = 0; cX[i] = 0; cP[i] = 0; cL[i] = 0; cLm[i] = 0; }

#pragma unroll
    for (int mi = 0; mi < 4; mi++)
#pragma unroll
        for (int q2 = 0; q2 < 2; q2++) {
            int rloc = wrow * 64 + mi * 16 + g + q2 * 8;
            char cr = ya[rloc];
            float rZ = 0, rX = 0, rP = 0, rL = 0, rLm = 0;
#pragma unroll
            for (int nt = 0; nt < 4; nt++)
#pragma unroll
                for (int cp = 0; cp < 2; cp++) {
                    int cloc = wcol * 32 + nt * 8 + tig * 2 + cp;
                    float m = acc[mi][nt][q2 * 2 + cp];
                    bool mt = (yb[cloc] == cr);
                    float lr = s * m;
                    float er = fexp(lr);
                    float ec = fexp(m);
                    rZ += er; rX += er * lr; rL += lr;
                    if (mt) { rP += er; rLm += lr; }
                    int ci = nt * 2 + cp;
                    cZ[ci] += ec; cX[ci] += ec * m; cL[ci] += m;
                    if (mt) { cP[ci] += ec; cLm[ci] += m; }
                }
            rZ = r4t(rZ); rX = r4t(rX); rP = r4t(rP); rL = r4t(rL); rLm = r4t(rLm);
            if (tig == 0) {
                int r = rbA + rloc;
                atomicAdd(rs + 0 * BATCH + r, rZ);
                atomicAdd(rs + 1 * BATCH + r, rX);
                atomicAdd(rs + 2 * BATCH + r, rP);
                atomicAdd(rs + 3 * BATCH + r, rL);
                atomicAdd(rs + 4 * BATCH + r, rLm);
            }
        }
#pragma unroll
    for (int ci = 0; ci < 8; ci++) {
        float zz = r8g(cZ[ci]), x = r8g(cX[ci]), pp = r8g(cP[ci]);
        float ll = r8g(cL[ci]), lm = r8g(cLm[ci]);
        if (g == 0) {
            int c = rbB + wcol * 32 + (ci >> 1) * 8 + tig * 2 + (ci & 1);
            atomicAdd(cs + 0 * BATCH + c, zz);
            atomicAdd(cs + 1 * BATCH + c, x);
            atomicAdd(cs + 2 * BATCH + c, pp);
            atomicAdd(cs + 3 * BATCH + c, ll);
            atomicAdd(cs + 4 * BATCH + c, lm);
        }
    }
}

// ==================== per-row softmax term ====================
__device__ __forceinline__ float so2_row_term(
    float Z, float X, float P, float L, float Lm, int c)
{
    float lse = logf(Z);
    float sum_p_logit = X / Z;
    float pmatch = P / Z;
    int n0 = g_n0;
    float nc = (c == 0) ? (float)n0 : (float)(BATCH - n0);
    float no = (float)BATCH - nc;
    float u = 1.0f / nc;
    float eu = expf(u);
    float denom = nc * eu + no;
    float lden = logf(denom);
    float lqm = u - lden;
    float lqn = -lden;
    float qm = eu / denom;
    float qn = 1.0f / denom;
    float sum_q_lq = nc * qm * lqm + no * qn * lqn;
    float sum_q_lp = qm * Lm + qn * (L - Lm) - lse;
    float sum_p_lp = sum_p_logit - lse;
    float sum_p_lq = lqm * pmatch + lqn * (1.0f - pmatch);
    return (sum_q_lq - sum_q_lp) + (sum_p_lp - sum_p_lq);
}

// ==================== clip finalize: both losses in one launch ====================
__global__ void so2_clip_final(const int* __restrict__ y) {
    int gi = blockIdx.x * 256 + threadIdx.x;     // 16384 total
    int li = gi >> 13;
    int idx = gi & 8191;
    float term;
    {
        const float* st;
        int k;
        if (idx < BATCH) { st = g_rs[li]; k = idx; }
        else { st = g_cs[li]; k = idx - BATCH; }
        float Z = st[0 * BATCH + k], X = st[1 * BATCH + k], P = st[2 * BATCH + k];
        float L = st[3 * BATCH + k], Lm = st[4 * BATCH + k];
        term = so2_row_term(Z, X, P, L, Lm, y[k]);
    }
    __shared__ double sd[256];
    sd[threadIdx.x] = (double)term;
    __syncthreads();
    for (int off = 128; off > 0; off >>= 1) {
        if (threadIdx.x < off) sd[threadIdx.x] += sd[threadIdx.x + off];
        __syncthreads();
    }
    if (threadIdx.x == 0) atomicAdd(&g_acc[li], sd[0]);
}

// ==================== small fused GEMM w/ prefetch: N=128, K%16==0 ====================
// SUM2: A := relu(A + A2 + biasA[k]) computed in the fetch stage.
template <bool RELU, bool NORM, bool SUM2>
__global__ __launch_bounds__(256) void so2_gemm_small(
    const float* __restrict__ A, const float* __restrict__ A2,
    const float* __restrict__ biasA,
    const float* __restrict__ W,
    const float* __restrict__ bias, float* __restrict__ Craw,
    __nv_bfloat16* __restrict__ Cnh, int K)
{
    const int BM = 32, BK = 16;
    __shared__ float As[BK][BM];
    __shared__ float Ws[BK][128];
    int bm = blockIdx.x * BM;
    int tid = threadIdx.x;
    int warp = tid >> 5, lane = tid & 31;
    int tr = warp * 4, tc = lane * 4;

    float acc[4][4];
#pragma unroll
    for (int i = 0; i < 4; i++)
#pragma unroll
        for (int j = 0; j < 4; j++) acc[i][j] = 0.f;

    float4 pa, pw[2];
    auto fetch = [&](int k0) {
        if (tid < 128) {
            int row = tid >> 2, kq = (tid & 3) * 4;
            float4 v = *(const float4*)(A + (size_t)(bm + row) * K + k0 + kq);
            if (SUM2) {
                float4 v2 = *(const float4*)(A2 + (size_t)(bm + row) * K + k0 + kq);
                float4 bb = *(const float4*)(biasA + k0 + kq);
                v.x = fmaxf(v.x + v2.x + bb.x, 0.f);
                v.y = fmaxf(v.y + v2.y + bb.y, 0.f);
                v.z = fmaxf(v.z + v2.z + bb.z, 0.f);
                v.w = fmaxf(v.w + v2.w + bb.w, 0.f);
            }
            pa = v;
        }
#pragma unroll
        for (int i = 0; i < 2; i++) {
            int l = tid + i * 256;
            int row = l >> 2, kq = (l & 3) * 4;
            pw[i] = *(const float4*)(W + (size_t)row * K + k0 + kq);
        }
    };
    auto stash = [&]() {
        if (tid < 128) {
            int row = tid >> 2, kq = (tid & 3) * 4;
            As[kq + 0][row] = pa.x; As[kq + 1][row] = pa.y;
            As[kq + 2][row] = pa.z; As[kq + 3][row] = pa.w;
        }
#pragma unroll
        for (int i = 0; i < 2; i++) {
            int l = tid + i * 256;
            int row = l >> 2, kq = (l & 3) * 4;
            Ws[kq + 0][row] = pw[i].x; Ws[kq + 1][row] = pw[i].y;
            Ws[kq + 2][row] = pw[i].z; Ws[kq + 3][row] = pw[i].w;
        }
    };

    int nt = K / BK;
    fetch(0);
    for (int t = 0; t < nt; t++) {
        stash();
        __syncthreads();
        if (t + 1 < nt) fetch((t + 1) * BK);
#pragma unroll
        for (int kk = 0; kk < BK; kk++) {
            float a[4], w[4];
            *(float4*)a = *(const float4*)&As[kk][tr];
            *(float4*)w = *(const float4*)&Ws[kk][tc];
#pragma unroll
            for (int i = 0; i < 4; i++)
#pragma unroll
                for (int j = 0; j < 4; j++) acc[i][j] = fmaf(a[i], w[j], acc[i][j]);
        }
        __syncthreads();
    }

    float b[4];
#pragma unroll
    for (int j = 0; j < 4; j++) b[j] = bias[tc + j];
    float v[4][4];
#pragma unroll
    for (int i = 0; i < 4; i++) {
#pragma unroll
        for (int j = 0; j < 4; j++) {
            v[i][j] = acc[i][j] + b[j];
            if (RELU) v[i][j] = fmaxf(v[i][j], 0.f);
        }
        *(float4*)(Craw + (size_t)(bm + tr + i) * 128 + tc) =
            make_float4(v[i][0], v[i][1], v[i][2], v[i][3]);
    }
    if (NORM) {
#pragma unroll
        for (int i = 0; i < 4; i++) {
            float s = v[i][0] * v[i][0] + v[i][1] * v[i][1] +
                      v[i][2] * v[i][2] + v[i][3] * v[i][3];
            s = wsum(s);
            float inv = 1.0f / fmaxf(sqrtf(s), 1e-12f);
            unsigned short hs[4];
#pragma unroll
            for (int j = 0; j < 4; j++)
                hs[j] = __bfloat16_as_ushort(__float2bfloat16(v[i][j] * inv));
            uint2 u;
            u.x = (uint32_t)hs[0] | ((uint32_t)hs[1] << 16);
            u.y = (uint32_t)hs[2] | ((uint32_t)hs[3] << 16);
            *(uint2*)(Cnh + (size_t)(bm + tr + i) * 128 + tc) = u;
        }
    }
}

// ==================== fused tab MLP ====================
__global__ __launch_bounds__(256) void so2_tab_fused(
    const float* __restrict__ T, const float* __restrict__ W1, const float* __restrict__ B1,
    const float* __restrict__ W2, const float* __restrict__ B2,
    float* __restrict__ ft2, __nv_bfloat16* __restrict__ ft2nh)
{
    const int BM = 32, BK = 16, K1 = 49;
    __shared__ float As[BK][BM];
    __shared__ float Ws[BK][128];
    __shared__ float F1[BM][132];
    int bm = blockIdx.x * BM;
    int tid = threadIdx.x;
    int warp = tid >> 5, lane = tid & 31;
    int tr = warp * 4, tc = lane * 4;

    float acc[4][4];
#pragma unroll
    for (int i = 0; i < 4; i++)
#pragma unroll
        for (int j = 0; j < 4; j++) acc[i][j] = 0.f;

    for (int t = 0; t < 4; t++) {
        int k0 = t * BK;
        for (int idx = tid; idx < BM * BK; idx += 256) {
            int r = idx >> 4, c = idx & 15;
            int gk = k0 + c;
            As[c][r] = (gk < K1) ? T[(size_t)(bm + r) * K1 + gk] : 0.f;
        }
        for (int idx = tid; idx < 128 * BK; idx += 256) {
            int r = idx >> 4, c = idx & 15;
            int gk = k0 + c;
            Ws[c][r] = (gk < K1) ? W1[(size_t)r * K1 + gk] : 0.f;
        }
        __syncthreads();
#pragma unroll
        for (int kk = 0; kk < BK; kk++) {
            float a[4], w[4];
            *(float4*)a = *(const float4*)&As[kk][tr];
            *(float4*)w = *(const float4*)&Ws[kk][tc];
#pragma unroll
            for (int i = 0; i < 4; i++)
#pragma unroll
                for (int j = 0; j < 4; j++) acc[i][j] = fmaf(a[i], w[j], acc[i][j]);
        }
        __syncthreads();
    }
#pragma unroll
    for (int i = 0; i < 4; i++)
#pragma unroll
        for (int j = 0; j < 4; j++)
            F1[tr + i][tc + j] = fmaxf(acc[i][j] + B1[tc + j], 0.f);

#pragma unroll
    for (int i = 0; i < 4; i++)
#pragma unroll
        for (int j = 0; j < 4; j++) acc[i][j] = 0.f;

    float4 pw[2];
    auto fetchW = [&](int k0) {
#pragma unroll
        for (int i = 0; i < 2; i++) {
            int l = tid + i * 256;
            int row = l >> 2, kq = (l & 3) * 4;
            pw[i] = *(const float4*)(W2 + (size_t)row * 128 + k0 + kq);
        }
    };
    auto stashW = [&]() {
#pragma unroll
        for (int i = 0; i < 2; i++) {
            int l = tid + i * 256;
            int row = l >> 2, kq = (l & 3) * 4;
            Ws[kq + 0][row] = pw[i].x; Ws[kq + 1][row] = pw[i].y;
            Ws[kq + 2][row] = pw[i].z; Ws[kq + 3][row] = pw[i].w;
        }
    };
    fetchW(0);
    for (int t = 0; t < 8; t++) {
        stashW();
        __syncthreads();
        if (t + 1 < 8) fetchW((t + 1) * BK);
#pragma unroll
        for (int kk = 0; kk < BK; kk++) {
            float a[4], w[4];
#pragma unroll
            for (int i = 0; i < 4; i++) a[i] = F1[tr + i][t * BK + kk];
            *(float4*)w = *(const float4*)&Ws[kk][tc];
#pragma unroll
            for (int i = 0; i < 4; i++)
#pragma unroll
                for (int j = 0; j < 4; j++) acc[i][j] = fmaf(a[i], w[j], acc[i][j]);
        }
        __syncthreads();
    }

    float b[4];
#pragma unroll
    for (int j = 0; j < 4; j++) b[j] = B2[tc + j];
    float v[4][4];
#pragma unroll
    for (int i = 0; i < 4; i++) {
#pragma unroll
        for (int j = 0; j < 4; j++) v[i][j] = acc[i][j] + b[j];
        *(float4*)(ft2 + (size_t)(bm + tr + i) * 128 + tc) =
            make_float4(v[i][0], v[i][1], v[i][2], v[i][3]);
    }
#pragma unroll
    for (int i = 0; i < 4; i++) {
        float s = v[i][0] * v[i][0] + v[i][1] * v[i][1] +
                  v[i][2] * v[i][2] + v[i][3] * v[i][3];
        s = wsum(s);
        float inv = 1.0f / fmaxf(sqrtf(s), 1e-12f);
        unsigned short hs[4];
#pragma unroll
        for (int j = 0; j < 4; j++)
            hs[j] = __bfloat16_as_ushort(__float2bfloat16(v[i][j] * inv));
        uint2 u;
        u.x = (uint32_t)hs[0] | ((uint32_t)hs[1] << 16);
        u.y = (uint32_t)hs[2] | ((uint32_t)hs[3] << 16);
        *(uint2*)(ft2nh + (size_t)(bm + tr + i) * 128 + tc) = u;
    }
}

// ==================== batched SS-heads GEMM (4 heads) + fused head outputs ====================
struct HeadsArgs {
    const float* A[4];
    const float* W[4];
    const float* b[4];
    float* raw[4];
    __nv_bfloat16* nh[4];
    const float* cw[4];
    const float* cb[4];
    int outoff[4];
};
__global__ __launch_bounds__(256) void so2_heads(HeadsArgs ha, float* __restrict__ out) {
    const int BM = 32, BK = 16, K = 128;
    int h = blockIdx.y;
    const float* A = ha.A[h];
    const float* W = ha.W[h];
    const float* bias = ha.b[h];
    float* Craw = ha.raw[h];
    __nv_bfloat16* Cnh = ha.nh[h];
    const float* cw = ha.cw[h];

    __shared__ float As[BK][BM];
    __shared__ float Ws[BK][128];
    int bm = blockIdx.x * BM;
    int tid = threadIdx.x;
    int warp = tid >> 5, lane = tid & 31;
    int tr = warp * 4, tc = lane * 4;

    float acc[4][4];
#pragma unroll
    for (int i = 0; i < 4; i++)
#pragma unroll
        for (int j = 0; j < 4; j++) acc[i][j] = 0.f;

    float4 pa, pw[2];
    auto fetch = [&](int k0) {
        if (tid < 128) {
            int row = tid >> 2, kq = (tid & 3) * 4;
            pa = *(const float4*)(A + (size_t)(bm + row) * K + k0 + kq);
        }
#pragma unroll
        for (int i = 0; i < 2; i++) {
            int l = tid + i * 256;
            int row = l >> 2, kq = (l & 3) * 4;
            pw[i] = *(const float4*)(W + (size_t)row * K + k0 + kq);
        }
    };
    auto stash = [&]() {
        if (tid < 128) {
            int row = tid >> 2, kq = (tid & 3) * 4;
            As[kq + 0][row] = pa.x; As[kq + 1][row] = pa.y;
            As[kq + 2][row] = pa.z; As[kq + 3][row] = pa.w;
        }
#pragma unroll
        for (int i = 0; i < 2; i++) {
            int l = tid + i * 256;
            int row = l >> 2, kq = (l & 3) * 4;
            Ws[kq + 0][row] = pw[i].x; Ws[kq + 1][row] = pw[i].y;
            Ws[kq + 2][row] = pw[i].z; Ws[kq + 3][row] = pw[i].w;
        }
    };

    fetch(0);
    for (int t = 0; t < K / BK; t++) {
        stash();
        __syncthreads();
        if (t + 1 < K / BK) fetch((t + 1) * BK);
#pragma unroll
        for (int kk = 0; kk < BK; kk++) {
            float a[4], w[4];
            *(float4*)a = *(const float4*)&As[kk][tr];
            *(float4*)w = *(const float4*)&Ws[kk][tc];
#pragma unroll
            for (int i = 0; i < 4; i++)
#pragma unroll
                for (int j = 0; j < 4; j++) acc[i][j] = fmaf(a[i], w[j], acc[i][j]);
        }
        __syncthreads();
    }

    float b4[4], cw4[4];
#pragma unroll
    for (int j = 0; j < 4; j++) { b4[j] = bias[tc + j]; cw4[j] = cw[tc + j]; }
    float v[4][4];
#pragma unroll
    for (int i = 0; i < 4; i++) {
#pragma unroll
        for (int j = 0; j < 4; j++) v[i][j] = acc[i][j] + b4[j];
        *(float4*)(Craw + (size_t)(bm + tr + i) * 128 + tc) =
            make_float4(v[i][0], v[i][1], v[i][2], v[i][3]);
        float d = v[i][0] * cw4[0] + v[i][1] * cw4[1] + v[i][2] * cw4[2] + v[i][3] * cw4[3];
        d = wsum(d);
        if (lane == 0) out[ha.outoff[h] + bm + tr + i] = d + ha.cb[h][0];
    }
    if (Cnh) {
#pragma unroll
        for (int i = 0; i < 4; i++) {
            float s = v[i][0] * v[i][0] + v[i][1] * v[i][1] +
                      v[i][2] * v[i][2] + v[i][3] * v[i][3];
            s = wsum(s);
            float inv = 1.0f / fmaxf(sqrtf(s), 1e-12f);
            unsigned short hs[4];
#pragma unroll
            for (int j = 0; j < 4; j++)
                hs[j] = __bfloat16_as_ushort(__float2bfloat16(v[i][j] * inv));
            uint2 u;
            u.x = (uint32_t)hs[0] | ((uint32_t)hs[1] << 16);
            u.y = (uint32_t)hs[2] | ((uint32_t)hs[3] << 16);
            *(uint2*)(Cnh + (size_t)(bm + tr + i) * 128 + tc) = u;
        }
    }
}

// ==================== sum over (A^T A) .* (B^T B), both pairs in one launch ====================
__global__ void so2_gram_pair(const float* __restrict__ A0, const float* __restrict__ B0,
                              const float* __restrict__ A1, const float* __restrict__ B1)
{
    const float* A = (blockIdx.z == 0) ? A0 : A1;
    const float* Bm = (blockIdx.z == 0) ? B0 : B1;
    int acc_idx = 2 + blockIdx.z;
    __shared__ float Au[16][17], Av[16][17], Bu[16][17], Bv[16][17];
    int u0 = blockIdx.x * 16, v0 = blockIdx.y * 16;
    int tx = threadIdx.x, ty = threadIdx.y;
    float ga = 0.f, gb = 0.f;
    for (int r0 = 0; r0 < BATCH; r0 += 16) {
        Au[ty][tx] = A[(r0 + ty) * 128 + u0 + tx];
        Av[ty][tx] = A[(r0 + ty) * 128 + v0 + tx];
        Bu[ty][tx] = Bm[(r0 + ty) * 128 + u0 + tx];
        Bv[ty][tx] = Bm[(r0 + ty) * 128 + v0 + tx];
        __syncthreads();
#pragma unroll
        for (int rr = 0; rr < 16; rr++) {
            ga += Au[rr][tx] * Av[rr][ty];
            gb += Bu[rr][tx] * Bv[rr][ty];
        }
        __syncthreads();
    }
    __shared__ float red[256];
    int t = ty * 16 + tx;
    red[t] = ga * gb;
    __syncthreads();
    for (int off = 128; off > 0; off >>= 1) {
        if (t < off) red[t] += red[t + off];
        __syncthreads();
    }
    if (t == 0) atomicAdd(&g_acc[acc_idx], (double)red[0]);
}

// ==================== final loss combine ====================
__global__ void so2_finalize(float* __restrict__ out) {
    double loss_sp = 0.5 * (sqrt(g_acc[2]) + sqrt(g_acc[3]));
    double loss1 = g_acc[0] / (4.0 * BATCH);
    double loss_sh = g_acc[1] / (4.0 * BATCH);
    out[0] = (float)((loss_sp + loss_sh + loss1) / 3.0);
}

// ==================== host driver (single stream) ====================
extern "C" void kernel_launch(void* const* d_in, const int* in_sizes, int n_in,
                              void* d_out, int out_size) {
    const float* i_   = (const float*)d_in[0];
    const float* t_   = (const float*)d_in[1];
    const int*   y    = (const int*)d_in[2];
    const float* l1w  = (const float*)d_in[3];  const float* l1b = (const float*)d_in[4];
    const float* l2w  = (const float*)d_in[5];  const float* l2b = (const float*)d_in[6];
    const float* l3w  = (const float*)d_in[7];  const float* l3b = (const float*)d_in[8];
    const float* tl1w = (const float*)d_in[9];  const float* tl1b = (const float*)d_in[10];
    const float* tl2w = (const float*)d_in[11]; const float* tl2b = (const float*)d_in[12];
    const float* ispw = (const float*)d_in[13]; const float* ispb = (const float*)d_in[14];
    const float* ishw = (const float*)d_in[15]; const float* ishb = (const float*)d_in[16];
    const float* tshw = (const float*)d_in[17]; const float* tshb = (const float*)d_in[18];
    const float* tspw = (const float*)d_in[19]; const float* tspb = (const float*)d_in[20];
    const float* c1w  = (const float*)d_in[21]; const float* c1b = (const float*)d_in[22];
    const float* c2w  = (const float*)d_in[23]; const float* c2b = (const float*)d_in[24];
    const float* c3w  = (const float*)d_in[25]; const float* c3b = (const float*)d_in[26];
    const float* c4w  = (const float*)d_in[27]; const float* c4b = (const float*)d_in[28];
    const float* scale1 = (const float*)d_in[29];
    const float* scale2 = (const float*)d_in[30];
    float* out = (float*)d_out;

    float *pfi2a, *pfi2b, *pfi3, *pft2, *pisp, *pish, *ptsh, *ptsp;
    __nv_bfloat16 *pf1h, *pf1l, *pfi3nh, *pft2nh, *pishnh, *ptshnh;
    cudaGetSymbolAddress((void**)&pfi2a, g_fi2a);
    cudaGetSymbolAddress((void**)&pfi2b, g_fi2b);
    cudaGetSymbolAddress((void**)&pfi3, g_fi3);
    cudaGetSymbolAddress((void**)&pft2, g_ft2);
    cudaGetSymbolAddress((void**)&pisp, g_isp);
    cudaGetSymbolAddress((void**)&pish, g_ish);
    cudaGetSymbolAddress((void**)&ptsh, g_tsh);
    cudaGetSymbolAddress((void**)&ptsp, g_tsp);
    cudaGetSymbolAddress((void**)&pf1h, g_f1h);
    cudaGetSymbolAddress((void**)&pf1l, g_f1l);
    cudaGetSymbolAddress((void**)&pfi3nh, g_fi3nh);
    cudaGetSymbolAddress((void**)&pft2nh, g_ft2nh);
    cudaGetSymbolAddress((void**)&pishnh, g_ishnh);
    cudaGetSymbolAddress((void**)&ptshnh, g_tshnh);

    so2_init<<<41, 256>>>(y);

    // layer1: i (fp32, inline split) @ w1 (fp32, inline split) -> f1 bf16 hi/lo
    so2_gemm_mma<true, true, true, 1><<<dim3(4, 32, 1), 256>>>(
        i_, nullptr, nullptr, l1w, nullptr, nullptr, l1b,
        nullptr, nullptr, pf1h, pf1l, 512, 2048, 2048);
    // layer2: f1 (bf16 pair) @ w2 (fp32, inline split), K-split z=2 -> fp32 partials
    so2_gemm_mma<false, true, false, 0><<<dim3(2, 32, 2), 256>>>(
        nullptr, pf1h, pf1l, l2w, nullptr, nullptr, nullptr,
        pfi2a, pfi2b, nullptr, nullptr, 256, 512, 256);
    // l3: reads relu(fi2a + fi2b + l2b) inline
    so2_gemm_small<false, true, true><<<128, 256>>>(
        pfi2a, pfi2b, l2b, l3w, l3b, pfi3, pfi3nh, 256);

    // tab MLP (fused both layers)
    so2_tab_fused<<<128, 256>>>(t_, tl1w, tl1b, tl2w, tl2b, pft2, pft2nh);

    // SS heads: one batched launch (raw + norms + fused head outputs)
    HeadsArgs ha;
    ha.A[0] = pfi3; ha.W[0] = ispw; ha.b[0] = ispb; ha.raw[0] = pisp; ha.nh[0] = nullptr;
    ha.cw[0] = c1w; ha.cb[0] = c1b; ha.outoff[0] = 1;
    ha.A[1] = pfi3; ha.W[1] = ishw; ha.b[1] = ishb; ha.raw[1] = pish; ha.nh[1] = pishnh;
    ha.cw[1] = c2w; ha.cb[1] = c2b; ha.outoff[1] = 1 + BATCH;
    ha.A[2] = pft2; ha.W[2] = tspw; ha.b[2] = tspb; ha.raw[2] = ptsp; ha.nh[2] = nullptr;
    ha.cw[2] = c4w; ha.cb[2] = c4b; ha.outoff[2] = 1 + 2 * BATCH;
    ha.A[3] = pft2; ha.W[3] = tshw; ha.b[3] = tshb; ha.raw[3] = ptsh; ha.nh[3] = ptshnh;
    ha.cw[3] = c3w; ha.cb[3] = c3b; ha.outoff[3] = 1 + 3 * BATCH;
    so2_heads<<<dim3(128, 4), 256>>>(ha, out);

    // ---- both clip losses in one launch (grid.z selects loss) ----
    so2_clip_gemm<<<dim3(32, 32, 2), 256>>>(pfi3nh, pft2nh, scale1,
                                            pishnh, ptshnh, scale2, y);
    so2_clip_final<<<64, 256>>>(y);

    // ---- separate loss via Gram trick (both pairs, one launch) ----
    so2_gram_pair<<<dim3(8, 8, 2), dim3(16, 16)>>>(ptsp, ptsh, pisp, pish);

    // ---- outputs ----
    so2_finalize<<<1, 1>>>(out);
}